// round 1
// baseline (speedup 1.0000x reference)
#include <cuda_runtime.h>
#include <math.h>

// Problem constants
#define B_   256
#define N_   32768
#define M_   64
#define R_   4
#define U_   256
#define DIN_ 512
#define G4_  1024   // 4*U
#define NSPLIT 32   // split of N for the fused reads kernel

// ---------------- scratch (static device allocations; no cudaMalloc) ----------
__device__ float g_gates[B_ * G4_];        // 1 MB
__device__ float g_hnew [B_ * U_];         // 256 KB
__device__ float g_kt   [R_ * B_ * M_];    // 256 KB (raw tanh keys)
__device__ float g_kts  [R_ * B_ * M_];    // 256 KB (keys / ||key||)
__device__ float g_alpha[B_ * R_];         // 4 KB
__device__ int   g_least[B_];              // 1 KB
__device__ float g_As   [N_ * M_];         // 8 MB  (A rows / ||A[n]||)
__device__ float g_Anew [N_ * M_];         // 8 MB  (memory after writes)
__device__ float g_pacc [R_ * B_ * NSPLIT * M_]; // 8 MB partial numerators
__device__ float g_pden [R_ * B_ * NSPLIT];      // 128 KB partial denominators

__device__ __forceinline__ float sigmoidf(float v) { return 1.0f / (1.0f + expf(-v)); }

// ---------------- K1: gates = [x|read_prev|h] @ [W;Uw] + b  (C[256,1024], K=1024)
__global__ void k_gates(const float* __restrict__ x, const float* __restrict__ rp,
                        const float* __restrict__ h, const float* __restrict__ W,
                        const float* __restrict__ Uw, const float* __restrict__ bias) {
    const int BM = 64, BN = 64, BK = 16;
    __shared__ float sA[BM][BK + 1];   // In tile, row-major, padded
    __shared__ float sB[BK][BN];       // weight tile
    int t  = threadIdx.x;
    int b0 = blockIdx.y * BM;
    int j0 = blockIdx.x * BN;
    int tr = t >> 4, tc = t & 15;
    float acc[4][4] = {};
    for (int k0 = 0; k0 < 1024; k0 += BK) {
        // load In tile: In[b0+i][k0+k]
        for (int l = t; l < BM * BK; l += 256) {
            int i = l >> 4, k = l & 15;
            int kk = k0 + k, b = b0 + i;
            float v;
            if (kk < DIN_)          v = x[b * DIN_ + kk];
            else if (kk < 768) { int idx = kk - DIN_; v = rp[((idx >> 6) * B_ + b) * M_ + (idx & 63)]; }
            else                    v = h[b * U_ + (kk - 768)];
            sA[i][k] = v;
        }
        // load weight tile (coalesced)
        for (int l = t; l < BK * BN; l += 256) {
            int k = l >> 6, j = l & 63;
            int kk = k0 + k;
            sB[k][j] = (kk < 768) ? W[kk * G4_ + j0 + j] : Uw[(kk - 768) * G4_ + j0 + j];
        }
        __syncthreads();
        #pragma unroll
        for (int k = 0; k < BK; k++) {
            float a[4], bb[4];
            #pragma unroll
            for (int i = 0; i < 4; i++) a[i] = sA[tr * 4 + i][k];
            float4 b4 = *(const float4*)&sB[k][tc * 4];
            bb[0] = b4.x; bb[1] = b4.y; bb[2] = b4.z; bb[3] = b4.w;
            #pragma unroll
            for (int i = 0; i < 4; i++)
                #pragma unroll
                for (int j = 0; j < 4; j++) acc[i][j] += a[i] * bb[j];
        }
        __syncthreads();
    }
    #pragma unroll
    for (int i = 0; i < 4; i++)
        #pragma unroll
        for (int j = 0; j < 4; j++)
            g_gates[(b0 + tr * 4 + i) * G4_ + j0 + tc * 4 + j] = acc[i][j] + bias[j0 + tc * 4 + j];
}

// ---------------- K2: LSTM pointwise -> h_new (also writes out[:, 0:256])
__global__ void k_lstm(const float* __restrict__ c, float* __restrict__ out) {
    int idx = blockIdx.x * 256 + threadIdx.x;     // 65536
    int b = idx >> 8, u = idx & 255;
    const float* g = g_gates + b * G4_;
    float gi = g[u], gf = g[256 + u], gg = g[512 + u], go = g[768 + u];
    float cn = sigmoidf(gf) * c[idx] + sigmoidf(gi) * tanhf(gg);
    float hn = sigmoidf(go) * tanhf(cn);
    g_hnew[idx] = hn;
    out[b * 512 + u] = hn;
}

// ---------------- K3: kt = tanh(h_new @ Wk[r] + bk[r]); kts = kt/||kt||
__global__ void k_kt(const float* __restrict__ Wk, const float* __restrict__ bk) {
    int q = blockIdx.x;            // r*B + b
    int r = q >> 8, b = q & 255;
    int m = threadIdx.x;           // 64 threads
    __shared__ float hs[U_];
    __shared__ float red[2];
    ((float4*)hs)[m] = ((const float4*)(g_hnew + b * U_))[m];
    __syncthreads();
    float acc = bk[r * M_ + m];
    const float* wk = Wk + r * U_ * M_ + m;
    #pragma unroll 8
    for (int u = 0; u < U_; u++) acc += hs[u] * wk[u * M_];
    float kt = tanhf(acc);
    g_kt[q * M_ + m] = kt;
    float s = kt * kt;
    #pragma unroll
    for (int o = 16; o > 0; o >>= 1) s += __shfl_xor_sync(0xffffffffu, s, o);
    if ((m & 31) == 0) red[m >> 5] = s;
    __syncthreads();
    float inv = 1.0f / sqrtf(red[0] + red[1]);
    g_kts[q * M_ + m] = kt * inv;
}

// ---------------- K3b: alpha = sigmoid(tanh(h_new @ Wa + ba))
__global__ void k_alpha(const float* __restrict__ Wa, const float* __restrict__ ba) {
    int idx = blockIdx.x * 256 + threadIdx.x;   // 1024
    int b = idx >> 2, r = idx & 3;
    float acc = ba[r];
    #pragma unroll 8
    for (int u = 0; u < U_; u++) acc += g_hnew[b * U_ + u] * Wa[u * R_ + r];
    g_alpha[idx] = sigmoidf(tanhf(acc));
}

// ---------------- K4: least[b] = argmin_n wu_prev[b,n]  (first-min semantics)
__global__ void k_argmin(const float* __restrict__ wu) {
    int b = blockIdx.x, t = threadIdx.x;
    const float4* row = (const float4*)(wu + (size_t)b * N_);
    float mv = 3.4e38f; int mi = 0;
    for (int i = t; i < N_ / 4; i += 256) {
        float4 v = row[i];
        int base = i * 4;
        if (v.x < mv) { mv = v.x; mi = base; }
        if (v.y < mv) { mv = v.y; mi = base + 1; }
        if (v.z < mv) { mv = v.z; mi = base + 2; }
        if (v.w < mv) { mv = v.w; mi = base + 3; }
    }
    __shared__ float sv[256];
    __shared__ int   si[256];
    sv[t] = mv; si[t] = mi;
    __syncthreads();
    for (int s = 128; s > 0; s >>= 1) {
        if (t < s) {
            if (sv[t + s] < sv[t] || (sv[t + s] == sv[t] && si[t + s] < si[t])) {
                sv[t] = sv[t + s]; si[t] = si[t + s];
            }
        }
        __syncthreads();
    }
    if (t == 0) g_least[b] = si[0];
}

// ---------------- K5: As[n,:] = A[n,:] / ||A[n,:]||   (warp per row)
__global__ void k_As(const float* __restrict__ A) {
    int n = blockIdx.x * 8 + (threadIdx.x >> 5);
    int lane = threadIdx.x & 31;
    float a0 = A[n * M_ + lane], a1 = A[n * M_ + 32 + lane];
    float s = a0 * a0 + a1 * a1;
    #pragma unroll
    for (int o = 16; o > 0; o >>= 1) s += __shfl_xor_sync(0xffffffffu, s, o);
    float inv = 1.0f / sqrtf(s);
    g_As[n * M_ + lane]      = a0 * inv;
    g_As[n * M_ + 32 + lane] = a1 * inv;
}

// ---------------- K6: A_new = A (copy), then zero least-used rows
__global__ void k_copy(const float* __restrict__ A) {
    int i = blockIdx.x * 256 + threadIdx.x;
    ((float4*)g_Anew)[i] = ((const float4*)A)[i];
}
__global__ void k_zero() {
    g_Anew[g_least[blockIdx.x] * M_ + threadIdx.x] = 0.0f;
}

// ---------------- K7a: deterministic scatter of (1-alpha[b,r])*kt[r,b,:] into least rows
// Owner = smallest b with this least-index; owner sums all duplicates in fixed order.
__global__ void k_scatter(int r) {
    __shared__ int sL[B_];
    int t = threadIdx.x, b = blockIdx.x;
    sL[t] = g_least[t];
    __syncthreads();
    int my = sL[b];
    bool owner = true;
    for (int bb = 0; bb < b; bb++) if (sL[bb] == my) { owner = false; break; }
    if (!owner) return;
    if (t < M_) {
        float acc = 0.0f;
        for (int bb = b; bb < B_; bb++)
            if (sL[bb] == my)
                acc += (1.0f - g_alpha[bb * R_ + r]) * g_kt[(r * B_ + bb) * M_ + t];
        g_Anew[my * M_ + t] += acc;
    }
}

// ---------------- K7b: A_new = tanh(A_new + (alpha.*wr_prev[r])^T @ kt[r])
// Block: 128 n-rows x 64 m. 256 threads, each 8x4 microtile.
__global__ void k_write(const float* __restrict__ wrp, int r) {
    __shared__ float sP[32][128];
    __shared__ float sK[32][64];
    __shared__ float sAl[B_];
    int t = threadIdx.x;
    int n0 = blockIdx.x * 128;
    sAl[t] = g_alpha[t * R_ + r];
    int tn = t >> 4, tm = t & 15;
    const float* wr_base = wrp + (size_t)r * B_ * N_;
    float acc[8][4] = {};
    for (int bt = 0; bt < 8; bt++) {
        __syncthreads();
        for (int l = t; l < 1024; l += 256) {        // 32 rows x 32 float4
            int bb = l >> 5, v = l & 31;
            float4 p = *(const float4*)(wr_base + (size_t)(bt * 32 + bb) * N_ + n0 + v * 4);
            float al = sAl[bt * 32 + bb];
            p.x *= al; p.y *= al; p.z *= al; p.w *= al;
            *(float4*)&sP[bb][v * 4] = p;
        }
        for (int l = t; l < 512; l += 256) {          // 32 rows x 16 float4
            int bb = l >> 4, v = l & 15;
            *(float4*)&sK[bb][v * 4] =
                *(const float4*)(g_kt + (r * B_ + bt * 32 + bb) * M_ + v * 4);
        }
        __syncthreads();
        #pragma unroll 4
        for (int bb = 0; bb < 32; bb++) {
            float4 kv = *(const float4*)&sK[bb][tm * 4];
            float4 p0 = *(const float4*)&sP[bb][tn * 8];
            float4 p1 = *(const float4*)&sP[bb][tn * 8 + 4];
            float pr[8] = { p0.x, p0.y, p0.z, p0.w, p1.x, p1.y, p1.z, p1.w };
            float kr[4] = { kv.x, kv.y, kv.z, kv.w };
            #pragma unroll
            for (int i = 0; i < 8; i++)
                #pragma unroll
                for (int j = 0; j < 4; j++) acc[i][j] += pr[i] * kr[j];
        }
    }
    float* dst = g_Anew + (size_t)(n0 + tn * 8) * M_ + tm * 4;
    #pragma unroll
    for (int i = 0; i < 8; i++) {
        float4 v = *(float4*)(dst + i * M_);
        v.x = tanhf(v.x + acc[i][0]);
        v.y = tanhf(v.y + acc[i][1]);
        v.z = tanhf(v.z + acc[i][2]);
        v.w = tanhf(v.w + acc[i][3]);
        *(float4*)(dst + i * M_) = v;
    }
}

// ---------------- K8: fused cosine-softmax-weighted reads (split over N)
// grid (NSPLIT, 16 q-tiles), 256 threads. Per block: 64 queries, 1024 keys.
__global__ void k_reads() {
    __shared__ float sQ[64][65];
    __shared__ float sA[32][64];
    __shared__ float sV[32][64];
    __shared__ float sE[64][33];
    int t = threadIdx.x;
    int q0 = blockIdx.y * 64;
    int n0 = blockIdx.x * (N_ / NSPLIT);
    for (int l = t; l < 1024; l += 256) {             // 64 q x 16 float4
        int q = l >> 4, m4 = l & 15;
        float4 v = *(const float4*)(g_kts + (q0 + q) * M_ + m4 * 4);
        sQ[q][m4 * 4] = v.x; sQ[q][m4 * 4 + 1] = v.y;
        sQ[q][m4 * 4 + 2] = v.z; sQ[q][m4 * 4 + 3] = v.w;
    }
    int qgE = (t & 15) * 4;      // phase E: 4 queries
    int ngE = (t >> 4) * 2;      // phase E: 2 keys
    int qB  = t >> 2;            // phase B: query
    int mB  = (t & 3) * 16;      // phase B: 16 m's
    bool dflag = (t & 3) == 0;
    float acc[16] = {};
    float den = 0.0f;
    for (int tile = 0; tile < 32; tile++) {
        __syncthreads();
        int nb = n0 + tile * 32;
        for (int l = t; l < 512; l += 256) {
            int nn = l >> 4, m4 = l & 15;
            *(float4*)&sA[nn][m4 * 4] = *(const float4*)(g_As   + (size_t)(nb + nn) * M_ + m4 * 4);
        }
        for (int l = t; l < 512; l += 256) {
            int nn = l >> 4, m4 = l & 15;
            *(float4*)&sV[nn][m4 * 4] = *(const float4*)(g_Anew + (size_t)(nb + nn) * M_ + m4 * 4);
        }
        __syncthreads();
        // phase E: E[q][nn] = exp( kts[q] . As[nn] )
        float e[4][2] = {};
        #pragma unroll 4
        for (int m = 0; m < 64; m++) {
            float a0 = sA[ngE][m];
            float a1 = sA[ngE + 1][m];
            #pragma unroll
            for (int i = 0; i < 4; i++) {
                float qv = sQ[qgE + i][m];
                e[i][0] += qv * a0;
                e[i][1] += qv * a1;
            }
        }
        #pragma unroll
        for (int i = 0; i < 4; i++) {
            sE[qgE + i][ngE]     = __expf(e[i][0]);
            sE[qgE + i][ngE + 1] = __expf(e[i][1]);
        }
        __syncthreads();
        // phase B: acc[q][m] += E[q][nn] * A_new[nn][m]; den[q] += E
        #pragma unroll 2
        for (int nn = 0; nn < 32; nn++) {
            float ev = sE[qB][nn];
            if (dflag) den += ev;
            const float4* vr = (const float4*)&sV[nn][mB];
            #pragma unroll
            for (int jj = 0; jj < 4; jj++) {
                float4 v = vr[jj];
                acc[jj * 4 + 0] += ev * v.x;
                acc[jj * 4 + 1] += ev * v.y;
                acc[jj * 4 + 2] += ev * v.z;
                acc[jj * 4 + 3] += ev * v.w;
            }
        }
    }
    int q = q0 + qB;
    float* pa = g_pacc + ((size_t)q * NSPLIT + blockIdx.x) * M_ + mB;
    #pragma unroll
    for (int jj = 0; jj < 4; jj++)
        *(float4*)(pa + jj * 4) = make_float4(acc[jj * 4], acc[jj * 4 + 1],
                                              acc[jj * 4 + 2], acc[jj * 4 + 3]);
    if (dflag) g_pden[q * NSPLIT + blockIdx.x] = den;
}

// ---------------- K9: combine partials, write out[:, 256:512]
__global__ void k_combine(float* __restrict__ out) {
    int q = blockIdx.x;          // r*B + b
    int m = threadIdx.x;         // 64
    float acc = 0.0f, den = 0.0f;
    for (int s = 0; s < NSPLIT; s++) {
        acc += g_pacc[((size_t)q * NSPLIT + s) * M_ + m];
        den += g_pden[q * NSPLIT + s];
    }
    int r = q >> 8, b = q & 255;
    out[b * 512 + 256 + r * M_ + m] = acc / den;
}

// ---------------- launch ----------------
extern "C" void kernel_launch(void* const* d_in, const int* in_sizes, int n_in,
                              void* d_out, int out_size) {
    const float* x    = (const float*)d_in[0];
    const float* A    = (const float*)d_in[1];
    const float* wrp  = (const float*)d_in[2];
    const float* wu   = (const float*)d_in[3];
    const float* rp   = (const float*)d_in[4];
    const float* h    = (const float*)d_in[5];
    const float* c    = (const float*)d_in[6];
    const float* W    = (const float*)d_in[7];
    const float* Uw   = (const float*)d_in[8];
    const float* bias = (const float*)d_in[9];
    const float* Wk   = (const float*)d_in[10];
    const float* bk   = (const float*)d_in[11];
    const float* Wa   = (const float*)d_in[12];
    const float* ba   = (const float*)d_in[13];
    float* out = (float*)d_out;

    k_gates <<<dim3(16, 4), 256>>>(x, rp, h, W, Uw, bias);
    k_lstm  <<<256, 256>>>(c, out);
    k_kt    <<<R_ * B_, 64>>>(Wk, bk);
    k_alpha <<<4, 256>>>(Wa, ba);
    k_argmin<<<B_, 256>>>(wu);
    k_As    <<<N_ / 8, 256>>>(A);
    k_copy  <<<(N_ * M_ / 4) / 256, 256>>>(A);
    k_zero  <<<B_, M_>>>();
    for (int r = 0; r < R_; r++) {
        k_scatter<<<B_, 256>>>(r);
        k_write  <<<N_ / 128, 256>>>(wrp, r);
    }
    k_reads  <<<dim3(NSPLIT, 16), 256>>>();
    k_combine<<<R_ * B_, 64>>>(out);
}

// round 3
// speedup vs baseline: 2.5629x; 2.5629x over previous
#include <cuda_runtime.h>
#include <cuda_fp16.h>
#include <math.h>
#include <stdint.h>

// Problem constants
#define B_   256
#define N_   32768
#define M_   64
#define R_   4
#define U_   256
#define DIN_ 512
#define G4_  1024
#define QT_  1024      // total queries = R*B
#define NBLK 256       // k_sim n-blocks (128 keys each)
#define NSPL 16        // k_acc split-K parts (2048 keys each)

// ---------------- static scratch ----------------
__device__ float  g_gates[B_ * G4_];
__device__ float  g_hnew [B_ * U_];
__device__ float  g_kt   [QT_ * M_];          // raw tanh keys fp32 (scatter)
__device__ __half g_ktsh [QT_ * M_];          // normalized keys fp16 [q][m]
__device__ __half g_ktTh [R_ * M_ * B_];      // raw keys fp16 transposed [r][m][b]
__device__ float  g_alpha[B_ * R_];
__device__ int    g_least[B_];
__device__ __half g_Ash  [N_ * M_];           // A rows / ||A[n]|| fp16 [n][m]
__device__ __half g_dA   [R_ * M_ * N_];      // write deltas fp16 [r][m][n]
__device__ float  g_emask[N_];
__device__ __half g_AnT  [M_ * N_];           // new memory fp16 [m][n]
__device__ __half g_E    [(size_t)QT_ * N_];  // exp(similarity) fp16 [q][n]
__device__ float  g_pden [QT_ * NBLK];
__device__ float  g_pacc [QT_ * NSPL * M_];

__device__ __forceinline__ float sigmoidf(float v) { return 1.0f / (1.0f + expf(-v)); }

__device__ __forceinline__ uint32_t smem_u32(const void* p) {
    uint32_t a;
    asm("{ .reg .u64 t; cvta.to.shared.u64 t, %1; cvt.u32.u64 %0, t; }" : "=r"(a) : "l"(p));
    return a;
}
__device__ __forceinline__ void ldsm4(uint32_t* r, uint32_t addr) {
    asm volatile("ldmatrix.sync.aligned.m8n8.x4.shared.b16 {%0,%1,%2,%3}, [%4];"
        : "=r"(r[0]), "=r"(r[1]), "=r"(r[2]), "=r"(r[3]) : "r"(addr));
}
__device__ __forceinline__ void ldsm4t(uint32_t* r, uint32_t addr) {
    asm volatile("ldmatrix.sync.aligned.m8n8.x4.trans.shared.b16 {%0,%1,%2,%3}, [%4];"
        : "=r"(r[0]), "=r"(r[1]), "=r"(r[2]), "=r"(r[3]) : "r"(addr));
}
__device__ __forceinline__ void mma16816(float* c, const uint32_t* a, uint32_t b0, uint32_t b1) {
    asm volatile("mma.sync.aligned.m16n8k16.row.col.f32.f16.f16.f32 "
        "{%0,%1,%2,%3}, {%4,%5,%6,%7}, {%8,%9}, {%0,%1,%2,%3};"
        : "+f"(c[0]), "+f"(c[1]), "+f"(c[2]), "+f"(c[3])
        : "r"(a[0]), "r"(a[1]), "r"(a[2]), "r"(a[3]), "r"(b0), "r"(b1));
}

// ---------------- K1: gates = [x|read_prev|h] @ [W;Uw] + b ----------------
__global__ void k_gates(const float* __restrict__ x, const float* __restrict__ rp,
                        const float* __restrict__ h, const float* __restrict__ W,
                        const float* __restrict__ Uw, const float* __restrict__ bias) {
    const int BM = 64, BN = 64, BK = 16;
    __shared__ float sA[BM][BK + 1];
    __shared__ float sB[BK][BN];
    int t  = threadIdx.x;
    int b0 = blockIdx.y * BM;
    int j0 = blockIdx.x * BN;
    int tr = t >> 4, tc = t & 15;
    float acc[4][4] = {};
    for (int k0 = 0; k0 < 1024; k0 += BK) {
        for (int l = t; l < BM * BK; l += 256) {
            int i = l >> 4, k = l & 15;
            int kk = k0 + k, b = b0 + i;
            float v;
            if (kk < DIN_)          v = x[b * DIN_ + kk];
            else if (kk < 768) { int idx = kk - DIN_; v = rp[((idx >> 6) * B_ + b) * M_ + (idx & 63)]; }
            else                    v = h[b * U_ + (kk - 768)];
            sA[i][k] = v;
        }
        for (int l = t; l < BK * BN; l += 256) {
            int k = l >> 6, j = l & 63;
            int kk = k0 + k;
            sB[k][j] = (kk < 768) ? W[kk * G4_ + j0 + j] : Uw[(kk - 768) * G4_ + j0 + j];
        }
        __syncthreads();
        #pragma unroll
        for (int k = 0; k < BK; k++) {
            float a[4], bb[4];
            #pragma unroll
            for (int i = 0; i < 4; i++) a[i] = sA[tr * 4 + i][k];
            float4 b4 = *(const float4*)&sB[k][tc * 4];
            bb[0] = b4.x; bb[1] = b4.y; bb[2] = b4.z; bb[3] = b4.w;
            #pragma unroll
            for (int i = 0; i < 4; i++)
                #pragma unroll
                for (int j = 0; j < 4; j++) acc[i][j] += a[i] * bb[j];
        }
        __syncthreads();
    }
    #pragma unroll
    for (int i = 0; i < 4; i++)
        #pragma unroll
        for (int j = 0; j < 4; j++)
            g_gates[(b0 + tr * 4 + i) * G4_ + j0 + tc * 4 + j] = acc[i][j] + bias[j0 + tc * 4 + j];
}

// ---------------- K2: LSTM pointwise -> h_new ----------------
__global__ void k_lstm(const float* __restrict__ c, float* __restrict__ out) {
    int idx = blockIdx.x * 256 + threadIdx.x;
    int b = idx >> 8, u = idx & 255;
    const float* g = g_gates + b * G4_;
    float gi = g[u], gf = g[256 + u], gg = g[512 + u], go = g[768 + u];
    float cn = sigmoidf(gf) * c[idx] + sigmoidf(gi) * tanhf(gg);
    float hn = sigmoidf(go) * tanhf(cn);
    g_hnew[idx] = hn;
    out[b * 512 + u] = hn;
}

// ---------------- K3: keys: raw fp32 + raw fp16 transposed + normalized fp16 ----------
__global__ void k_kt(const float* __restrict__ Wk, const float* __restrict__ bk) {
    int q = blockIdx.x;            // r*B + b
    int r = q >> 8, b = q & 255;
    int m = threadIdx.x;           // 64 threads
    __shared__ float hs[U_];
    __shared__ float red[2];
    ((float4*)hs)[m] = ((const float4*)(g_hnew + b * U_))[m];
    __syncthreads();
    float acc = bk[r * M_ + m];
    const float* wk = Wk + r * U_ * M_ + m;
    #pragma unroll 8
    for (int u = 0; u < U_; u++) acc += hs[u] * wk[u * M_];
    float kt = tanhf(acc);
    g_kt[q * M_ + m] = kt;
    g_ktTh[(r * M_ + m) * B_ + b] = __float2half(kt);
    float s = kt * kt;
    #pragma unroll
    for (int o = 16; o > 0; o >>= 1) s += __shfl_xor_sync(0xffffffffu, s, o);
    if ((m & 31) == 0) red[m >> 5] = s;
    __syncthreads();
    float inv = 1.0f / sqrtf(red[0] + red[1]);
    g_ktsh[q * M_ + m] = __float2half(kt * inv);
}

// ---------------- K3b: alpha = sigmoid(tanh(h_new @ Wa + ba)) ----------------
__global__ void k_alpha(const float* __restrict__ Wa, const float* __restrict__ ba) {
    int b = blockIdx.x, l = threadIdx.x;   // 32 threads
    const float4* hp = (const float4*)(g_hnew + b * U_);
    float4 h0 = hp[l * 2], h1 = hp[l * 2 + 1];
    float hb[8] = { h0.x, h0.y, h0.z, h0.w, h1.x, h1.y, h1.z, h1.w };
    float a0 = 0, a1 = 0, a2 = 0, a3 = 0;
    #pragma unroll
    for (int i = 0; i < 8; i++) {
        float4 w = *(const float4*)(Wa + (l * 8 + i) * 4);
        a0 += hb[i] * w.x; a1 += hb[i] * w.y; a2 += hb[i] * w.z; a3 += hb[i] * w.w;
    }
    #pragma unroll
    for (int o = 16; o > 0; o >>= 1) {
        a0 += __shfl_xor_sync(0xffffffffu, a0, o);
        a1 += __shfl_xor_sync(0xffffffffu, a1, o);
        a2 += __shfl_xor_sync(0xffffffffu, a2, o);
        a3 += __shfl_xor_sync(0xffffffffu, a3, o);
    }
    if (l == 0) {
        g_alpha[b * 4 + 0] = sigmoidf(tanhf(a0 + ba[0]));
        g_alpha[b * 4 + 1] = sigmoidf(tanhf(a1 + ba[1]));
        g_alpha[b * 4 + 2] = sigmoidf(tanhf(a2 + ba[2]));
        g_alpha[b * 4 + 3] = sigmoidf(tanhf(a3 + ba[3]));
    }
}

// ---------------- K4: least[b] = argmin_n wu_prev[b,n] (first-min) ----------------
__global__ void k_argmin(const float* __restrict__ wu) {
    int b = blockIdx.x, t = threadIdx.x;
    const float4* row = (const float4*)(wu + (size_t)b * N_);
    float mv = 3.4e38f; int mi = 0;
    for (int i = t; i < N_ / 4; i += 256) {
        float4 v = row[i];
        int base = i * 4;
        if (v.x < mv) { mv = v.x; mi = base; }
        if (v.y < mv) { mv = v.y; mi = base + 1; }
        if (v.z < mv) { mv = v.z; mi = base + 2; }
        if (v.w < mv) { mv = v.w; mi = base + 3; }
    }
    __shared__ float sv[256];
    __shared__ int   si[256];
    sv[t] = mv; si[t] = mi;
    __syncthreads();
    for (int s = 128; s > 0; s >>= 1) {
        if (t < s) {
            if (sv[t + s] < sv[t] || (sv[t + s] == sv[t] && si[t + s] < si[t])) {
                sv[t] = sv[t + s]; si[t] = si[t + s];
            }
        }
        __syncthreads();
    }
    if (t == 0) g_least[b] = si[0];
}

// ---------------- K5: Ash[n,:] = fp16( A[n,:] / ||A[n,:]|| ) ----------------
__global__ void k_As(const float* __restrict__ A) {
    int n = blockIdx.x * 8 + (threadIdx.x >> 5);
    int lane = threadIdx.x & 31;
    float a0 = A[n * M_ + lane], a1 = A[n * M_ + 32 + lane];
    float s = a0 * a0 + a1 * a1;
    #pragma unroll
    for (int o = 16; o > 0; o >>= 1) s += __shfl_xor_sync(0xffffffffu, s, o);
    float inv = 1.0f / sqrtf(s);
    g_Ash[n * M_ + lane]      = __float2half(a0 * inv);
    g_Ash[n * M_ + 32 + lane] = __float2half(a1 * inv);
}

// ---------------- K6: similarity + exp (tensor cores). CTA: 128 q x 128 n ------------
__global__ void __launch_bounds__(256) k_sim() {
    __shared__ __align__(16) __half sbuf[2 * 128 * 72];
    const int t = threadIdx.x, w = t >> 5, l = t & 31;
    const int q0 = blockIdx.y * 128, n0 = blockIdx.x * 128;
    __half* sQ = sbuf;              // [128][72]
    __half* sK = sbuf + 128 * 72;   // [128][72]
    for (int idx = t; idx < 1024; idx += 256) {
        int row = idx >> 3, c4 = idx & 7;
        *(uint4*)(sQ + row * 72 + c4 * 8) = *(const uint4*)(g_ktsh + (size_t)(q0 + row) * M_ + c4 * 8);
        *(uint4*)(sK + row * 72 + c4 * 8) = *(const uint4*)(g_Ash  + (size_t)(n0 + row) * M_ + c4 * 8);
    }
    __syncthreads();
    float acc[16][4] = {};
    uint32_t qb = smem_u32(sQ), kb = smem_u32(sK);
    #pragma unroll
    for (int k16 = 0; k16 < 4; k16++) {
        uint32_t a[4];
        ldsm4(a, qb + ((w * 16 + (l & 15)) * 72 + (l >> 4) * 8 + k16 * 16) * 2);
        #pragma unroll
        for (int j = 0; j < 8; j++) {
            uint32_t bb[4];
            ldsm4(bb, kb + ((j * 16 + (l & 15)) * 72 + (l >> 4) * 8 + k16 * 16) * 2);
            mma16816(acc[2 * j],     a, bb[0], bb[2]);
            mma16816(acc[2 * j + 1], a, bb[1], bb[3]);
        }
    }
    __syncthreads();
    // epilogue: exp -> smem staging [128][136], accumulate per-row denominators
    __half* sE = sbuf;
    float den0 = 0.0f, den1 = 0.0f;
    int r0 = w * 16 + (l >> 2), cb = (l & 3) * 2;
    #pragma unroll
    for (int jj = 0; jj < 16; jj++) {
        float e0 = __expf(acc[jj][0]), e1 = __expf(acc[jj][1]);
        float e2 = __expf(acc[jj][2]), e3 = __expf(acc[jj][3]);
        den0 += e0 + e1; den1 += e2 + e3;
        *(__half2*)(sE + r0 * 136 + jj * 8 + cb)       = __floats2half2_rn(e0, e1);
        *(__half2*)(sE + (r0 + 8) * 136 + jj * 8 + cb) = __floats2half2_rn(e2, e3);
    }
    den0 += __shfl_xor_sync(0xffffffffu, den0, 1);
    den0 += __shfl_xor_sync(0xffffffffu, den0, 2);
    den1 += __shfl_xor_sync(0xffffffffu, den1, 1);
    den1 += __shfl_xor_sync(0xffffffffu, den1, 2);
    if ((l & 3) == 0) {
        g_pden[(q0 + r0) * NBLK + blockIdx.x]     = den0;
        g_pden[(q0 + r0 + 8) * NBLK + blockIdx.x] = den1;
    }
    __syncthreads();
    for (int idx = t; idx < 2048; idx += 256) {
        int row = idx >> 4, c4 = idx & 15;
        *(uint4*)(g_E + (size_t)(q0 + row) * N_ + n0 + c4 * 8) = *(const uint4*)(sE + row * 136 + c4 * 8);
    }
}

// ---------------- K7: write deltas (tensor). D[m][n] = kt^T @ (alpha.*wr_prev) -------
// grid (N_/256, R_), 256 threads. CTA: 64 m x 256 n, K = 256 batch.
__global__ void __launch_bounds__(256) k_dA(const float* __restrict__ wrp) {
    __shared__ __align__(16) __half sP[64 * 264];   // [b-chunk 64][n 256 +8]
    __shared__ __align__(16) __half sA[64 * 72];    // [m 64][b-chunk 64 +8]
    __shared__ float salpha[B_];
    const int t = threadIdx.x, w = t >> 5, l = t & 31;
    const int n0 = blockIdx.x * 256, r = blockIdx.y;
    salpha[t] = g_alpha[t * R_ + r];
    const int mrow = (w & 3) * 16, nhalf = (w >> 2) * 128;
    const float* wr_base = wrp + (size_t)r * B_ * N_;
    float acc[16][4] = {};
    uint32_t pb = smem_u32(sP), ab = smem_u32(sA);
    for (int kt = 0; kt < 4; kt++) {
        __syncthreads();
        for (int idx = t; idx < 512; idx += 256) {
            int row = idx >> 3, c4 = idx & 7;
            *(uint4*)(sA + row * 72 + c4 * 8) =
                *(const uint4*)(g_ktTh + (size_t)(r * M_ + row) * B_ + kt * 64 + c4 * 8);
        }
        for (int idx = t; idx < 4096; idx += 256) {
            int row = idx >> 6, c = idx & 63;
            float4 v = *(const float4*)(wr_base + (size_t)(kt * 64 + row) * N_ + n0 + c * 4);
            float al = salpha[kt * 64 + row];
            *(__half2*)(sP + row * 264 + c * 4)     = __floats2half2_rn(v.x * al, v.y * al);
            *(__half2*)(sP + row * 264 + c * 4 + 2) = __floats2half2_rn(v.z * al, v.w * al);
        }
        __syncthreads();
        #pragma unroll
        for (int k16 = 0; k16 < 4; k16++) {
            uint32_t a[4];
            ldsm4(a, ab + ((mrow + (l & 15)) * 72 + (l >> 4) * 8 + k16 * 16) * 2);
            #pragma unroll
            for (int j = 0; j < 8; j++) {
                uint32_t bb[4];
                int rowb = k16 * 16 + (l & 7) + ((l >> 3) & 1) * 8;
                int colb = nhalf + j * 16 + ((l >> 4) & 1) * 8;
                ldsm4t(bb, pb + (rowb * 264 + colb) * 2);
                mma16816(acc[2 * j],     a, bb[0], bb[1]);
                mma16816(acc[2 * j + 1], a, bb[2], bb[3]);
            }
        }
    }
    int m0 = mrow + (l >> 2), cb = n0 + nhalf + (l & 3) * 2;
    #pragma unroll
    for (int jj = 0; jj < 16; jj++) {
        *(__half2*)(g_dA + (size_t)(r * M_ + m0) * N_ + cb + jj * 8) =
            __floats2half2_rn(acc[jj][0], acc[jj][1]);
        *(__half2*)(g_dA + (size_t)(r * M_ + m0 + 8) * N_ + cb + jj * 8) =
            __floats2half2_rn(acc[jj][2], acc[jj][3]);
    }
}

// ---------------- K8: deterministic least-used scatter into g_dA ----------------
__global__ void k_scatter() {
    const int r = blockIdx.y;
    __shared__ int sL[B_];
    int t = threadIdx.x, b = blockIdx.x;
    sL[t] = g_least[t];
    __syncthreads();
    int my = sL[b];
    bool owner = true;
    for (int bb = 0; bb < b; bb++) if (sL[bb] == my) { owner = false; break; }
    if (!owner) return;
    if (t < M_) {
        float acc = 0.0f;
        for (int bb = b; bb < B_; bb++)
            if (sL[bb] == my)
                acc += (1.0f - g_alpha[bb * R_ + r]) * g_kt[((r << 8) + bb) * M_ + t];
        size_t o = (size_t)(r * M_ + t) * N_ + my;
        g_dA[o] = __float2half(__half2float(g_dA[o]) + acc);
    }
}

// ---------------- K9: erase mask ----------------
__global__ void k_einit() { g_emask[blockIdx.x * 256 + threadIdx.x] = 1.0f; }
__global__ void k_eset()  { g_emask[g_least[threadIdx.x]] = 0.0f; }

// ---------------- K10: chain: AnT = fp16(tanh^4 chain of A*e + deltas) ----------------
__global__ void k_chain(const float* __restrict__ A) {
    __shared__ float sT[64][65];
    __shared__ float se[64];
    int t = threadIdx.x, n0 = blockIdx.x * 64;
    for (int idx = t; idx < 4096; idx += 256) {
        int row = idx >> 6, c = idx & 63;
        sT[row][c] = A[(size_t)(n0 + row) * M_ + c];
    }
    if (t < 64) se[t] = g_emask[n0 + t];
    __syncthreads();
    for (int idx = t; idx < 4096; idx += 256) {
        int m = idx >> 6, n = idx & 63;
        float a = sT[n][m] * se[n];
        #pragma unroll
        for (int r = 0; r < 4; r++)
            a = tanhf(a + __half2float(g_dA[(size_t)(r * M_ + m) * N_ + n0 + n]));
        g_AnT[(size_t)m * N_ + n0 + n] = __float2half(a);
    }
}

// ---------------- K11: numerator GEMM (tensor): pacc = E @ AnT^T, split-K -------------
__global__ void __launch_bounds__(256) k_acc() {
    __shared__ __align__(16) __half sE[128 * 72];
    __shared__ __align__(16) __half sV[64 * 72];
    const int t = threadIdx.x, w = t >> 5, l = t & 31;
    const int q0 = blockIdx.y * 128, k0 = blockIdx.x * 2048;
    float acc[8][4] = {};
    uint32_t eb = smem_u32(sE), vb = smem_u32(sV);
    for (int kt = 0; kt < 32; kt++) {
        __syncthreads();
        int kg = k0 + kt * 64;
        for (int idx = t; idx < 1024; idx += 256) {
            int row = idx >> 3, c4 = idx & 7;
            *(uint4*)(sE + row * 72 + c4 * 8) = *(const uint4*)(g_E + (size_t)(q0 + row) * N_ + kg + c4 * 8);
        }
        for (int idx = t; idx < 512; idx += 256) {
            int row = idx >> 3, c4 = idx & 7;
            *(uint4*)(sV + row * 72 + c4 * 8) = *(const uint4*)(g_AnT + (size_t)row * N_ + kg + c4 * 8);
        }
        __syncthreads();
        #pragma unroll
        for (int k16 = 0; k16 < 4; k16++) {
            uint32_t a[4];
            ldsm4(a, eb + ((w * 16 + (l & 15)) * 72 + (l >> 4) * 8 + k16 * 16) * 2);
            #pragma unroll
            for (int j = 0; j < 4; j++) {
                uint32_t bb[4];
                ldsm4(bb, vb + ((j * 16 + (l & 15)) * 72 + (l >> 4) * 8 + k16 * 16) * 2);
                mma16816(acc[2 * j],     a, bb[0], bb[2]);
                mma16816(acc[2 * j + 1], a, bb[1], bb[3]);
            }
        }
    }
    int r0 = q0 + w * 16 + (l >> 2), cb = (l & 3) * 2;
    float* p0 = g_pacc + ((size_t)r0 * NSPL + blockIdx.x) * M_;
    float* p1 = g_pacc + ((size_t)(r0 + 8) * NSPL + blockIdx.x) * M_;
    #pragma unroll
    for (int jj = 0; jj < 8; jj++) {
        *(float2*)(p0 + jj * 8 + cb) = make_float2(acc[jj][0], acc[jj][1]);
        *(float2*)(p1 + jj * 8 + cb) = make_float2(acc[jj][2], acc[jj][3]);
    }
}

// ---------------- K12: combine partials -> out[:, 256:512] ----------------
__global__ void k_combine(float* __restrict__ out) {
    int q = blockIdx.x;          // r*B + b
    int m = threadIdx.x;         // 64
    __shared__ float sd[64];
    float d = 0.0f;
    #pragma unroll
    for (int i = 0; i < 4; i++) d += g_pden[q * NBLK + m * 4 + i];
    sd[m] = d;
    __syncthreads();
    for (int s = 32; s > 0; s >>= 1) {
        if (m < s) sd[m] += sd[m + s];
        __syncthreads();
    }
    float den = sd[0];
    float acc = 0.0f;
    #pragma unroll
    for (int s = 0; s < NSPL; s++) acc += g_pacc[((size_t)q * NSPL + s) * M_ + m];
    int r = q >> 8, b = q & 255;
    out[b * 512 + 256 + r * M_ + m] = acc / den;
}

// ---------------- launch ----------------
extern "C" void kernel_launch(void* const* d_in, const int* in_sizes, int n_in,
                              void* d_out, int out_size) {
    const float* x    = (const float*)d_in[0];
    const float* A    = (const float*)d_in[1];
    const float* wrp  = (const float*)d_in[2];
    const float* wu   = (const float*)d_in[3];
    const float* rp   = (const float*)d_in[4];
    const float* h    = (const float*)d_in[5];
    const float* c    = (const float*)d_in[6];
    const float* W    = (const float*)d_in[7];
    const float* Uw   = (const float*)d_in[8];
    const float* bias = (const float*)d_in[9];
    const float* Wk   = (const float*)d_in[10];
    const float* bk   = (const float*)d_in[11];
    const float* Wa   = (const float*)d_in[12];
    const float* ba   = (const float*)d_in[13];
    float* out = (float*)d_out;

    k_gates  <<<dim3(16, 4), 256>>>(x, rp, h, W, Uw, bias);
    k_lstm   <<<256, 256>>>(c, out);
    k_kt     <<<QT_, 64>>>(Wk, bk);
    k_alpha  <<<B_, 32>>>(Wa, ba);
    k_argmin <<<B_, 256>>>(wu);
    k_As     <<<N_ / 8, 256>>>(A);
    k_sim    <<<dim3(NBLK, 8), 256>>>();
    k_dA     <<<dim3(N_ / 256, R_), 256>>>(wrp);
    k_scatter<<<dim3(B_, R_), 256>>>();
    k_einit  <<<N_ / 256, 256>>>();
    k_eset   <<<1, 256>>>();
    k_chain  <<<N_ / 64, 256>>>(A);
    k_acc    <<<dim3(NSPL, 8), 256>>>();
    k_combine<<<QT_, 64>>>(out);
}

// round 4
// speedup vs baseline: 3.1252x; 1.2194x over previous
#include <cuda_runtime.h>
#include <cuda_fp16.h>
#include <math.h>
#include <stdint.h>

// Problem constants
#define B_   256
#define N_   32768
#define M_   64
#define R_   4
#define U_   256
#define DIN_ 512
#define G4_  1024
#define QT_  1024      // total queries = R*B
#define NSPL 32        // flash reads: split of N (1024 keys per chunk)

// ---------------- static scratch ----------------
__device__ float  g_gates[B_ * G4_];
__device__ float  g_hnew [B_ * U_];
__device__ float  g_kt   [QT_ * M_];          // raw tanh keys fp32 (scatter)
__device__ __half g_ktsh [QT_ * M_];          // normalized keys fp16 [q][m]
__device__ __half g_ktTh [R_ * M_ * B_];      // raw keys fp16 transposed [r][m][b]
__device__ float  g_alpha[B_ * R_];
__device__ int    g_least[B_];
__device__ __half g_Ash  [N_ * M_];           // A rows / ||A[n]|| fp16 [n][m]
__device__ __half g_dA   [R_ * M_ * N_];      // write deltas fp16 [r][m][n]
__device__ float  g_emask[N_];
__device__ __half g_AnT  [M_ * N_];           // new memory fp16 [m][n]
__device__ float  g_pden [QT_ * NSPL];
__device__ float  g_pacc [QT_ * NSPL * M_];

__device__ __forceinline__ float sigmoidf(float v) { return 1.0f / (1.0f + expf(-v)); }

__device__ __forceinline__ uint32_t smem_u32(const void* p) {
    uint32_t a;
    asm("{ .reg .u64 t; cvta.to.shared.u64 t, %1; cvt.u32.u64 %0, t; }" : "=r"(a) : "l"(p));
    return a;
}
__device__ __forceinline__ void ldsm4(uint32_t* r, uint32_t addr) {
    asm volatile("ldmatrix.sync.aligned.m8n8.x4.shared.b16 {%0,%1,%2,%3}, [%4];"
        : "=r"(r[0]), "=r"(r[1]), "=r"(r[2]), "=r"(r[3]) : "r"(addr));
}
__device__ __forceinline__ void ldsm4t(uint32_t* r, uint32_t addr) {
    asm volatile("ldmatrix.sync.aligned.m8n8.x4.trans.shared.b16 {%0,%1,%2,%3}, [%4];"
        : "=r"(r[0]), "=r"(r[1]), "=r"(r[2]), "=r"(r[3]) : "r"(addr));
}
__device__ __forceinline__ void mma16816(float* c, const uint32_t* a, uint32_t b0, uint32_t b1) {
    asm volatile("mma.sync.aligned.m16n8k16.row.col.f32.f16.f16.f32 "
        "{%0,%1,%2,%3}, {%4,%5,%6,%7}, {%8,%9}, {%0,%1,%2,%3};"
        : "+f"(c[0]), "+f"(c[1]), "+f"(c[2]), "+f"(c[3])
        : "r"(a[0]), "r"(a[1]), "r"(a[2]), "r"(a[3]), "r"(b0), "r"(b1));
}
__device__ __forceinline__ uint32_t packh2(float a, float b) {
    __half2 h = __floats2half2_rn(a, b);
    return *(uint32_t*)&h;
}

// ---------------- K1: gates = [x|read_prev|h] @ [W;Uw] + b ----------------
__global__ void k_gates(const float* __restrict__ x, const float* __restrict__ rp,
                        const float* __restrict__ h, const float* __restrict__ W,
                        const float* __restrict__ Uw, const float* __restrict__ bias) {
    const int BM = 64, BN = 64, BK = 16;
    __shared__ float sA[BM][BK + 1];
    __shared__ float sB[BK][BN];
    int t  = threadIdx.x;
    int b0 = blockIdx.y * BM;
    int j0 = blockIdx.x * BN;
    int tr = t >> 4, tc = t & 15;
    float acc[4][4] = {};
    for (int k0 = 0; k0 < 1024; k0 += BK) {
        for (int l = t; l < BM * BK; l += 256) {
            int i = l >> 4, k = l & 15;
            int kk = k0 + k, b = b0 + i;
            float v;
            if (kk < DIN_)          v = x[b * DIN_ + kk];
            else if (kk < 768) { int idx = kk - DIN_; v = rp[((idx >> 6) * B_ + b) * M_ + (idx & 63)]; }
            else                    v = h[b * U_ + (kk - 768)];
            sA[i][k] = v;
        }
        for (int l = t; l < BK * BN; l += 256) {
            int k = l >> 6, j = l & 63;
            int kk = k0 + k;
            sB[k][j] = (kk < 768) ? W[kk * G4_ + j0 + j] : Uw[(kk - 768) * G4_ + j0 + j];
        }
        __syncthreads();
        #pragma unroll
        for (int k = 0; k < BK; k++) {
            float a[4], bb[4];
            #pragma unroll
            for (int i = 0; i < 4; i++) a[i] = sA[tr * 4 + i][k];
            float4 b4 = *(const float4*)&sB[k][tc * 4];
            bb[0] = b4.x; bb[1] = b4.y; bb[2] = b4.z; bb[3] = b4.w;
            #pragma unroll
            for (int i = 0; i < 4; i++)
                #pragma unroll
                for (int j = 0; j < 4; j++) acc[i][j] += a[i] * bb[j];
        }
        __syncthreads();
    }
    #pragma unroll
    for (int i = 0; i < 4; i++)
        #pragma unroll
        for (int j = 0; j < 4; j++)
            g_gates[(b0 + tr * 4 + i) * G4_ + j0 + tc * 4 + j] = acc[i][j] + bias[j0 + tc * 4 + j];
}

// ---------------- K2: LSTM pointwise -> h_new, fused alpha ----------------
// block = one batch row b (256 threads = 256 u)
__global__ void k_lstm(const float* __restrict__ c, float* __restrict__ out,
                       const float* __restrict__ Wa, const float* __restrict__ ba) {
    int b = blockIdx.x, u = threadIdx.x;
    int idx = b * 256 + u;
    const float* g = g_gates + b * G4_;
    float gi = g[u], gf = g[256 + u], gg = g[512 + u], go = g[768 + u];
    float cn = sigmoidf(gf) * c[idx] + sigmoidf(gi) * tanhf(gg);
    float hn = sigmoidf(go) * tanhf(cn);
    g_hnew[idx] = hn;
    out[b * 512 + u] = hn;
    // alpha[b][0..3] = sigmoid(tanh(sum_u hn*Wa[u][r] + ba[r]))
    __shared__ float red[8][4];
    float4 w4 = *(const float4*)(Wa + u * 4);
    float p0 = hn * w4.x, p1 = hn * w4.y, p2 = hn * w4.z, p3 = hn * w4.w;
    #pragma unroll
    for (int o = 16; o > 0; o >>= 1) {
        p0 += __shfl_xor_sync(0xffffffffu, p0, o);
        p1 += __shfl_xor_sync(0xffffffffu, p1, o);
        p2 += __shfl_xor_sync(0xffffffffu, p2, o);
        p3 += __shfl_xor_sync(0xffffffffu, p3, o);
    }
    if ((u & 31) == 0) {
        red[u >> 5][0] = p0; red[u >> 5][1] = p1;
        red[u >> 5][2] = p2; red[u >> 5][3] = p3;
    }
    __syncthreads();
    if (u < 4) {
        float a = ba[u];
        #pragma unroll
        for (int i = 0; i < 8; i++) a += red[i][u];
        g_alpha[b * 4 + u] = sigmoidf(tanhf(a));
    }
}

// ---------------- K3: keys: raw fp32 + raw fp16 transposed + normalized fp16 ----------
__global__ void k_kt(const float* __restrict__ Wk, const float* __restrict__ bk) {
    int q = blockIdx.x;            // r*B + b
    int r = q >> 8, b = q & 255;
    int m = threadIdx.x;           // 64 threads
    __shared__ float hs[U_];
    __shared__ float red[2];
    ((float4*)hs)[m] = ((const float4*)(g_hnew + b * U_))[m];
    __syncthreads();
    float acc = bk[r * M_ + m];
    const float* wk = Wk + r * U_ * M_ + m;
    #pragma unroll 8
    for (int u = 0; u < U_; u++) acc += hs[u] * wk[u * M_];
    float kt = tanhf(acc);
    g_kt[q * M_ + m] = kt;
    g_ktTh[(r * M_ + m) * B_ + b] = __float2half(kt);
    float s = kt * kt;
    #pragma unroll
    for (int o = 16; o > 0; o >>= 1) s += __shfl_xor_sync(0xffffffffu, s, o);
    if ((m & 31) == 0) red[m >> 5] = s;
    __syncthreads();
    float inv = 1.0f / sqrtf(red[0] + red[1]);
    g_ktsh[q * M_ + m] = __float2half(kt * inv);
}

// ---------------- K4: write deltas (tensor). dA[r][m][n] = kt[r]^T @ (alpha.*wr_prev[r])
__global__ void __launch_bounds__(256) k_dA(const float* __restrict__ wrp) {
    __shared__ __align__(16) __half sP[64 * 264];   // [b-chunk 64][n 256 +8]
    __shared__ __align__(16) __half sA[64 * 72];    // [m 64][b-chunk 64 +8]
    __shared__ float salpha[B_];
    const int t = threadIdx.x, w = t >> 5, l = t & 31;
    const int n0 = blockIdx.x * 256, r = blockIdx.y;
    salpha[t] = g_alpha[t * R_ + r];
    const int mrow = (w & 3) * 16, nhalf = (w >> 2) * 128;
    const float* wr_base = wrp + (size_t)r * B_ * N_;
    float acc[16][4] = {};
    uint32_t pb = smem_u32(sP), ab = smem_u32(sA);
    for (int kt = 0; kt < 4; kt++) {
        __syncthreads();
        for (int idx = t; idx < 512; idx += 256) {
            int row = idx >> 3, c4 = idx & 7;
            *(uint4*)(sA + row * 72 + c4 * 8) =
                *(const uint4*)(g_ktTh + (size_t)(r * M_ + row) * B_ + kt * 64 + c4 * 8);
        }
        for (int idx = t; idx < 4096; idx += 256) {
            int row = idx >> 6, c = idx & 63;
            float4 v = *(const float4*)(wr_base + (size_t)(kt * 64 + row) * N_ + n0 + c * 4);
            float al = salpha[kt * 64 + row];
            *(__half2*)(sP + row * 264 + c * 4)     = __floats2half2_rn(v.x * al, v.y * al);
            *(__half2*)(sP + row * 264 + c * 4 + 2) = __floats2half2_rn(v.z * al, v.w * al);
        }
        __syncthreads();
        #pragma unroll
        for (int k16 = 0; k16 < 4; k16++) {
            uint32_t a[4];
            ldsm4(a, ab + ((mrow + (l & 15)) * 72 + (l >> 4) * 8 + k16 * 16) * 2);
            #pragma unroll
            for (int j = 0; j < 8; j++) {
                uint32_t bb[4];
                int rowb = k16 * 16 + (l & 7) + ((l >> 3) & 1) * 8;
                int colb = nhalf + j * 16 + ((l >> 4) & 1) * 8;
                ldsm4t(bb, pb + (rowb * 264 + colb) * 2);
                mma16816(acc[2 * j],     a, bb[0], bb[1]);
                mma16816(acc[2 * j + 1], a, bb[2], bb[3]);
            }
        }
    }
    int m0 = mrow + (l >> 2), cb = n0 + nhalf + (l & 3) * 2;
    #pragma unroll
    for (int jj = 0; jj < 16; jj++) {
        *(__half2*)(g_dA + (size_t)(r * M_ + m0) * N_ + cb + jj * 8) =
            __floats2half2_rn(acc[jj][0], acc[jj][1]);
        *(__half2*)(g_dA + (size_t)(r * M_ + m0 + 8) * N_ + cb + jj * 8) =
            __floats2half2_rn(acc[jj][2], acc[jj][3]);
    }
}

// ---------------- K5: least[b] = argmin_n wu_prev[b,n] (first-min) ----------------
__global__ void k_argmin(const float* __restrict__ wu) {
    int b = blockIdx.x, t = threadIdx.x;
    const float4* row = (const float4*)(wu + (size_t)b * N_);
    float mv = 3.4e38f; int mi = 0;
    for (int i = t; i < N_ / 4; i += 256) {
        float4 v = row[i];
        int base = i * 4;
        if (v.x < mv) { mv = v.x; mi = base; }
        if (v.y < mv) { mv = v.y; mi = base + 1; }
        if (v.z < mv) { mv = v.z; mi = base + 2; }
        if (v.w < mv) { mv = v.w; mi = base + 3; }
    }
    __shared__ float sv[256];
    __shared__ int   si[256];
    sv[t] = mv; si[t] = mi;
    __syncthreads();
    for (int s = 128; s > 0; s >>= 1) {
        if (t < s) {
            if (sv[t + s] < sv[t] || (sv[t + s] == sv[t] && si[t + s] < si[t])) {
                sv[t] = sv[t + s]; si[t] = si[t + s];
            }
        }
        __syncthreads();
    }
    if (t == 0) g_least[b] = si[0];
}

// ---------------- K6: Ash[n,:] = fp16( A[n,:] / ||A[n,:]|| ); emask = 1 ----------------
__global__ void k_As(const float* __restrict__ A) {
    int n = blockIdx.x * 8 + (threadIdx.x >> 5);
    int lane = threadIdx.x & 31;
    float a0 = A[n * M_ + lane], a1 = A[n * M_ + 32 + lane];
    float s = a0 * a0 + a1 * a1;
    #pragma unroll
    for (int o = 16; o > 0; o >>= 1) s += __shfl_xor_sync(0xffffffffu, s, o);
    float inv = 1.0f / sqrtf(s);
    g_Ash[n * M_ + lane]      = __float2half(a0 * inv);
    g_Ash[n * M_ + 32 + lane] = __float2half(a1 * inv);
    if (lane == 0) g_emask[n] = 1.0f;
}
__global__ void k_eset() { g_emask[g_least[threadIdx.x]] = 0.0f; }

// ---------------- K7: deterministic least-used scatter into g_dA ----------------
__global__ void k_scatter() {
    const int r = blockIdx.y;
    __shared__ int sL[B_];
    int t = threadIdx.x, b = blockIdx.x;
    sL[t] = g_least[t];
    __syncthreads();
    int my = sL[b];
    bool owner = true;
    for (int bb = 0; bb < b; bb++) if (sL[bb] == my) { owner = false; break; }
    if (!owner) return;
    if (t < M_) {
        float acc = 0.0f;
        for (int bb = b; bb < B_; bb++)
            if (sL[bb] == my)
                acc += (1.0f - g_alpha[bb * R_ + r]) * g_kt[((r << 8) + bb) * M_ + t];
        size_t o = (size_t)(r * M_ + t) * N_ + my;
        g_dA[o] = __float2half(__half2float(g_dA[o]) + acc);
    }
}

// ---------------- K8: chain: AnT = fp16(tanh^4 chain of A*e + deltas) ----------------
__global__ void k_chain(const float* __restrict__ A) {
    __shared__ float sT[64][65];
    __shared__ float se[64];
    int t = threadIdx.x, n0 = blockIdx.x * 64;
    for (int idx = t; idx < 4096; idx += 256) {
        int row = idx >> 6, c = idx & 63;
        sT[row][c] = A[(size_t)(n0 + row) * M_ + c];
    }
    if (t < 64) se[t] = g_emask[n0 + t];
    __syncthreads();
    for (int idx = t; idx < 4096; idx += 256) {
        int m = idx >> 6, n = idx & 63;
        float a = sT[n][m] * se[n];
        #pragma unroll
        for (int r = 0; r < 4; r++)
            a = tanhf(a + __half2float(g_dA[(size_t)(r * M_ + m) * N_ + n0 + n]));
        g_AnT[(size_t)m * N_ + n0 + n] = __float2half(a);
    }
}

// ---------------- K9: flash fused reads: S=Q·K^T, P=exp(S), O+=P·V ----------------
// grid (NSPL, 8), 256 threads. CTA: 128 queries x 1024-key chunk (8 subtiles of 128).
__global__ void __launch_bounds__(256) k_read() {
    __shared__ __align__(16) __half sQ[128 * 72];
    __shared__ __align__(16) __half sK[128 * 72];
    __shared__ __align__(16) __half sV[64 * 136];
    const int t = threadIdx.x, w = t >> 5, l = t & 31;
    const int q0 = blockIdx.y * 128, n0 = blockIdx.x * 1024;
    for (int idx = t; idx < 1024; idx += 256) {
        int row = idx >> 3, c4 = idx & 7;
        *(uint4*)(sQ + row * 72 + c4 * 8) = *(const uint4*)(g_ktsh + (size_t)(q0 + row) * M_ + c4 * 8);
    }
    uint32_t qb = smem_u32(sQ), kb = smem_u32(sK), vb = smem_u32(sV);
    float acc_o[8][4] = {};
    float den0 = 0.0f, den1 = 0.0f;
    for (int sub = 0; sub < 8; sub++) {
        __syncthreads();
        int kg = n0 + sub * 128;
        for (int idx = t; idx < 1024; idx += 256) {
            int row = idx >> 3, c4 = idx & 7;
            *(uint4*)(sK + row * 72 + c4 * 8) = *(const uint4*)(g_Ash + (size_t)(kg + row) * M_ + c4 * 8);
        }
        for (int idx = t; idx < 1024; idx += 256) {
            int row = idx >> 4, c4 = idx & 15;
            *(uint4*)(sV + row * 136 + c4 * 8) = *(const uint4*)(g_AnT + (size_t)row * N_ + kg + c4 * 8);
        }
        __syncthreads();
        // S = Q · K^T : s[16][4] = 16 n8-col groups
        float s[16][4] = {};
        #pragma unroll
        for (int k16 = 0; k16 < 4; k16++) {
            uint32_t a[4];
            ldsm4(a, qb + ((w * 16 + (l & 15)) * 72 + (l >> 4) * 8 + k16 * 16) * 2);
            #pragma unroll
            for (int j = 0; j < 8; j++) {
                uint32_t bbf[4];
                ldsm4(bbf, kb + ((j * 16 + (l & 15)) * 72 + (l >> 4) * 8 + k16 * 16) * 2);
                mma16816(s[2 * j],     a, bbf[0], bbf[2]);
                mma16816(s[2 * j + 1], a, bbf[1], bbf[3]);
            }
        }
        // per 16-key slice: exp -> A-frag (registers), then O += P·V
        #pragma unroll
        for (int kk = 0; kk < 8; kk++) {
            float e00 = __expf(s[2 * kk][0]),     e01 = __expf(s[2 * kk][1]);
            float e02 = __expf(s[2 * kk][2]),     e03 = __expf(s[2 * kk][3]);
            float e10 = __expf(s[2 * kk + 1][0]), e11 = __expf(s[2 * kk + 1][1]);
            float e12 = __expf(s[2 * kk + 1][2]), e13 = __expf(s[2 * kk + 1][3]);
            den0 += e00 + e01 + e10 + e11;
            den1 += e02 + e03 + e12 + e13;
            uint32_t pa[4];
            pa[0] = packh2(e00, e01);
            pa[1] = packh2(e02, e03);
            pa[2] = packh2(e10, e11);
            pa[3] = packh2(e12, e13);
            #pragma unroll
            for (int j = 0; j < 4; j++) {
                uint32_t bbf[4];
                ldsm4(bbf, vb + ((j * 16 + (l & 15)) * 136 + (l >> 4) * 8 + kk * 16) * 2);
                mma16816(acc_o[2 * j],     pa, bbf[0], bbf[2]);
                mma16816(acc_o[2 * j + 1], pa, bbf[1], bbf[3]);
            }
        }
    }
    den0 += __shfl_xor_sync(0xffffffffu, den0, 1);
    den0 += __shfl_xor_sync(0xffffffffu, den0, 2);
    den1 += __shfl_xor_sync(0xffffffffu, den1, 1);
    den1 += __shfl_xor_sync(0xffffffffu, den1, 2);
    int r0 = q0 + w * 16 + (l >> 2);
    if ((l & 3) == 0) {
        g_pden[r0 * NSPL + blockIdx.x]       = den0;
        g_pden[(r0 + 8) * NSPL + blockIdx.x] = den1;
    }
    float* p0 = g_pacc + ((size_t)r0 * NSPL + blockIdx.x) * M_;
    float* p1 = g_pacc + ((size_t)(r0 + 8) * NSPL + blockIdx.x) * M_;
    int cb = (l & 3) * 2;
    #pragma unroll
    for (int jj = 0; jj < 8; jj++) {
        *(float2*)(p0 + jj * 8 + cb) = make_float2(acc_o[jj][0], acc_o[jj][1]);
        *(float2*)(p1 + jj * 8 + cb) = make_float2(acc_o[jj][2], acc_o[jj][3]);
    }
}

// ---------------- K10: combine partials -> out[:, 256:512] ----------------
__global__ void k_combine(float* __restrict__ out) {
    int q = blockIdx.x;          // r*B + b
    int m = threadIdx.x;         // 64
    float acc = 0.0f, den = 0.0f;
    #pragma unroll
    for (int s = 0; s < NSPL; s++) {
        acc += g_pacc[((size_t)q * NSPL + s) * M_ + m];
        den += g_pden[q * NSPL + s];
    }
    int r = q >> 8, b = q & 255;
    out[b * 512 + 256 + r * M_ + m] = acc / den;
}

// ---------------- launch ----------------
extern "C" void kernel_launch(void* const* d_in, const int* in_sizes, int n_in,
                              void* d_out, int out_size) {
    const float* x    = (const float*)d_in[0];
    const float* A    = (const float*)d_in[1];
    const float* wrp  = (const float*)d_in[2];
    const float* wu   = (const float*)d_in[3];
    const float* rp   = (const float*)d_in[4];
    const float* h    = (const float*)d_in[5];
    const float* c    = (const float*)d_in[6];
    const float* W    = (const float*)d_in[7];
    const float* Uw   = (const float*)d_in[8];
    const float* bias = (const float*)d_in[9];
    const float* Wk   = (const float*)d_in[10];
    const float* bk   = (const float*)d_in[11];
    const float* Wa   = (const float*)d_in[12];
    const float* ba   = (const float*)d_in[13];
    float* out = (float*)d_out;

    k_gates  <<<dim3(16, 4), 256>>>(x, rp, h, W, Uw, bias);   // launch 0
    k_lstm   <<<B_, 256>>>(c, out, Wa, ba);                   // launch 1 (fused alpha)
    k_kt     <<<QT_, 64>>>(Wk, bk);                           // launch 2
    k_dA     <<<dim3(N_ / 256, R_), 256>>>(wrp);              // launch 3 <- profiled
    k_argmin <<<B_, 256>>>(wu);                               // launch 4
    k_As     <<<N_ / 8, 256>>>(A);                            // launch 5 (+emask init)
    k_eset   <<<1, 256>>>();                                  // launch 6
    k_scatter<<<dim3(B_, R_), 256>>>();                       // launch 7
    k_chain  <<<N_ / 64, 256>>>(A);                           // launch 8
    k_read   <<<dim3(NSPL, 8), 256>>>();                      // launch 9
    k_combine<<<QT_, 64>>>(out);                              // launch 10
}

// round 5
// speedup vs baseline: 3.3943x; 1.0861x over previous
#include <cuda_runtime.h>
#include <cuda_fp16.h>
#include <math.h>
#include <stdint.h>

// Problem constants
#define B_   256
#define N_   32768
#define M_   64
#define R_   4
#define U_   256
#define DIN_ 512
#define G4_  1024
#define QT_  1024      // total queries = R*B
#define NSPL 32        // flash reads: split of N (1024 keys per chunk)

// ---------------- static scratch ----------------
__device__ float  g_gates[B_ * G4_];
__device__ float  g_hnew [B_ * U_];
__device__ float  g_kt   [QT_ * M_];          // raw tanh keys fp32 (scatter)
__device__ __half g_ktsh [QT_ * M_];          // normalized keys fp16 [q][m]
__device__ __half g_ktTh [R_ * M_ * B_];      // alpha-scaled keys fp16 [r][m][b]
__device__ float  g_alpha[B_ * R_];
__device__ int    g_least[B_];
__device__ __half g_Ash  [N_ * M_];           // A rows / ||A[n]|| fp16 [n][m]
__device__ __half g_dA   [R_ * M_ * N_];      // write deltas fp16 [r][m][n]
__device__ float  g_emask[N_];
__device__ __half g_AnT  [M_ * N_];           // new memory fp16 [m][n]
__device__ float  g_pden [QT_ * NSPL];
__device__ float  g_pacc [QT_ * NSPL * M_];

__device__ __forceinline__ float sigmoidf(float v) { return 1.0f / (1.0f + expf(-v)); }

__device__ __forceinline__ uint32_t smem_u32(const void* p) {
    uint32_t a;
    asm("{ .reg .u64 t; cvta.to.shared.u64 t, %1; cvt.u32.u64 %0, t; }" : "=r"(a) : "l"(p));
    return a;
}
__device__ __forceinline__ void ldsm4(uint32_t* r, uint32_t addr) {
    asm volatile("ldmatrix.sync.aligned.m8n8.x4.shared.b16 {%0,%1,%2,%3}, [%4];"
        : "=r"(r[0]), "=r"(r[1]), "=r"(r[2]), "=r"(r[3]) : "r"(addr));
}
__device__ __forceinline__ void ldsm4t(uint32_t* r, uint32_t addr) {
    asm volatile("ldmatrix.sync.aligned.m8n8.x4.trans.shared.b16 {%0,%1,%2,%3}, [%4];"
        : "=r"(r[0]), "=r"(r[1]), "=r"(r[2]), "=r"(r[3]) : "r"(addr));
}
__device__ __forceinline__ void mma16816(float* c, const uint32_t* a, uint32_t b0, uint32_t b1) {
    asm volatile("mma.sync.aligned.m16n8k16.row.col.f32.f16.f16.f32 "
        "{%0,%1,%2,%3}, {%4,%5,%6,%7}, {%8,%9}, {%0,%1,%2,%3};"
        : "+f"(c[0]), "+f"(c[1]), "+f"(c[2]), "+f"(c[3])
        : "r"(a[0]), "r"(a[1]), "r"(a[2]), "r"(a[3]), "r"(b0), "r"(b1));
}
__device__ __forceinline__ uint32_t packh2(float a, float b) {
    __half2 h = __floats2half2_rn(a, b);
    return *(uint32_t*)&h;
}
__device__ __forceinline__ void cpa16(uint32_t dst, const void* src) {
    asm volatile("cp.async.ca.shared.global [%0], [%1], 16;" :: "r"(dst), "l"(src));
}
#define CP_COMMIT() asm volatile("cp.async.commit_group;" ::: "memory")
#define CP_WAIT(n)  asm volatile("cp.async.wait_group %0;" :: "n"(n) : "memory")

// ---------------- K1: gates = [x|read_prev|h] @ [W;Uw] + b ----------------
__global__ void k_gates(const float* __restrict__ x, const float* __restrict__ rp,
                        const float* __restrict__ h, const float* __restrict__ W,
                        const float* __restrict__ Uw, const float* __restrict__ bias) {
    const int BM = 64, BN = 64, BK = 16;
    __shared__ float sA[BM][BK + 1];
    __shared__ float sB[BK][BN];
    int t  = threadIdx.x;
    int b0 = blockIdx.y * BM;
    int j0 = blockIdx.x * BN;
    int tr = t >> 4, tc = t & 15;
    float acc[4][4] = {};
    for (int k0 = 0; k0 < 1024; k0 += BK) {
        for (int l = t; l < BM * BK; l += 256) {
            int i = l >> 4, k = l & 15;
            int kk = k0 + k, b = b0 + i;
            float v;
            if (kk < DIN_)          v = x[b * DIN_ + kk];
            else if (kk < 768) { int idx = kk - DIN_; v = rp[((idx >> 6) * B_ + b) * M_ + (idx & 63)]; }
            else                    v = h[b * U_ + (kk - 768)];
            sA[i][k] = v;
        }
        for (int l = t; l < BK * BN; l += 256) {
            int k = l >> 6, j = l & 63;
            int kk = k0 + k;
            sB[k][j] = (kk < 768) ? W[kk * G4_ + j0 + j] : Uw[(kk - 768) * G4_ + j0 + j];
        }
        __syncthreads();
        #pragma unroll
        for (int k = 0; k < BK; k++) {
            float a[4], bb[4];
            #pragma unroll
            for (int i = 0; i < 4; i++) a[i] = sA[tr * 4 + i][k];
            float4 b4 = *(const float4*)&sB[k][tc * 4];
            bb[0] = b4.x; bb[1] = b4.y; bb[2] = b4.z; bb[3] = b4.w;
            #pragma unroll
            for (int i = 0; i < 4; i++)
                #pragma unroll
                for (int j = 0; j < 4; j++) acc[i][j] += a[i] * bb[j];
        }
        __syncthreads();
    }
    #pragma unroll
    for (int i = 0; i < 4; i++)
        #pragma unroll
        for (int j = 0; j < 4; j++)
            g_gates[(b0 + tr * 4 + i) * G4_ + j0 + tc * 4 + j] = acc[i][j] + bias[j0 + tc * 4 + j];
}

// ---------------- K2: LSTM pointwise -> h_new, fused alpha ----------------
__global__ void k_lstm(const float* __restrict__ c, float* __restrict__ out,
                       const float* __restrict__ Wa, const float* __restrict__ ba) {
    int b = blockIdx.x, u = threadIdx.x;
    int idx = b * 256 + u;
    const float* g = g_gates + b * G4_;
    float gi = g[u], gf = g[256 + u], gg = g[512 + u], go = g[768 + u];
    float cn = sigmoidf(gf) * c[idx] + sigmoidf(gi) * tanhf(gg);
    float hn = sigmoidf(go) * tanhf(cn);
    g_hnew[idx] = hn;
    out[b * 512 + u] = hn;
    __shared__ float red[8][4];
    float4 w4 = *(const float4*)(Wa + u * 4);
    float p0 = hn * w4.x, p1 = hn * w4.y, p2 = hn * w4.z, p3 = hn * w4.w;
    #pragma unroll
    for (int o = 16; o > 0; o >>= 1) {
        p0 += __shfl_xor_sync(0xffffffffu, p0, o);
        p1 += __shfl_xor_sync(0xffffffffu, p1, o);
        p2 += __shfl_xor_sync(0xffffffffu, p2, o);
        p3 += __shfl_xor_sync(0xffffffffu, p3, o);
    }
    if ((u & 31) == 0) {
        red[u >> 5][0] = p0; red[u >> 5][1] = p1;
        red[u >> 5][2] = p2; red[u >> 5][3] = p3;
    }
    __syncthreads();
    if (u < 4) {
        float a = ba[u];
        #pragma unroll
        for (int i = 0; i < 8; i++) a += red[i][u];
        g_alpha[b * 4 + u] = sigmoidf(tanhf(a));
    }
}

// ---------------- K3: keys (raw fp32, alpha-scaled fp16 T, normalized fp16) ----------
__global__ void k_kt(const float* __restrict__ Wk, const float* __restrict__ bk) {
    int q = blockIdx.x;            // r*B + b
    int r = q >> 8, b = q & 255;
    int m = threadIdx.x;           // 64 threads
    __shared__ float hs[U_];
    __shared__ float red[2];
    ((float4*)hs)[m] = ((const float4*)(g_hnew + b * U_))[m];
    __syncthreads();
    float acc = bk[r * M_ + m];
    const float* wk = Wk + r * U_ * M_ + m;
    #pragma unroll 8
    for (int u = 0; u < U_; u++) acc += hs[u] * wk[u * M_];
    float kt = tanhf(acc);
    g_kt[q * M_ + m] = kt;
    g_ktTh[(r * M_ + m) * B_ + b] = __float2half(kt * g_alpha[b * 4 + r]);
    float s = kt * kt;
    #pragma unroll
    for (int o = 16; o > 0; o >>= 1) s += __shfl_xor_sync(0xffffffffu, s, o);
    if ((m & 31) == 0) red[m >> 5] = s;
    __syncthreads();
    float inv = 1.0f / sqrtf(red[0] + red[1]);
    g_ktsh[q * M_ + m] = __float2half(kt * inv);
}

// ---------------- K4: write deltas (tensor). dA[r][m][n] = (alpha.*kt[r])^T @ wr_prev[r]
// grid (N_/128, R_), 256 threads. CTA: 64 m x 128 n, K = 256 batch.
__global__ void __launch_bounds__(256) k_dA(const float* __restrict__ wrp) {
    __shared__ __align__(16) __half sP[64 * 136];   // [b-chunk 64][n 128 +8]
    __shared__ __align__(16) __half sA[64 * 72];    // [m 64][b-chunk 64 +8]
    const int t = threadIdx.x, w = t >> 5, l = t & 31;
    const int n0 = blockIdx.x * 128, r = blockIdx.y;
    const int mrow = (w & 3) * 16, nhalf = (w >> 2) * 64;
    const float* wr_base = wrp + (size_t)r * B_ * N_;
    float acc[8][4] = {};
    uint32_t pb = smem_u32(sP), ab = smem_u32(sA);
    for (int kt = 0; kt < 4; kt++) {
        __syncthreads();
        for (int idx = t; idx < 512; idx += 256) {
            int row = idx >> 3, c4 = idx & 7;
            *(uint4*)(sA + row * 72 + c4 * 8) =
                *(const uint4*)(g_ktTh + (size_t)(r * M_ + row) * B_ + kt * 64 + c4 * 8);
        }
        for (int idx = t; idx < 2048; idx += 256) {
            int row = idx >> 5, c = idx & 31;    // 64 rows x 32 float4
            float4 v = *(const float4*)(wr_base + (size_t)(kt * 64 + row) * N_ + n0 + c * 4);
            *(__half2*)(sP + row * 136 + c * 4)     = __floats2half2_rn(v.x, v.y);
            *(__half2*)(sP + row * 136 + c * 4 + 2) = __floats2half2_rn(v.z, v.w);
        }
        __syncthreads();
        #pragma unroll
        for (int k16 = 0; k16 < 4; k16++) {
            uint32_t a[4];
            ldsm4(a, ab + ((mrow + (l & 15)) * 72 + (l >> 4) * 8 + k16 * 16) * 2);
            #pragma unroll
            for (int j = 0; j < 4; j++) {
                uint32_t bb[4];
                int rowb = k16 * 16 + (l & 7) + ((l >> 3) & 1) * 8;
                int colb = nhalf + j * 16 + ((l >> 4) & 1) * 8;
                ldsm4t(bb, pb + (rowb * 136 + colb) * 2);
                mma16816(acc[2 * j],     a, bb[0], bb[1]);
                mma16816(acc[2 * j + 1], a, bb[2], bb[3]);
            }
        }
    }
    int m0 = mrow + (l >> 2), cb = n0 + nhalf + (l & 3) * 2;
    #pragma unroll
    for (int jj = 0; jj < 8; jj++) {
        *(__half2*)(g_dA + (size_t)(r * M_ + m0) * N_ + cb + jj * 8) =
            __floats2half2_rn(acc[jj][0], acc[jj][1]);
        *(__half2*)(g_dA + (size_t)(r * M_ + m0 + 8) * N_ + cb + jj * 8) =
            __floats2half2_rn(acc[jj][2], acc[jj][3]);
    }
}

// ---------------- K5: Ash[n,:] = fp16( A[n,:] / ||A[n,:]|| ); emask = 1 ----------------
__global__ void k_As(const float* __restrict__ A) {
    int n = blockIdx.x * 8 + (threadIdx.x >> 5);
    int lane = threadIdx.x & 31;
    float a0 = A[n * M_ + lane], a1 = A[n * M_ + 32 + lane];
    float s = a0 * a0 + a1 * a1;
    #pragma unroll
    for (int o = 16; o > 0; o >>= 1) s += __shfl_xor_sync(0xffffffffu, s, o);
    float inv = 1.0f / sqrtf(s);
    g_Ash[n * M_ + lane]      = __float2half(a0 * inv);
    g_Ash[n * M_ + 32 + lane] = __float2half(a1 * inv);
    if (lane == 0) g_emask[n] = 1.0f;
}

// ---------------- K6: argmin + erase-mask set (emask must be pre-initialized) ---------
__global__ void k_argmin(const float* __restrict__ wu) {
    int b = blockIdx.x, t = threadIdx.x;
    const float4* row = (const float4*)(wu + (size_t)b * N_);
    float mv = 3.4e38f; int mi = 0;
    for (int i = t; i < N_ / 4; i += 256) {
        float4 v = row[i];
        int base = i * 4;
        if (v.x < mv) { mv = v.x; mi = base; }
        if (v.y < mv) { mv = v.y; mi = base + 1; }
        if (v.z < mv) { mv = v.z; mi = base + 2; }
        if (v.w < mv) { mv = v.w; mi = base + 3; }
    }
    __shared__ float sv[256];
    __shared__ int   si[256];
    sv[t] = mv; si[t] = mi;
    __syncthreads();
    for (int s = 128; s > 0; s >>= 1) {
        if (t < s) {
            if (sv[t + s] < sv[t] || (sv[t + s] == sv[t] && si[t + s] < si[t])) {
                sv[t] = sv[t + s]; si[t] = si[t + s];
            }
        }
        __syncthreads();
    }
    if (t == 0) {
        g_least[b] = si[0];
        g_emask[si[0]] = 0.0f;     // all writers store the same value: deterministic
    }
}

// ---------------- K7: deterministic least-used scatter into g_dA ----------------
__global__ void k_scatter() {
    const int r = blockIdx.y;
    __shared__ int sL[B_];
    int t = threadIdx.x, b = blockIdx.x;
    sL[t] = g_least[t];
    __syncthreads();
    int my = sL[b];
    bool owner = true;
    for (int bb = 0; bb < b; bb++) if (sL[bb] == my) { owner = false; break; }
    if (!owner) return;
    if (t < M_) {
        float acc = 0.0f;
        for (int bb = b; bb < B_; bb++)
            if (sL[bb] == my)
                acc += (1.0f - g_alpha[bb * R_ + r]) * g_kt[((r << 8) + bb) * M_ + t];
        size_t o = (size_t)(r * M_ + t) * N_ + my;
        g_dA[o] = __float2half(__half2float(g_dA[o]) + acc);
    }
}

// ---------------- K8: chain: AnT = fp16(tanh^4 chain of A*e + deltas) ----------------
__global__ void k_chain(const float* __restrict__ A) {
    __shared__ float sT[64][65];
    __shared__ float se[64];
    int t = threadIdx.x, n0 = blockIdx.x * 64;
    for (int idx = t; idx < 4096; idx += 256) {
        int row = idx >> 6, c = idx & 63;
        sT[row][c] = A[(size_t)(n0 + row) * M_ + c];
    }
    if (t < 64) se[t] = g_emask[n0 + t];
    __syncthreads();
    for (int idx = t; idx < 4096; idx += 256) {
        int m = idx >> 6, n = idx & 63;
        float a = sT[n][m] * se[n];
        #pragma unroll
        for (int r = 0; r < 4; r++)
            a = tanhf(a + __half2float(g_dA[(size_t)(r * M_ + m) * N_ + n0 + n]));
        g_AnT[(size_t)m * N_ + n0 + n] = __float2half(a);
    }
}

// ---------------- K9: flash fused reads with cp.async double buffering ----------------
// grid (NSPL, 8), 256 threads. CTA: 128 queries x 1024-key chunk (8 subtiles of 128).
__global__ void __launch_bounds__(256) k_read() {
    __shared__ __align__(16) __half sQ[128 * 72];
    __shared__ __align__(16) __half sK[2][128 * 72];
    __shared__ __align__(16) __half sV[2][64 * 136];
    const int t = threadIdx.x, w = t >> 5, l = t & 31;
    const int q0 = blockIdx.y * 128, n0 = blockIdx.x * 1024;
    uint32_t qb = smem_u32(sQ);

    // stage 0: Q + K0 + V0 (group 0)
    for (int idx = t; idx < 1024; idx += 256) {
        int row = idx >> 3, c4 = idx & 7;
        cpa16(qb + (row * 72 + c4 * 8) * 2, g_ktsh + (size_t)(q0 + row) * M_ + c4 * 8);
    }
    {
        uint32_t kb = smem_u32(sK[0]), vb = smem_u32(sV[0]);
        for (int idx = t; idx < 1024; idx += 256) {
            int row = idx >> 3, c4 = idx & 7;
            cpa16(kb + (row * 72 + c4 * 8) * 2, g_Ash + (size_t)(n0 + row) * M_ + c4 * 8);
        }
        for (int idx = t; idx < 1024; idx += 256) {
            int row = idx >> 4, c4 = idx & 15;
            cpa16(vb + (row * 136 + c4 * 8) * 2, g_AnT + (size_t)row * N_ + n0 + c4 * 8);
        }
    }
    CP_COMMIT();

    uint32_t qa[4][4];
    float acc_o[8][4] = {};
    float den0 = 0.0f, den1 = 0.0f;
    for (int sub = 0; sub < 8; sub++) {
        if (sub + 1 < 8) {       // prefetch next subtile into the other buffer
            int kg = n0 + (sub + 1) * 128;
            uint32_t kb = smem_u32(sK[(sub + 1) & 1]), vb = smem_u32(sV[(sub + 1) & 1]);
            for (int idx = t; idx < 1024; idx += 256) {
                int row = idx >> 3, c4 = idx & 7;
                cpa16(kb + (row * 72 + c4 * 8) * 2, g_Ash + (size_t)(kg + row) * M_ + c4 * 8);
            }
            for (int idx = t; idx < 1024; idx += 256) {
                int row = idx >> 4, c4 = idx & 15;
                cpa16(vb + (row * 136 + c4 * 8) * 2, g_AnT + (size_t)row * N_ + kg + c4 * 8);
            }
        }
        CP_COMMIT();
        CP_WAIT(1);
        __syncthreads();
        if (sub == 0) {          // hoist Q fragments (constant across subtiles)
            #pragma unroll
            for (int k16 = 0; k16 < 4; k16++)
                ldsm4(qa[k16], qb + ((w * 16 + (l & 15)) * 72 + (l >> 4) * 8 + k16 * 16) * 2);
        }
        uint32_t kb = smem_u32(sK[sub & 1]), vb = smem_u32(sV[sub & 1]);
        // S = Q · K^T
        float s[16][4] = {};
        #pragma unroll
        for (int k16 = 0; k16 < 4; k16++) {
            #pragma unroll
            for (int j = 0; j < 8; j++) {
                uint32_t bbf[4];
                ldsm4(bbf, kb + ((j * 16 + (l & 15)) * 72 + (l >> 4) * 8 + k16 * 16) * 2);
                mma16816(s[2 * j],     qa[k16], bbf[0], bbf[2]);
                mma16816(s[2 * j + 1], qa[k16], bbf[1], bbf[3]);
            }
        }
        // P = exp(S) in registers -> A-fragments; O += P · V
        #pragma unroll
        for (int kk = 0; kk < 8; kk++) {
            float e00 = __expf(s[2 * kk][0]),     e01 = __expf(s[2 * kk][1]);
            float e02 = __expf(s[2 * kk][2]),     e03 = __expf(s[2 * kk][3]);
            float e10 = __expf(s[2 * kk + 1][0]), e11 = __expf(s[2 * kk + 1][1]);
            float e12 = __expf(s[2 * kk + 1][2]), e13 = __expf(s[2 * kk + 1][3]);
            den0 += e00 + e01 + e10 + e11;
            den1 += e02 + e03 + e12 + e13;
            uint32_t pa[4];
            pa[0] = packh2(e00, e01);
            pa[1] = packh2(e02, e03);
            pa[2] = packh2(e10, e11);
            pa[3] = packh2(e12, e13);
            #pragma unroll
            for (int j = 0; j < 4; j++) {
                uint32_t bbf[4];
                ldsm4(bbf, vb + ((j * 16 + (l & 15)) * 136 + (l >> 4) * 8 + kk * 16) * 2);
                mma16816(acc_o[2 * j],     pa, bbf[0], bbf[2]);
                mma16816(acc_o[2 * j + 1], pa, bbf[1], bbf[3]);
            }
        }
        __syncthreads();
    }
    den0 += __shfl_xor_sync(0xffffffffu, den0, 1);
    den0 += __shfl_xor_sync(0xffffffffu, den0, 2);
    den1 += __shfl_xor_sync(0xffffffffu, den1, 1);
    den1 += __shfl_xor_sync(0xffffffffu, den1, 2);
    int r0 = q0 + w * 16 + (l >> 2);
    if ((l & 3) == 0) {
        g_pden[r0 * NSPL + blockIdx.x]       = den0;
        g_pden[(r0 + 8) * NSPL + blockIdx.x] = den1;
    }
    float* p0 = g_pacc + ((size_t)r0 * NSPL + blockIdx.x) * M_;
    float* p1 = g_pacc + ((size_t)(r0 + 8) * NSPL + blockIdx.x) * M_;
    int cb = (l & 3) * 2;
    #pragma unroll
    for (int jj = 0; jj < 8; jj++) {
        *(float2*)(p0 + jj * 8 + cb) = make_float2(acc_o[jj][0], acc_o[jj][1]);
        *(float2*)(p1 + jj * 8 + cb) = make_float2(acc_o[jj][2], acc_o[jj][3]);
    }
}

// ---------------- K10: combine partials -> out[:, 256:512] ----------------
__global__ void k_combine(float* __restrict__ out) {
    int q = blockIdx.x;          // r*B + b
    int m = threadIdx.x;         // 64
    float acc = 0.0f, den = 0.0f;
    #pragma unroll
    for (int s = 0; s < NSPL; s++) {
        acc += g_pacc[((size_t)q * NSPL + s) * M_ + m];
        den += g_pden[q * NSPL + s];
    }
    int r = q >> 8, b = q & 255;
    out[b * 512 + 256 + r * M_ + m] = acc / den;
}

// ---------------- launch ----------------
extern "C" void kernel_launch(void* const* d_in, const int* in_sizes, int n_in,
                              void* d_out, int out_size) {
    const float* x    = (const float*)d_in[0];
    const float* A    = (const float*)d_in[1];
    const float* wrp  = (const float*)d_in[2];
    const float* wu   = (const float*)d_in[3];
    const float* rp   = (const float*)d_in[4];
    const float* h    = (const float*)d_in[5];
    const float* c    = (const float*)d_in[6];
    const float* W    = (const float*)d_in[7];
    const float* Uw   = (const float*)d_in[8];
    const float* bias = (const float*)d_in[9];
    const float* Wk   = (const float*)d_in[10];
    const float* bk   = (const float*)d_in[11];
    const float* Wa   = (const float*)d_in[12];
    const float* ba   = (const float*)d_in[13];
    float* out = (float*)d_out;

    k_gates  <<<dim3(16, 4), 256>>>(x, rp, h, W, Uw, bias);   // 0
    k_lstm   <<<B_, 256>>>(c, out, Wa, ba);                   // 1 (fused alpha)
    k_kt     <<<QT_, 64>>>(Wk, bk);                           // 2 (alpha-scaled ktTh)
    k_dA     <<<dim3(N_ / 128, R_), 256>>>(wrp);              // 3 <- profiled slot
    k_As     <<<N_ / 8, 256>>>(A);                            // 4 (+emask=1)
    k_argmin <<<B_, 256>>>(wu);                               // 5 (+emask set)
    k_scatter<<<dim3(B_, R_), 256>>>();                       // 6
    k_chain  <<<N_ / 64, 256>>>(A);                           // 7
    k_read   <<<dim3(NSPL, 8), 256>>>();                      // 8
    k_combine<<<QT_, 64>>>(out);                              // 9
}

// round 6
// speedup vs baseline: 3.5652x; 1.0504x over previous
#include <cuda_runtime.h>
#include <cuda_fp16.h>
#include <math.h>
#include <stdint.h>

// Problem constants
#define B_   256
#define N_   32768
#define M_   64
#define R_   4
#define U_   256
#define DIN_ 512
#define G4_  1024
#define QT_  1024      // total queries = R*B
#define NSPL 32        // flash reads: split of N (1024 keys per chunk)

// ---------------- static scratch ----------------
__device__ float  g_gates[B_ * G4_];
__device__ float  g_hnew [B_ * U_];
__device__ float  g_kt   [QT_ * M_];          // raw tanh keys fp32 (scatter)
__device__ __half g_ktsh [QT_ * M_];          // normalized keys fp16 [q][m]
__device__ __half g_ktTh [R_ * M_ * B_];      // alpha-scaled keys fp16 [r][m][b]
__device__ float  g_alpha[B_ * R_];
__device__ int    g_least[B_];
__device__ __half g_Ash  [N_ * M_];           // A rows / ||A[n]|| fp16 [n][m]
__device__ __half g_dA   [R_ * M_ * N_];      // write deltas fp16 [r][m][n]
__device__ float  g_emask[N_];
__device__ __half g_AnT  [M_ * N_];           // new memory fp16 [m][n]
__device__ float  g_pden [QT_ * NSPL];
__device__ float  g_pacc [QT_ * NSPL * M_];

// fast transcendentals (bounded args on this workload; err ~1e-6 << fp16 noise)
__device__ __forceinline__ float fsigmoid(float x) {
    return __fdividef(1.0f, 1.0f + __expf(-x));
}
__device__ __forceinline__ float ftanh(float x) {
    float e = __expf(2.0f * x);
    return __fdividef(e - 1.0f, e + 1.0f);
}

__device__ __forceinline__ uint32_t smem_u32(const void* p) {
    uint32_t a;
    asm("{ .reg .u64 t; cvta.to.shared.u64 t, %1; cvt.u32.u64 %0, t; }" : "=r"(a) : "l"(p));
    return a;
}
__device__ __forceinline__ void ldsm4(uint32_t* r, uint32_t addr) {
    asm volatile("ldmatrix.sync.aligned.m8n8.x4.shared.b16 {%0,%1,%2,%3}, [%4];"
        : "=r"(r[0]), "=r"(r[1]), "=r"(r[2]), "=r"(r[3]) : "r"(addr));
}
__device__ __forceinline__ void ldsm4t(uint32_t* r, uint32_t addr) {
    asm volatile("ldmatrix.sync.aligned.m8n8.x4.trans.shared.b16 {%0,%1,%2,%3}, [%4];"
        : "=r"(r[0]), "=r"(r[1]), "=r"(r[2]), "=r"(r[3]) : "r"(addr));
}
__device__ __forceinline__ void mma16816(float* c, const uint32_t* a, uint32_t b0, uint32_t b1) {
    asm volatile("mma.sync.aligned.m16n8k16.row.col.f32.f16.f16.f32 "
        "{%0,%1,%2,%3}, {%4,%5,%6,%7}, {%8,%9}, {%0,%1,%2,%3};"
        : "+f"(c[0]), "+f"(c[1]), "+f"(c[2]), "+f"(c[3])
        : "r"(a[0]), "r"(a[1]), "r"(a[2]), "r"(a[3]), "r"(b0), "r"(b1));
}
__device__ __forceinline__ uint32_t packh2(float a, float b) {
    __half2 h = __floats2half2_rn(a, b);
    return *(uint32_t*)&h;
}
__device__ __forceinline__ void cpa16(uint32_t dst, const void* src) {
    asm volatile("cp.async.ca.shared.global [%0], [%1], 16;" :: "r"(dst), "l"(src));
}
#define CP_COMMIT() asm volatile("cp.async.commit_group;" ::: "memory")
#define CP_WAIT(n)  asm volatile("cp.async.wait_group %0;" :: "n"(n) : "memory")

// ---------------- K1: gates = [x|read_prev|h] @ [W;Uw] + b ----------------
__global__ void k_gates(const float* __restrict__ x, const float* __restrict__ rp,
                        const float* __restrict__ h, const float* __restrict__ W,
                        const float* __restrict__ Uw, const float* __restrict__ bias) {
    const int BM = 64, BN = 64, BK = 16;
    __shared__ float sA[BM][BK + 1];
    __shared__ float sB[BK][BN];
    int t  = threadIdx.x;
    int b0 = blockIdx.y * BM;
    int j0 = blockIdx.x * BN;
    int tr = t >> 4, tc = t & 15;
    float acc[4][4] = {};
    for (int k0 = 0; k0 < 1024; k0 += BK) {
        for (int l = t; l < BM * BK; l += 256) {
            int i = l >> 4, k = l & 15;
            int kk = k0 + k, b = b0 + i;
            float v;
            if (kk < DIN_)          v = x[b * DIN_ + kk];
            else if (kk < 768) { int idx = kk - DIN_; v = rp[((idx >> 6) * B_ + b) * M_ + (idx & 63)]; }
            else                    v = h[b * U_ + (kk - 768)];
            sA[i][k] = v;
        }
        for (int l = t; l < BK * BN; l += 256) {
            int k = l >> 6, j = l & 63;
            int kk = k0 + k;
            sB[k][j] = (kk < 768) ? W[kk * G4_ + j0 + j] : Uw[(kk - 768) * G4_ + j0 + j];
        }
        __syncthreads();
        #pragma unroll
        for (int k = 0; k < BK; k++) {
            float a[4], bb[4];
            #pragma unroll
            for (int i = 0; i < 4; i++) a[i] = sA[tr * 4 + i][k];
            float4 b4 = *(const float4*)&sB[k][tc * 4];
            bb[0] = b4.x; bb[1] = b4.y; bb[2] = b4.z; bb[3] = b4.w;
            #pragma unroll
            for (int i = 0; i < 4; i++)
                #pragma unroll
                for (int j = 0; j < 4; j++) acc[i][j] += a[i] * bb[j];
        }
        __syncthreads();
    }
    #pragma unroll
    for (int i = 0; i < 4; i++)
        #pragma unroll
        for (int j = 0; j < 4; j++)
            g_gates[(b0 + tr * 4 + i) * G4_ + j0 + tc * 4 + j] = acc[i][j] + bias[j0 + tc * 4 + j];
}

// ---------------- K2: LSTM pointwise -> h_new, fused alpha ----------------
__global__ void k_lstm(const float* __restrict__ c, float* __restrict__ out,
                       const float* __restrict__ Wa, const float* __restrict__ ba) {
    int b = blockIdx.x, u = threadIdx.x;
    int idx = b * 256 + u;
    const float* g = g_gates + b * G4_;
    float gi = g[u], gf = g[256 + u], gg = g[512 + u], go = g[768 + u];
    float cn = fsigmoid(gf) * c[idx] + fsigmoid(gi) * ftanh(gg);
    float hn = fsigmoid(go) * ftanh(cn);
    g_hnew[idx] = hn;
    out[b * 512 + u] = hn;
    __shared__ float red[8][4];
    float4 w4 = *(const float4*)(Wa + u * 4);
    float p0 = hn * w4.x, p1 = hn * w4.y, p2 = hn * w4.z, p3 = hn * w4.w;
    #pragma unroll
    for (int o = 16; o > 0; o >>= 1) {
        p0 += __shfl_xor_sync(0xffffffffu, p0, o);
        p1 += __shfl_xor_sync(0xffffffffu, p1, o);
        p2 += __shfl_xor_sync(0xffffffffu, p2, o);
        p3 += __shfl_xor_sync(0xffffffffu, p3, o);
    }
    if ((u & 31) == 0) {
        red[u >> 5][0] = p0; red[u >> 5][1] = p1;
        red[u >> 5][2] = p2; red[u >> 5][3] = p3;
    }
    __syncthreads();
    if (u < 4) {
        float a = ba[u];
        #pragma unroll
        for (int i = 0; i < 8; i++) a += red[i][u];
        g_alpha[b * 4 + u] = fsigmoid(ftanh(a));
    }
}

// ---------------- K3: keys (raw fp32, alpha-scaled fp16 T, normalized fp16) ----------
__global__ void k_kt(const float* __restrict__ Wk, const float* __restrict__ bk) {
    int q = blockIdx.x;            // r*B + b
    int r = q >> 8, b = q & 255;
    int m = threadIdx.x;           // 64 threads
    __shared__ float hs[U_];
    __shared__ float red[2];
    ((float4*)hs)[m] = ((const float4*)(g_hnew + b * U_))[m];
    __syncthreads();
    float acc = bk[r * M_ + m];
    const float* wk = Wk + r * U_ * M_ + m;
    #pragma unroll 8
    for (int u = 0; u < U_; u++) acc += hs[u] * wk[u * M_];
    float kt = ftanh(acc);
    g_kt[q * M_ + m] = kt;
    g_ktTh[(r * M_ + m) * B_ + b] = __float2half(kt * g_alpha[b * 4 + r]);
    float s = kt * kt;
    #pragma unroll
    for (int o = 16; o > 0; o >>= 1) s += __shfl_xor_sync(0xffffffffu, s, o);
    if ((m & 31) == 0) red[m >> 5] = s;
    __syncthreads();
    float inv = 1.0f / sqrtf(red[0] + red[1]);
    g_ktsh[q * M_ + m] = __float2half(kt * inv);
}

// ---------------- K4: write deltas (tensor), software-pipelined loads ----------------
// dA[r][m][n] = (alpha.*kt[r])^T @ wr_prev[r].  grid (N_/128, R_), 256 threads.
__global__ void __launch_bounds__(256) k_dA(const float* __restrict__ wrp) {
    __shared__ __align__(16) __half sP[64 * 136];   // [b-chunk 64][n 128 +8]
    __shared__ __align__(16) __half sA[64 * 72];    // [m 64][b-chunk 64 +8]
    const int t = threadIdx.x, w = t >> 5, l = t & 31;
    const int n0 = blockIdx.x * 128, r = blockIdx.y;
    const int mrow = (w & 3) * 16, nhalf = (w >> 2) * 64;
    const float* wr_base = wrp + (size_t)r * B_ * N_;
    float acc[8][4] = {};
    uint32_t pb = smem_u32(sP), ab = smem_u32(sA);

    // per-thread prefetch registers: 8 float4 of wr_prev, 2 uint4 of ktTh
    const int prow = t >> 5, pc = t & 31;           // wr: rows t>>5 + i*8, col pc
    const int arow = t >> 3, ac4 = t & 7;           // kt: rows t>>3 + i*32, col ac4
    float4 pv[8]; uint4 av[2];
    #pragma unroll
    for (int i = 0; i < 8; i++)
        pv[i] = *(const float4*)(wr_base + (size_t)(prow + i * 8) * N_ + n0 + pc * 4);
    #pragma unroll
    for (int i = 0; i < 2; i++)
        av[i] = *(const uint4*)(g_ktTh + (size_t)(r * M_ + arow + i * 32) * B_ + ac4 * 8);

    for (int kt = 0; kt < 4; kt++) {
        __syncthreads();
        #pragma unroll
        for (int i = 0; i < 8; i++) {
            int row = prow + i * 8;
            *(__half2*)(sP + row * 136 + pc * 4)     = __floats2half2_rn(pv[i].x, pv[i].y);
            *(__half2*)(sP + row * 136 + pc * 4 + 2) = __floats2half2_rn(pv[i].z, pv[i].w);
        }
        #pragma unroll
        for (int i = 0; i < 2; i++)
            *(uint4*)(sA + (arow + i * 32) * 72 + ac4 * 8) = av[i];
        __syncthreads();
        if (kt < 3) {          // prefetch next k-tile while MMAs run
            int kb = (kt + 1) * 64;
            #pragma unroll
            for (int i = 0; i < 8; i++)
                pv[i] = *(const float4*)(wr_base + (size_t)(kb + prow + i * 8) * N_ + n0 + pc * 4);
            #pragma unroll
            for (int i = 0; i < 2; i++)
                av[i] = *(const uint4*)(g_ktTh + (size_t)(r * M_ + arow + i * 32) * B_ + kb + ac4 * 8);
        }
        #pragma unroll
        for (int k16 = 0; k16 < 4; k16++) {
            uint32_t a[4];
            ldsm4(a, ab + ((mrow + (l & 15)) * 72 + (l >> 4) * 8 + k16 * 16) * 2);
            #pragma unroll
            for (int j = 0; j < 4; j++) {
                uint32_t bb[4];
                int rowb = k16 * 16 + (l & 7) + ((l >> 3) & 1) * 8;
                int colb = nhalf + j * 16 + ((l >> 4) & 1) * 8;
                ldsm4t(bb, pb + (rowb * 136 + colb) * 2);
                mma16816(acc[2 * j],     a, bb[0], bb[1]);
                mma16816(acc[2 * j + 1], a, bb[2], bb[3]);
            }
        }
    }
    int m0 = mrow + (l >> 2), cb = n0 + nhalf + (l & 3) * 2;
    #pragma unroll
    for (int jj = 0; jj < 8; jj++) {
        *(__half2*)(g_dA + (size_t)(r * M_ + m0) * N_ + cb + jj * 8) =
            __floats2half2_rn(acc[jj][0], acc[jj][1]);
        *(__half2*)(g_dA + (size_t)(r * M_ + m0 + 8) * N_ + cb + jj * 8) =
            __floats2half2_rn(acc[jj][2], acc[jj][3]);
    }
}

// ---------------- K5: Ash[n,:] = fp16( A[n,:] / ||A[n,:]|| ); emask = 1 ----------------
__global__ void k_As(const float* __restrict__ A) {
    int n = blockIdx.x * 8 + (threadIdx.x >> 5);
    int lane = threadIdx.x & 31;
    float a0 = A[n * M_ + lane], a1 = A[n * M_ + 32 + lane];
    float s = a0 * a0 + a1 * a1;
    #pragma unroll
    for (int o = 16; o > 0; o >>= 1) s += __shfl_xor_sync(0xffffffffu, s, o);
    float inv = 1.0f / sqrtf(s);
    g_Ash[n * M_ + lane]      = __float2half(a0 * inv);
    g_Ash[n * M_ + 32 + lane] = __float2half(a1 * inv);
    if (lane == 0) g_emask[n] = 1.0f;
}

// ---------------- K6: argmin + erase-mask set ----------------
__global__ void k_argmin(const float* __restrict__ wu) {
    int b = blockIdx.x, t = threadIdx.x;
    const float4* row = (const float4*)(wu + (size_t)b * N_);
    float mv = 3.4e38f; int mi = 0;
    for (int i = t; i < N_ / 4; i += 256) {
        float4 v = row[i];
        int base = i * 4;
        if (v.x < mv) { mv = v.x; mi = base; }
        if (v.y < mv) { mv = v.y; mi = base + 1; }
        if (v.z < mv) { mv = v.z; mi = base + 2; }
        if (v.w < mv) { mv = v.w; mi = base + 3; }
    }
    __shared__ float sv[256];
    __shared__ int   si[256];
    sv[t] = mv; si[t] = mi;
    __syncthreads();
    for (int s = 128; s > 0; s >>= 1) {
        if (t < s) {
            if (sv[t + s] < sv[t] || (sv[t + s] == sv[t] && si[t + s] < si[t])) {
                sv[t] = sv[t + s]; si[t] = si[t + s];
            }
        }
        __syncthreads();
    }
    if (t == 0) {
        g_least[b] = si[0];
        g_emask[si[0]] = 0.0f;     // all writers store the same value: deterministic
    }
}

// ---------------- K7: deterministic least-used scatter into g_dA ----------------
__global__ void k_scatter() {
    const int r = blockIdx.y;
    __shared__ int sL[B_];
    int t = threadIdx.x, b = blockIdx.x;
    sL[t] = g_least[t];
    __syncthreads();
    int my = sL[b];
    bool owner = true;
    for (int bb = 0; bb < b; bb++) if (sL[bb] == my) { owner = false; break; }
    if (!owner) return;
    if (t < M_) {
        float acc = 0.0f;
        for (int bb = b; bb < B_; bb++)
            if (sL[bb] == my)
                acc += (1.0f - g_alpha[bb * R_ + r]) * g_kt[((r << 8) + bb) * M_ + t];
        size_t o = (size_t)(r * M_ + t) * N_ + my;
        g_dA[o] = __float2half(__half2float(g_dA[o]) + acc);
    }
}

// ---------------- K8: chain: AnT = fp16(tanh^4 chain of A*e + deltas) ----------------
__global__ void k_chain(const float* __restrict__ A) {
    __shared__ float sT[64][65];
    __shared__ float se[64];
    int t = threadIdx.x, n0 = blockIdx.x * 64;
    for (int idx = t; idx < 4096; idx += 256) {
        int row = idx >> 6, c = idx & 63;
        sT[row][c] = A[(size_t)(n0 + row) * M_ + c];
    }
    if (t < 64) se[t] = g_emask[n0 + t];
    __syncthreads();
    for (int idx = t; idx < 4096; idx += 256) {
        int m = idx >> 6, n = idx & 63;
        float a = sT[n][m] * se[n];
        #pragma unroll
        for (int r = 0; r < 4; r++)
            a = ftanh(a + __half2float(g_dA[(size_t)(r * M_ + m) * N_ + n0 + n]));
        g_AnT[(size_t)m * N_ + n0 + n] = __float2half(a);
    }
}

// ---------------- K9: flash fused reads with cp.async double buffering ----------------
// grid (NSPL, 8), 256 threads. CTA: 128 queries x 1024-key chunk (8 subtiles of 128).
__global__ void __launch_bounds__(256, 2) k_read() {
    __shared__ __align__(16) __half sQ[128 * 72];
    __shared__ __align__(16) __half sK[2][128 * 72];
    __shared__ __align__(16) __half sV[2][64 * 136];
    const int t = threadIdx.x, w = t >> 5, l = t & 31;
    const int q0 = blockIdx.y * 128, n0 = blockIdx.x * 1024;
    uint32_t qb = smem_u32(sQ);

    for (int idx = t; idx < 1024; idx += 256) {
        int row = idx >> 3, c4 = idx & 7;
        cpa16(qb + (row * 72 + c4 * 8) * 2, g_ktsh + (size_t)(q0 + row) * M_ + c4 * 8);
    }
    {
        uint32_t kb = smem_u32(sK[0]), vb = smem_u32(sV[0]);
        for (int idx = t; idx < 1024; idx += 256) {
            int row = idx >> 3, c4 = idx & 7;
            cpa16(kb + (row * 72 + c4 * 8) * 2, g_Ash + (size_t)(n0 + row) * M_ + c4 * 8);
        }
        for (int idx = t; idx < 1024; idx += 256) {
            int row = idx >> 4, c4 = idx & 15;
            cpa16(vb + (row * 136 + c4 * 8) * 2, g_AnT + (size_t)row * N_ + n0 + c4 * 8);
        }
    }
    CP_COMMIT();

    uint32_t qa[4][4];
    float acc_o[8][4] = {};
    float den0 = 0.0f, den1 = 0.0f;
    for (int sub = 0; sub < 8; sub++) {
        if (sub + 1 < 8) {
            int kg = n0 + (sub + 1) * 128;
            uint32_t kb = smem_u32(sK[(sub + 1) & 1]), vb = smem_u32(sV[(sub + 1) & 1]);
            for (int idx = t; idx < 1024; idx += 256) {
                int row = idx >> 3, c4 = idx & 7;
                cpa16(kb + (row * 72 + c4 * 8) * 2, g_Ash + (size_t)(kg + row) * M_ + c4 * 8);
            }
            for (int idx = t; idx < 1024; idx += 256) {
                int row = idx >> 4, c4 = idx & 15;
                cpa16(vb + (row * 136 + c4 * 8) * 2, g_AnT + (size_t)row * N_ + kg + c4 * 8);
            }
        }
        CP_COMMIT();
        CP_WAIT(1);
        __syncthreads();
        if (sub == 0) {
            #pragma unroll
            for (int k16 = 0; k16 < 4; k16++)
                ldsm4(qa[k16], qb + ((w * 16 + (l & 15)) * 72 + (l >> 4) * 8 + k16 * 16) * 2);
        }
        uint32_t kb = smem_u32(sK[sub & 1]), vb = smem_u32(sV[sub & 1]);
        float s[16][4] = {};
        #pragma unroll
        for (int k16 = 0; k16 < 4; k16++) {
            #pragma unroll
            for (int j = 0; j < 8; j++) {
                uint32_t bbf[4];
                ldsm4(bbf, kb + ((j * 16 + (l & 15)) * 72 + (l >> 4) * 8 + k16 * 16) * 2);
                mma16816(s[2 * j],     qa[k16], bbf[0], bbf[2]);
                mma16816(s[2 * j + 1], qa[k16], bbf[1], bbf[3]);
            }
        }
        #pragma unroll
        for (int kk = 0; kk < 8; kk++) {
            float e00 = __expf(s[2 * kk][0]),     e01 = __expf(s[2 * kk][1]);
            float e02 = __expf(s[2 * kk][2]),     e03 = __expf(s[2 * kk][3]);
            float e10 = __expf(s[2 * kk + 1][0]), e11 = __expf(s[2 * kk + 1][1]);
            float e12 = __expf(s[2 * kk + 1][2]), e13 = __expf(s[2 * kk + 1][3]);
            den0 += e00 + e01 + e10 + e11;
            den1 += e02 + e03 + e12 + e13;
            uint32_t pa[4];
            pa[0] = packh2(e00, e01);
            pa[1] = packh2(e02, e03);
            pa[2] = packh2(e10, e11);
            pa[3] = packh2(e12, e13);
            #pragma unroll
            for (int j = 0; j < 4; j++) {
                uint32_t bbf[4];
                ldsm4(bbf, vb + ((j * 16 + (l & 15)) * 136 + (l >> 4) * 8 + kk * 16) * 2);
                mma16816(acc_o[2 * j],     pa, bbf[0], bbf[2]);
                mma16816(acc_o[2 * j + 1], pa, bbf[1], bbf[3]);
            }
        }
        __syncthreads();
    }
    den0 += __shfl_xor_sync(0xffffffffu, den0, 1);
    den0 += __shfl_xor_sync(0xffffffffu, den0, 2);
    den1 += __shfl_xor_sync(0xffffffffu, den1, 1);
    den1 += __shfl_xor_sync(0xffffffffu, den1, 2);
    int r0 = q0 + w * 16 + (l >> 2);
    if ((l & 3) == 0) {
        g_pden[r0 * NSPL + blockIdx.x]       = den0;
        g_pden[(r0 + 8) * NSPL + blockIdx.x] = den1;
    }
    float* p0 = g_pacc + ((size_t)r0 * NSPL + blockIdx.x) * M_;
    float* p1 = g_pacc + ((size_t)(r0 + 8) * NSPL + blockIdx.x) * M_;
    int cb = (l & 3) * 2;
    #pragma unroll
    for (int jj = 0; jj < 8; jj++) {
        *(float2*)(p0 + jj * 8 + cb) = make_float2(acc_o[jj][0], acc_o[jj][1]);
        *(float2*)(p1 + jj * 8 + cb) = make_float2(acc_o[jj][2], acc_o[jj][3]);
    }
}

// ---------------- K10: combine partials -> out[:, 256:512] ----------------
__global__ void k_combine(float* __restrict__ out) {
    int q = blockIdx.x;          // r*B + b
    int m = threadIdx.x;         // 64
    float acc = 0.0f, den = 0.0f;
    #pragma unroll
    for (int s = 0; s < NSPL; s++) {
        acc += g_pacc[((size_t)q * NSPL + s) * M_ + m];
        den += g_pden[q * NSPL + s];
    }
    int r = q >> 8, b = q & 255;
    out[b * 512 + 256 + r * M_ + m] = acc / den;
}

// ---------------- launch ----------------
extern "C" void kernel_launch(void* const* d_in, const int* in_sizes, int n_in,
                              void* d_out, int out_size) {
    const float* x    = (const float*)d_in[0];
    const float* A    = (const float*)d_in[1];
    const float* wrp  = (const float*)d_in[2];
    const float* wu   = (const float*)d_in[3];
    const float* rp   = (const float*)d_in[4];
    const float* h    = (const float*)d_in[5];
    const float* c    = (const float*)d_in[6];
    const float* W    = (const float*)d_in[7];
    const float* Uw   = (const float*)d_in[8];
    const float* bias = (const float*)d_in[9];
    const float* Wk   = (const float*)d_in[10];
    const float* bk   = (const float*)d_in[11];
    const float* Wa   = (const float*)d_in[12];
    const float* ba   = (const float*)d_in[13];
    float* out = (float*)d_out;

    k_gates  <<<dim3(16, 4), 256>>>(x, rp, h, W, Uw, bias);   // 0
    k_lstm   <<<B_, 256>>>(c, out, Wa, ba);                   // 1
    k_kt     <<<QT_, 64>>>(Wk, bk);                           // 2
    k_dA     <<<dim3(N_ / 128, R_), 256>>>(wrp);              // 3 <- profiled slot
    k_As     <<<N_ / 8, 256>>>(A);                            // 4
    k_argmin <<<B_, 256>>>(wu);                               // 5
    k_scatter<<<dim3(B_, R_), 256>>>();                       // 6
    k_chain  <<<N_ / 64, 256>>>(A);                           // 7
    k_read   <<<dim3(NSPL, 8), 256>>>();                      // 8
    k_combine<<<QT_, 64>>>(out);                              // 9
}

// round 7
// speedup vs baseline: 6.0577x; 1.6991x over previous
#include <cuda_runtime.h>
#include <cuda_fp16.h>
#include <math.h>
#include <stdint.h>

// Problem constants
#define B_   256
#define N_   32768
#define M_   64
#define R_   4
#define U_   256
#define DIN_ 512
#define G4_  1024
#define QT_  1024      // total queries = R*B
#define NSPL 32        // flash reads: split of N (1024 keys per chunk)

// ---------------- static scratch ----------------
__device__ float  g_gates[B_ * G4_];
__device__ float  g_hnew [B_ * U_];
__device__ float  g_kt   [QT_ * M_];          // raw tanh keys fp32 (scatter)
__device__ __half g_ktsh [QT_ * M_];          // normalized keys fp16 [q][m]
__device__ __half g_ktTh [R_ * M_ * B_];      // alpha-scaled keys fp16 [r][m][b]
__device__ float  g_alpha[B_ * R_];
__device__ int    g_least[B_];
__device__ __half g_Ash  [N_ * M_];           // A rows / ||A[n]|| fp16 [n][m]
__device__ __half g_dA   [R_ * M_ * N_];      // write deltas fp16 [r][m][n]
__device__ float  g_emask[N_];
__device__ __half g_AnT  [M_ * N_];           // new memory fp16 [m][n]
__device__ float  g_pden [QT_ * NSPL];
__device__ float  g_pacc [QT_ * NSPL * M_];

// fast transcendentals (bounded args on this workload; err ~1e-6 << fp16 noise)
__device__ __forceinline__ float fsigmoid(float x) {
    return __fdividef(1.0f, 1.0f + __expf(-x));
}
__device__ __forceinline__ float ftanh(float x) {
    float e = __expf(2.0f * x);
    return __fdividef(e - 1.0f, e + 1.0f);
}

__device__ __forceinline__ uint32_t smem_u32(const void* p) {
    uint32_t a;
    asm("{ .reg .u64 t; cvta.to.shared.u64 t, %1; cvt.u32.u64 %0, t; }" : "=r"(a) : "l"(p));
    return a;
}
__device__ __forceinline__ void ldsm4(uint32_t* r, uint32_t addr) {
    asm volatile("ldmatrix.sync.aligned.m8n8.x4.shared.b16 {%0,%1,%2,%3}, [%4];"
        : "=r"(r[0]), "=r"(r[1]), "=r"(r[2]), "=r"(r[3]) : "r"(addr));
}
__device__ __forceinline__ void ldsm4t(uint32_t* r, uint32_t addr) {
    asm volatile("ldmatrix.sync.aligned.m8n8.x4.trans.shared.b16 {%0,%1,%2,%3}, [%4];"
        : "=r"(r[0]), "=r"(r[1]), "=r"(r[2]), "=r"(r[3]) : "r"(addr));
}
__device__ __forceinline__ void mma16816(float* c, const uint32_t* a, uint32_t b0, uint32_t b1) {
    asm volatile("mma.sync.aligned.m16n8k16.row.col.f32.f16.f16.f32 "
        "{%0,%1,%2,%3}, {%4,%5,%6,%7}, {%8,%9}, {%0,%1,%2,%3};"
        : "+f"(c[0]), "+f"(c[1]), "+f"(c[2]), "+f"(c[3])
        : "r"(a[0]), "r"(a[1]), "r"(a[2]), "r"(a[3]), "r"(b0), "r"(b1));
}
__device__ __forceinline__ uint32_t packh2(float a, float b) {
    __half2 h = __floats2half2_rn(a, b);
    return *(uint32_t*)&h;
}
__device__ __forceinline__ void cpa16(uint32_t dst, const void* src) {
    asm volatile("cp.async.ca.shared.global [%0], [%1], 16;" :: "r"(dst), "l"(src));
}
__device__ __forceinline__ void cpa4(uint32_t dst, const void* src) {
    asm volatile("cp.async.ca.shared.global [%0], [%1], 4;" :: "r"(dst), "l"(src));
}
#define CP_COMMIT() asm volatile("cp.async.commit_group;" ::: "memory")
#define CP_WAIT(n)  asm volatile("cp.async.wait_group %0;" :: "n"(n) : "memory")

// ---------------- K1: gates = [x|read_prev|h] @ [W;Uw] + b (cp.async pipelined) ------
__global__ void __launch_bounds__(256) k_gates(
        const float* __restrict__ x, const float* __restrict__ rp,
        const float* __restrict__ h, const float* __restrict__ W,
        const float* __restrict__ Uw, const float* __restrict__ bias) {
    const int BK = 16;
    __shared__ float sA[2][64][17];
    __shared__ float sB[2][16][64];
    int t  = threadIdx.x;
    int b0 = blockIdx.y * 64;
    int j0 = blockIdx.x * 64;
    int tr = t >> 4, tc = t & 15;

    // prefetch helper (as lambda-free macro style)
    #define GATES_PREFETCH(k0, buf) do {                                                \
        for (int l = t; l < 1024; l += 256) {                                           \
            int i = l >> 4, k = l & 15;                                                 \
            int kk = (k0) + k, b = b0 + i;                                              \
            const float* src;                                                           \
            if (kk < DIN_)       src = x + b * DIN_ + kk;                               \
            else if (kk < 768) { int id = kk - DIN_; src = rp + ((id >> 6) * B_ + b) * M_ + (id & 63); } \
            else                 src = h + b * U_ + (kk - 768);                         \
            cpa4(smem_u32(&sA[buf][i][k]), src);                                        \
        }                                                                               \
        {                                                                               \
            int row = t >> 4, c4 = t & 15;                                              \
            int kk = (k0) + row;                                                        \
            const float* src = (kk < 768) ? W + kk * G4_ + j0 + c4 * 4                  \
                                          : Uw + (kk - 768) * G4_ + j0 + c4 * 4;        \
            cpa16(smem_u32(&sB[buf][row][c4 * 4]), src);                                \
        }                                                                               \
        CP_COMMIT();                                                                    \
    } while (0)

    GATES_PREFETCH(0, 0);
    float acc[4][4] = {};
    for (int kt = 0; kt < 64; kt++) {
        int buf = kt & 1;
        if (kt < 63) GATES_PREFETCH((kt + 1) * BK, buf ^ 1);
        CP_WAIT(1);
        __syncthreads();
        #pragma unroll
        for (int k = 0; k < BK; k++) {
            float a[4], bb[4];
            #pragma unroll
            for (int i = 0; i < 4; i++) a[i] = sA[buf][tr * 4 + i][k];
            float4 b4 = *(const float4*)&sB[buf][k][tc * 4];
            bb[0] = b4.x; bb[1] = b4.y; bb[2] = b4.z; bb[3] = b4.w;
            #pragma unroll
            for (int i = 0; i < 4; i++)
                #pragma unroll
                for (int j = 0; j < 4; j++) acc[i][j] += a[i] * bb[j];
        }
        __syncthreads();
    }
    #pragma unroll
    for (int i = 0; i < 4; i++)
        #pragma unroll
        for (int j = 0; j < 4; j++)
            g_gates[(b0 + tr * 4 + i) * G4_ + j0 + tc * 4 + j] = acc[i][j] + bias[j0 + tc * 4 + j];
    #undef GATES_PREFETCH
}

// ---------------- K2: LSTM pointwise -> h_new, fused alpha ----------------
__global__ void k_lstm(const float* __restrict__ c, float* __restrict__ out,
                       const float* __restrict__ Wa, const float* __restrict__ ba) {
    int b = blockIdx.x, u = threadIdx.x;
    int idx = b * 256 + u;
    const float* g = g_gates + b * G4_;
    float gi = g[u], gf = g[256 + u], gg = g[512 + u], go = g[768 + u];
    float cn = fsigmoid(gf) * c[idx] + fsigmoid(gi) * ftanh(gg);
    float hn = fsigmoid(go) * ftanh(cn);
    g_hnew[idx] = hn;
    out[b * 512 + u] = hn;
    __shared__ float red[8][4];
    float4 w4 = *(const float4*)(Wa + u * 4);
    float p0 = hn * w4.x, p1 = hn * w4.y, p2 = hn * w4.z, p3 = hn * w4.w;
    #pragma unroll
    for (int o = 16; o > 0; o >>= 1) {
        p0 += __shfl_xor_sync(0xffffffffu, p0, o);
        p1 += __shfl_xor_sync(0xffffffffu, p1, o);
        p2 += __shfl_xor_sync(0xffffffffu, p2, o);
        p3 += __shfl_xor_sync(0xffffffffu, p3, o);
    }
    if ((u & 31) == 0) {
        red[u >> 5][0] = p0; red[u >> 5][1] = p1;
        red[u >> 5][2] = p2; red[u >> 5][3] = p3;
    }
    __syncthreads();
    if (u < 4) {
        float a = ba[u];
        #pragma unroll
        for (int i = 0; i < 8; i++) a += red[i][u];
        g_alpha[b * 4 + u] = fsigmoid(ftanh(a));
    }
}

// ---------------- K3: keys (raw fp32, alpha-scaled fp16 T, normalized fp16) ----------
__global__ void k_kt(const float* __restrict__ Wk, const float* __restrict__ bk) {
    int q = blockIdx.x;            // r*B + b
    int r = q >> 8, b = q & 255;
    int m = threadIdx.x;           // 64 threads
    __shared__ float hs[U_];
    __shared__ float red[2];
    ((float4*)hs)[m] = ((const float4*)(g_hnew + b * U_))[m];
    __syncthreads();
    float acc = bk[r * M_ + m];
    const float* wk = Wk + r * U_ * M_ + m;
    #pragma unroll 8
    for (int u = 0; u < U_; u++) acc += hs[u] * wk[u * M_];
    float kt = ftanh(acc);
    g_kt[q * M_ + m] = kt;
    g_ktTh[(r * M_ + m) * B_ + b] = __float2half(kt * g_alpha[b * 4 + r]);
    float s = kt * kt;
    #pragma unroll
    for (int o = 16; o > 0; o >>= 1) s += __shfl_xor_sync(0xffffffffu, s, o);
    if ((m & 31) == 0) red[m >> 5] = s;
    __syncthreads();
    float inv = 1.0f / sqrtf(red[0] + red[1]);
    g_ktsh[q * M_ + m] = __float2half(kt * inv);
}

// ---------------- K4: write deltas (tensor), pipelined, 3 CTAs/SM ----------------
// dA[r][m][n] = (alpha.*kt[r])^T @ wr_prev[r].  grid (N_/128, R_), 256 threads.
__global__ void __launch_bounds__(256, 3) k_dA(const float* __restrict__ wrp) {
    __shared__ __align__(16) __half sP[64 * 136];   // [b-chunk 64][n 128 +8]
    __shared__ __align__(16) __half sA[64 * 72];    // [m 64][b-chunk 64 +8]
    const int t = threadIdx.x, w = t >> 5, l = t & 31;
    const int n0 = blockIdx.x * 128, r = blockIdx.y;
    const int mrow = (w & 3) * 16, nhalf = (w >> 2) * 64;
    const float* wr_base = wrp + (size_t)r * B_ * N_;
    float acc[8][4] = {};
    uint32_t pb = smem_u32(sP), ab = smem_u32(sA);

    const int prow = t >> 5, pc = t & 31;
    const int arow = t >> 3, ac4 = t & 7;
    float4 pv[8]; uint4 av[2];
    #pragma unroll
    for (int i = 0; i < 8; i++)
        pv[i] = *(const float4*)(wr_base + (size_t)(prow + i * 8) * N_ + n0 + pc * 4);
    #pragma unroll
    for (int i = 0; i < 2; i++)
        av[i] = *(const uint4*)(g_ktTh + (size_t)(r * M_ + arow + i * 32) * B_ + ac4 * 8);

    for (int kt = 0; kt < 4; kt++) {
        __syncthreads();
        #pragma unroll
        for (int i = 0; i < 8; i++) {
            int row = prow + i * 8;
            *(__half2*)(sP + row * 136 + pc * 4)     = __floats2half2_rn(pv[i].x, pv[i].y);
            *(__half2*)(sP + row * 136 + pc * 4 + 2) = __floats2half2_rn(pv[i].z, pv[i].w);
        }
        #pragma unroll
        for (int i = 0; i < 2; i++)
            *(uint4*)(sA + (arow + i * 32) * 72 + ac4 * 8) = av[i];
        __syncthreads();
        if (kt < 3) {
            int kb = (kt + 1) * 64;
            #pragma unroll
            for (int i = 0; i < 8; i++)
                pv[i] = *(const float4*)(wr_base + (size_t)(kb + prow + i * 8) * N_ + n0 + pc * 4);
            #pragma unroll
            for (int i = 0; i < 2; i++)
                av[i] = *(const uint4*)(g_ktTh + (size_t)(r * M_ + arow + i * 32) * B_ + kb + ac4 * 8);
        }
        #pragma unroll
        for (int k16 = 0; k16 < 4; k16++) {
            uint32_t a[4];
            ldsm4(a, ab + ((mrow + (l & 15)) * 72 + (l >> 4) * 8 + k16 * 16) * 2);
            #pragma unroll
            for (int j = 0; j < 4; j++) {
                uint32_t bb[4];
                int rowb = k16 * 16 + (l & 7) + ((l >> 3) & 1) * 8;
                int colb = nhalf + j * 16 + ((l >> 4) & 1) * 8;
                ldsm4t(bb, pb + (rowb * 136 + colb) * 2);
                mma16816(acc[2 * j],     a, bb[0], bb[1]);
                mma16816(acc[2 * j + 1], a, bb[2], bb[3]);
            }
        }
    }
    int m0 = mrow + (l >> 2), cb = n0 + nhalf + (l & 3) * 2;
    #pragma unroll
    for (int jj = 0; jj < 8; jj++) {
        *(__half2*)(g_dA + (size_t)(r * M_ + m0) * N_ + cb + jj * 8) =
            __floats2half2_rn(acc[jj][0], acc[jj][1]);
        *(__half2*)(g_dA + (size_t)(r * M_ + m0 + 8) * N_ + cb + jj * 8) =
            __floats2half2_rn(acc[jj][2], acc[jj][3]);
    }
}

// ---------------- K5: Ash[n,:] = fp16( A[n,:] / ||A[n,:]|| ); emask = 1 ----------------
__global__ void k_As(const float* __restrict__ A) {
    int n = blockIdx.x * 8 + (threadIdx.x >> 5);
    int lane = threadIdx.x & 31;
    float a0 = A[n * M_ + lane], a1 = A[n * M_ + 32 + lane];
    float s = a0 * a0 + a1 * a1;
    #pragma unroll
    for (int o = 16; o > 0; o >>= 1) s += __shfl_xor_sync(0xffffffffu, s, o);
    float inv = 1.0f / sqrtf(s);
    g_Ash[n * M_ + lane]      = __float2half(a0 * inv);
    g_Ash[n * M_ + 32 + lane] = __float2half(a1 * inv);
    if (lane == 0) g_emask[n] = 1.0f;
}

// ---------------- K6: argmin + erase-mask set ----------------
__global__ void k_argmin(const float* __restrict__ wu) {
    int b = blockIdx.x, t = threadIdx.x;
    const float4* row = (const float4*)(wu + (size_t)b * N_);
    float mv = 3.4e38f; int mi = 0;
    for (int i = t; i < N_ / 4; i += 256) {
        float4 v = row[i];
        int base = i * 4;
        if (v.x < mv) { mv = v.x; mi = base; }
        if (v.y < mv) { mv = v.y; mi = base + 1; }
        if (v.z < mv) { mv = v.z; mi = base + 2; }
        if (v.w < mv) { mv = v.w; mi = base + 3; }
    }
    __shared__ float sv[256];
    __shared__ int   si[256];
    sv[t] = mv; si[t] = mi;
    __syncthreads();
    for (int s = 128; s > 0; s >>= 1) {
        if (t < s) {
            if (sv[t + s] < sv[t] || (sv[t + s] == sv[t] && si[t + s] < si[t])) {
                sv[t] = sv[t + s]; si[t] = si[t + s];
            }
        }
        __syncthreads();
    }
    if (t == 0) {
        g_least[b] = si[0];
        g_emask[si[0]] = 0.0f;
    }
}

// ---------------- K7: deterministic least-used scatter into g_dA ----------------
__global__ void k_scatter() {
    const int r = blockIdx.y;
    __shared__ int sL[B_];
    int t = threadIdx.x, b = blockIdx.x;
    sL[t] = g_least[t];
    __syncthreads();
    int my = sL[b];
    bool owner = true;
    for (int bb = 0; bb < b; bb++) if (sL[bb] == my) { owner = false; break; }
    if (!owner) return;
    if (t < M_) {
        float acc = 0.0f;
        for (int bb = b; bb < B_; bb++)
            if (sL[bb] == my)
                acc += (1.0f - g_alpha[bb * R_ + r]) * g_kt[((r << 8) + bb) * M_ + t];
        size_t o = (size_t)(r * M_ + t) * N_ + my;
        g_dA[o] = __float2half(__half2float(g_dA[o]) + acc);
    }
}

// ---------------- K8: chain: AnT = fp16(tanh^4 chain of A*e + deltas) ----------------
__global__ void k_chain(const float* __restrict__ A) {
    __shared__ float sT[64][65];
    __shared__ float se[64];
    int t = threadIdx.x, n0 = blockIdx.x * 64;
    for (int idx = t; idx < 4096; idx += 256) {
        int row = idx >> 6, c = idx & 63;
        sT[row][c] = A[(size_t)(n0 + row) * M_ + c];
    }
    if (t < 64) se[t] = g_emask[n0 + t];
    __syncthreads();
    for (int idx = t; idx < 4096; idx += 256) {
        int m = idx >> 6, n = idx & 63;
        float a = sT[n][m] * se[n];
        #pragma unroll
        for (int r = 0; r < 4; r++)
            a = ftanh(a + __half2float(g_dA[(size_t)(r * M_ + m) * N_ + n0 + n]));
        g_AnT[(size_t)m * N_ + n0 + n] = __float2half(a);
    }
}

// ---------------- K9: flash fused reads with cp.async double buffering ----------------
__global__ void __launch_bounds__(256, 2) k_read() {
    __shared__ __align__(16) __half sQ[128 * 72];
    __shared__ __align__(16) __half sK[2][128 * 72];
    __shared__ __align__(16) __half sV[2][64 * 136];
    const int t = threadIdx.x, w = t >> 5, l = t & 31;
    const int q0 = blockIdx.y * 128, n0 = blockIdx.x * 1024;
    uint32_t qb = smem_u32(sQ);

    for (int idx = t; idx < 1024; idx += 256) {
        int row = idx >> 3, c4 = idx & 7;
        cpa16(qb + (row * 72 + c4 * 8) * 2, g_ktsh + (size_t)(q0 + row) * M_ + c4 * 8);
    }
    {
        uint32_t kb = smem_u32(sK[0]), vb = smem_u32(sV[0]);
        for (int idx = t; idx < 1024; idx += 256) {
            int row = idx >> 3, c4 = idx & 7;
            cpa16(kb + (row * 72 + c4 * 8) * 2, g_Ash + (size_t)(n0 + row) * M_ + c4 * 8);
        }
        for (int idx = t; idx < 1024; idx += 256) {
            int row = idx >> 4, c4 = idx & 15;
            cpa16(vb + (row * 136 + c4 * 8) * 2, g_AnT + (size_t)row * N_ + n0 + c4 * 8);
        }
    }
    CP_COMMIT();

    uint32_t qa[4][4];
    float acc_o[8][4] = {};
    float den0 = 0.0f, den1 = 0.0f;
    for (int sub = 0; sub < 8; sub++) {
        if (sub + 1 < 8) {
            int kg = n0 + (sub + 1) * 128;
            uint32_t kb = smem_u32(sK[(sub + 1) & 1]), vb = smem_u32(sV[(sub + 1) & 1]);
            for (int idx = t; idx < 1024; idx += 256) {
                int row = idx >> 3, c4 = idx & 7;
                cpa16(kb + (row * 72 + c4 * 8) * 2, g_Ash + (size_t)(kg + row) * M_ + c4 * 8);
            }
            for (int idx = t; idx < 1024; idx += 256) {
                int row = idx >> 4, c4 = idx & 15;
                cpa16(vb + (row * 136 + c4 * 8) * 2, g_AnT + (size_t)row * N_ + kg + c4 * 8);
            }
        }
        CP_COMMIT();
        CP_WAIT(1);
        __syncthreads();
        if (sub == 0) {
            #pragma unroll
            for (int k16 = 0; k16 < 4; k16++)
                ldsm4(qa[k16], qb + ((w * 16 + (l & 15)) * 72 + (l >> 4) * 8 + k16 * 16) * 2);
        }
        uint32_t kb = smem_u32(sK[sub & 1]), vb = smem_u32(sV[sub & 1]);
        float s[16][4] = {};
        #pragma unroll
        for (int k16 = 0; k16 < 4; k16++) {
            #pragma unroll
            for (int j = 0; j < 8; j++) {
                uint32_t bbf[4];
                ldsm4(bbf, kb + ((j * 16 + (l & 15)) * 72 + (l >> 4) * 8 + k16 * 16) * 2);
                mma16816(s[2 * j],     qa[k16], bbf[0], bbf[2]);
                mma16816(s[2 * j + 1], qa[k16], bbf[1], bbf[3]);
            }
        }
        #pragma unroll
        for (int kk = 0; kk < 8; kk++) {
            float e00 = __expf(s[2 * kk][0]),     e01 = __expf(s[2 * kk][1]);
            float e02 = __expf(s[2 * kk][2]),     e03 = __expf(s[2 * kk][3]);
            float e10 = __expf(s[2 * kk + 1][0]), e11 = __expf(s[2 * kk + 1][1]);
            float e12 = __expf(s[2 * kk + 1][2]), e13 = __expf(s[2 * kk + 1][3]);
            den0 += e00 + e01 + e10 + e11;
            den1 += e02 + e03 + e12 + e13;
            uint32_t pa[4];
            pa[0] = packh2(e00, e01);
            pa[1] = packh2(e02, e03);
            pa[2] = packh2(e10, e11);
            pa[3] = packh2(e12, e13);
            #pragma unroll
            for (int j = 0; j < 4; j++) {
                uint32_t bbf[4];
                ldsm4(bbf, vb + ((j * 16 + (l & 15)) * 136 + (l >> 4) * 8 + kk * 16) * 2);
                mma16816(acc_o[2 * j],     pa, bbf[0], bbf[2]);
                mma16816(acc_o[2 * j + 1], pa, bbf[1], bbf[3]);
            }
        }
        __syncthreads();
    }
    den0 += __shfl_xor_sync(0xffffffffu, den0, 1);
    den0 += __shfl_xor_sync(0xffffffffu, den0, 2);
    den1 += __shfl_xor_sync(0xffffffffu, den1, 1);
    den1 += __shfl_xor_sync(0xffffffffu, den1, 2);
    int r0 = q0 + w * 16 + (l >> 2);
    if ((l & 3) == 0) {
        g_pden[r0 * NSPL + blockIdx.x]       = den0;
        g_pden[(r0 + 8) * NSPL + blockIdx.x] = den1;
    }
    float* p0 = g_pacc + ((size_t)r0 * NSPL + blockIdx.x) * M_;
    float* p1 = g_pacc + ((size_t)(r0 + 8) * NSPL + blockIdx.x) * M_;
    int cb = (l & 3) * 2;
    #pragma unroll
    for (int jj = 0; jj < 8; jj++) {
        *(float2*)(p0 + jj * 8 + cb) = make_float2(acc_o[jj][0], acc_o[jj][1]);
        *(float2*)(p1 + jj * 8 + cb) = make_float2(acc_o[jj][2], acc_o[jj][3]);
    }
}

// ---------------- K10: combine partials -> out[:, 256:512] ----------------
__global__ void k_combine(float* __restrict__ out) {
    int q = blockIdx.x;          // r*B + b
    int m = threadIdx.x;         // 64
    float acc = 0.0f, den = 0.0f;
    #pragma unroll
    for (int s = 0; s < NSPL; s++) {
        acc += g_pacc[((size_t)q * NSPL + s) * M_ + m];
        den += g_pden[q * NSPL + s];
    }
    int r = q >> 8, b = q & 255;
    out[b * 512 + 256 + r * M_ + m] = acc / den;
}

// ---------------- launch ----------------
extern "C" void kernel_launch(void* const* d_in, const int* in_sizes, int n_in,
                              void* d_out, int out_size) {
    const float* x    = (const float*)d_in[0];
    const float* A    = (const float*)d_in[1];
    const float* wrp  = (const float*)d_in[2];
    const float* wu   = (const float*)d_in[3];
    const float* rp   = (const float*)d_in[4];
    const float* h    = (const float*)d_in[5];
    const float* c    = (const float*)d_in[6];
    const float* W    = (const float*)d_in[7];
    const float* Uw   = (const float*)d_in[8];
    const float* bias = (const float*)d_in[9];
    const float* Wk   = (const float*)d_in[10];
    const float* bk   = (const float*)d_in[11];
    const float* Wa   = (const float*)d_in[12];
    const float* ba   = (const float*)d_in[13];
    float* out = (float*)d_out;

    k_gates  <<<dim3(16, 4), 256>>>(x, rp, h, W, Uw, bias);   // 0
    k_lstm   <<<B_, 256>>>(c, out, Wa, ba);                   // 1
    k_kt     <<<QT_, 64>>>(Wk, bk);                           // 2
    k_dA     <<<dim3(N_ / 128, R_), 256>>>(wrp);              // 3 <- profiled slot
    k_As     <<<N_ / 8, 256>>>(A);                            // 4
    k_argmin <<<B_, 256>>>(wu);                               // 5
    k_scatter<<<dim3(B_, R_), 256>>>();                       // 6
    k_chain  <<<N_ / 64, 256>>>(A);                           // 7
    k_read   <<<dim3(NSPL, 8), 256>>>();                      // 8
    k_combine<<<QT_, 64>>>(out);                              // 9
}

// round 8
// speedup vs baseline: 6.5418x; 1.0799x over previous
#include <cuda_runtime.h>
#include <cuda_fp16.h>
#include <math.h>
#include <stdint.h>

// Problem constants
#define B_   256
#define N_   32768
#define M_   64
#define R_   4
#define U_   256
#define DIN_ 512
#define G4_  1024
#define QT_  1024      // total queries = R*B
#define NSPL 32        // flash reads: split of N (1024 keys per chunk)

// ---------------- static scratch ----------------
__device__ float  g_gates[B_ * G4_];
__device__ float  g_hnew [B_ * U_];
__device__ float  g_kt   [QT_ * M_];          // raw tanh keys fp32 (scatter)
__device__ __half g_ktsh [QT_ * M_];          // normalized keys fp16 [q][m]
__device__ __half g_ktTh [R_ * M_ * B_];      // alpha-scaled keys fp16 [r][m][b]
__device__ float  g_alpha[B_ * R_];
__device__ int    g_least[B_];
__device__ __half g_Ash  [N_ * M_];           // A rows / ||A[n]|| fp16 [n][m]
__device__ __half g_dA   [R_ * M_ * N_];      // write deltas fp16 [r][m][n]
__device__ float  g_emask[N_];
__device__ __half g_AnT  [M_ * N_];           // new memory fp16 [m][n]
__device__ float  g_pden [QT_ * NSPL];
__device__ float  g_pacc [QT_ * NSPL * M_];

// fast transcendentals (bounded args on this workload; err ~1e-6 << fp16 noise)
__device__ __forceinline__ float fsigmoid(float x) {
    return __fdividef(1.0f, 1.0f + __expf(-x));
}
__device__ __forceinline__ float ftanh(float x) {
    float e = __expf(2.0f * x);
    return __fdividef(e - 1.0f, e + 1.0f);
}

__device__ __forceinline__ uint32_t smem_u32(const void* p) {
    uint32_t a;
    asm("{ .reg .u64 t; cvta.to.shared.u64 t, %1; cvt.u32.u64 %0, t; }" : "=r"(a) : "l"(p));
    return a;
}
__device__ __forceinline__ void ldsm4(uint32_t* r, uint32_t addr) {
    asm volatile("ldmatrix.sync.aligned.m8n8.x4.shared.b16 {%0,%1,%2,%3}, [%4];"
        : "=r"(r[0]), "=r"(r[1]), "=r"(r[2]), "=r"(r[3]) : "r"(addr));
}
__device__ __forceinline__ void ldsm4t(uint32_t* r, uint32_t addr) {
    asm volatile("ldmatrix.sync.aligned.m8n8.x4.trans.shared.b16 {%0,%1,%2,%3}, [%4];"
        : "=r"(r[0]), "=r"(r[1]), "=r"(r[2]), "=r"(r[3]) : "r"(addr));
}
__device__ __forceinline__ void mma16816(float* c, const uint32_t* a, uint32_t b0, uint32_t b1) {
    asm volatile("mma.sync.aligned.m16n8k16.row.col.f32.f16.f16.f32 "
        "{%0,%1,%2,%3}, {%4,%5,%6,%7}, {%8,%9}, {%0,%1,%2,%3};"
        : "+f"(c[0]), "+f"(c[1]), "+f"(c[2]), "+f"(c[3])
        : "r"(a[0]), "r"(a[1]), "r"(a[2]), "r"(a[3]), "r"(b0), "r"(b1));
}
__device__ __forceinline__ uint32_t packh2(float a, float b) {
    __half2 h = __floats2half2_rn(a, b);
    return *(uint32_t*)&h;
}
__device__ __forceinline__ void cpa16(uint32_t dst, const void* src) {
    asm volatile("cp.async.ca.shared.global [%0], [%1], 16;" :: "r"(dst), "l"(src));
}
__device__ __forceinline__ void cpa4(uint32_t dst, const void* src) {
    asm volatile("cp.async.ca.shared.global [%0], [%1], 4;" :: "r"(dst), "l"(src));
}
#define CP_COMMIT() asm volatile("cp.async.commit_group;" ::: "memory")
#define CP_WAIT(n)  asm volatile("cp.async.wait_group %0;" :: "n"(n) : "memory")

// ---------------- K1: gates = [x|read_prev|h] @ [W;Uw] + b (cp.async pipelined) ------
__global__ void __launch_bounds__(256) k_gates(
        const float* __restrict__ x, const float* __restrict__ rp,
        const float* __restrict__ h, const float* __restrict__ W,
        const float* __restrict__ Uw, const float* __restrict__ bias) {
    const int BK = 16;
    __shared__ float sA[2][64][17];
    __shared__ float sB[2][16][64];
    int t  = threadIdx.x;
    int b0 = blockIdx.y * 64;
    int j0 = blockIdx.x * 64;
    int tr = t >> 4, tc = t & 15;

    #define GATES_PREFETCH(k0, buf) do {                                                \
        for (int l = t; l < 1024; l += 256) {                                           \
            int i = l >> 4, k = l & 15;                                                 \
            int kk = (k0) + k, b = b0 + i;                                              \
            const float* src;                                                           \
            if (kk < DIN_)       src = x + b * DIN_ + kk;                               \
            else if (kk < 768) { int id = kk - DIN_; src = rp + ((id >> 6) * B_ + b) * M_ + (id & 63); } \
            else                 src = h + b * U_ + (kk - 768);                         \
            cpa4(smem_u32(&sA[buf][i][k]), src);                                        \
        }                                                                               \
        {                                                                               \
            int row = t >> 4, c4 = t & 15;                                              \
            int kk = (k0) + row;                                                        \
            const float* src = (kk < 768) ? W + kk * G4_ + j0 + c4 * 4                  \
                                          : Uw + (kk - 768) * G4_ + j0 + c4 * 4;        \
            cpa16(smem_u32(&sB[buf][row][c4 * 4]), src);                                \
        }                                                                               \
        CP_COMMIT();                                                                    \
    } while (0)

    GATES_PREFETCH(0, 0);
    float acc[4][4] = {};
    for (int kt = 0; kt < 64; kt++) {
        int buf = kt & 1;
        if (kt < 63) GATES_PREFETCH((kt + 1) * BK, buf ^ 1);
        CP_WAIT(1);
        __syncthreads();
        #pragma unroll
        for (int k = 0; k < BK; k++) {
            float a[4], bb[4];
            #pragma unroll
            for (int i = 0; i < 4; i++) a[i] = sA[buf][tr * 4 + i][k];
            float4 b4 = *(const float4*)&sB[buf][k][tc * 4];
            bb[0] = b4.x; bb[1] = b4.y; bb[2] = b4.z; bb[3] = b4.w;
            #pragma unroll
            for (int i = 0; i < 4; i++)
                #pragma unroll
                for (int j = 0; j < 4; j++) acc[i][j] += a[i] * bb[j];
        }
        __syncthreads();
    }
    #pragma unroll
    for (int i = 0; i < 4; i++)
        #pragma unroll
        for (int j = 0; j < 4; j++)
            g_gates[(b0 + tr * 4 + i) * G4_ + j0 + tc * 4 + j] = acc[i][j] + bias[j0 + tc * 4 + j];
    #undef GATES_PREFETCH
}

// ---------------- K2: LSTM pointwise -> h_new, fused alpha ----------------
__global__ void k_lstm(const float* __restrict__ c, float* __restrict__ out,
                       const float* __restrict__ Wa, const float* __restrict__ ba) {
    int b = blockIdx.x, u = threadIdx.x;
    int idx = b * 256 + u;
    const float* g = g_gates + b * G4_;
    float gi = g[u], gf = g[256 + u], gg = g[512 + u], go = g[768 + u];
    float cn = fsigmoid(gf) * c[idx] + fsigmoid(gi) * ftanh(gg);
    float hn = fsigmoid(go) * ftanh(cn);
    g_hnew[idx] = hn;
    out[b * 512 + u] = hn;
    __shared__ float red[8][4];
    float4 w4 = *(const float4*)(Wa + u * 4);
    float p0 = hn * w4.x, p1 = hn * w4.y, p2 = hn * w4.z, p3 = hn * w4.w;
    #pragma unroll
    for (int o = 16; o > 0; o >>= 1) {
        p0 += __shfl_xor_sync(0xffffffffu, p0, o);
        p1 += __shfl_xor_sync(0xffffffffu, p1, o);
        p2 += __shfl_xor_sync(0xffffffffu, p2, o);
        p3 += __shfl_xor_sync(0xffffffffu, p3, o);
    }
    if ((u & 31) == 0) {
        red[u >> 5][0] = p0; red[u >> 5][1] = p1;
        red[u >> 5][2] = p2; red[u >> 5][3] = p3;
    }
    __syncthreads();
    if (u < 4) {
        float a = ba[u];
        #pragma unroll
        for (int i = 0; i < 8; i++) a += red[i][u];
        g_alpha[b * 4 + u] = fsigmoid(ftanh(a));
    }
}

// ---------------- K3: keys (raw fp32, alpha-scaled fp16 T, normalized fp16) ----------
__global__ void k_kt(const float* __restrict__ Wk, const float* __restrict__ bk) {
    int q = blockIdx.x;            // r*B + b
    int r = q >> 8, b = q & 255;
    int m = threadIdx.x;           // 64 threads
    __shared__ float hs[U_];
    __shared__ float red[2];
    ((float4*)hs)[m] = ((const float4*)(g_hnew + b * U_))[m];
    __syncthreads();
    float acc = bk[r * M_ + m];
    const float* wk = Wk + r * U_ * M_ + m;
    #pragma unroll 8
    for (int u = 0; u < U_; u++) acc += hs[u] * wk[u * M_];
    float kt = ftanh(acc);
    g_kt[q * M_ + m] = kt;
    g_ktTh[(r * M_ + m) * B_ + b] = __float2half(kt * g_alpha[b * 4 + r]);
    float s = kt * kt;
    #pragma unroll
    for (int o = 16; o > 0; o >>= 1) s += __shfl_xor_sync(0xffffffffu, s, o);
    if ((m & 31) == 0) red[m >> 5] = s;
    __syncthreads();
    float inv = 1.0f / sqrtf(red[0] + red[1]);
    g_ktsh[q * M_ + m] = __float2half(kt * inv);
}

// ---------------- K4: write deltas (tensor), pipelined, packed STS ----------------
// dA[r][m][n] = (alpha.*kt[r])^T @ wr_prev[r].  grid (N_/128, R_), 256 threads.
__global__ void __launch_bounds__(256) k_dA(const float* __restrict__ wrp) {
    __shared__ __align__(16) __half sP[64 * 136];   // [b-chunk 64][n 128 +8]
    __shared__ __align__(16) __half sA[64 * 72];    // [m 64][b-chunk 64 +8]
    const int t = threadIdx.x, w = t >> 5, l = t & 31;
    const int n0 = blockIdx.x * 128, r = blockIdx.y;
    const int mrow = (w & 3) * 16, nhalf = (w >> 2) * 64;
    const float* wr_base = wrp + (size_t)r * B_ * N_;
    float acc[8][4] = {};
    uint32_t pb = smem_u32(sP), ab = smem_u32(sA);

    // per-thread prefetch: 4 rows x 8 floats (2 float4) of wr_prev + 2 uint4 of ktTh
    const int prow2 = t >> 4, pg = t & 15;          // wr: rows prow2 + i*16, col group pg (8 floats)
    const int arow = t >> 3, ac4 = t & 7;           // kt: rows arow + i*32, col ac4
    float4 pv[8]; uint4 av[2];
    #pragma unroll
    for (int i = 0; i < 4; i++) {
        const float* s = wr_base + (size_t)(prow2 + i * 16) * N_ + n0 + pg * 8;
        pv[2 * i]     = *(const float4*)s;
        pv[2 * i + 1] = *(const float4*)(s + 4);
    }
    #pragma unroll
    for (int i = 0; i < 2; i++)
        av[i] = *(const uint4*)(g_ktTh + (size_t)(r * M_ + arow + i * 32) * B_ + ac4 * 8);

    for (int kt = 0; kt < 4; kt++) {
        __syncthreads();
        #pragma unroll
        for (int i = 0; i < 4; i++) {       // one STS.128 per row instead of 4 STS.32
            int row = prow2 + i * 16;
            uint4 o;
            o.x = packh2(pv[2 * i].x,     pv[2 * i].y);
            o.y = packh2(pv[2 * i].z,     pv[2 * i].w);
            o.z = packh2(pv[2 * i + 1].x, pv[2 * i + 1].y);
            o.w = packh2(pv[2 * i + 1].z, pv[2 * i + 1].w);
            *(uint4*)(sP + row * 136 + pg * 8) = o;
        }
        #pragma unroll
        for (int i = 0; i < 2; i++)
            *(uint4*)(sA + (arow + i * 32) * 72 + ac4 * 8) = av[i];
        __syncthreads();
        if (kt < 3) {                        // prefetch next k-tile while MMAs run
            int kb = (kt + 1) * 64;
            #pragma unroll
            for (int i = 0; i < 4; i++) {
                const float* s = wr_base + (size_t)(kb + prow2 + i * 16) * N_ + n0 + pg * 8;
                pv[2 * i]     = *(const float4*)s;
                pv[2 * i + 1] = *(const float4*)(s + 4);
            }
            #pragma unroll
            for (int i = 0; i < 2; i++)
                av[i] = *(const uint4*)(g_ktTh + (size_t)(r * M_ + arow + i * 32) * B_ + kb + ac4 * 8);
        }
        #pragma unroll
        for (int k16 = 0; k16 < 4; k16++) {
            uint32_t a[4];
            ldsm4(a, ab + ((mrow + (l & 15)) * 72 + (l >> 4) * 8 + k16 * 16) * 2);
            #pragma unroll
            for (int j = 0; j < 4; j++) {
                uint32_t bb[4];
                int rowb = k16 * 16 + (l & 7) + ((l >> 3) & 1) * 8;
                int colb = nhalf + j * 16 + ((l >> 4) & 1) * 8;
                ldsm4t(bb, pb + (rowb * 136 + colb) * 2);
                mma16816(acc[2 * j],     a, bb[0], bb[1]);
                mma16816(acc[2 * j + 1], a, bb[2], bb[3]);
            }
        }
    }
    int m0 = mrow + (l >> 2), cb = n0 + nhalf + (l & 3) * 2;
    #pragma unroll
    for (int jj = 0; jj < 8; jj++) {
        *(__half2*)(g_dA + (size_t)(r * M_ + m0) * N_ + cb + jj * 8) =
            __floats2half2_rn(acc[jj][0], acc[jj][1]);
        *(__half2*)(g_dA + (size_t)(r * M_ + m0 + 8) * N_ + cb + jj * 8) =
            __floats2half2_rn(acc[jj][2], acc[jj][3]);
    }
}

// ---------------- K5: Ash[n,:] = fp16( A[n,:] / ||A[n,:]|| ); emask = 1 ----------------
__global__ void k_As(const float* __restrict__ A) {
    int n = blockIdx.x * 8 + (threadIdx.x >> 5);
    int lane = threadIdx.x & 31;
    float a0 = A[n * M_ + lane], a1 = A[n * M_ + 32 + lane];
    float s = a0 * a0 + a1 * a1;
    #pragma unroll
    for (int o = 16; o > 0; o >>= 1) s += __shfl_xor_sync(0xffffffffu, s, o);
    float inv = 1.0f / sqrtf(s);
    g_Ash[n * M_ + lane]      = __float2half(a0 * inv);
    g_Ash[n * M_ + 32 + lane] = __float2half(a1 * inv);
    if (lane == 0) g_emask[n] = 1.0f;
}

// ---------------- K6: argmin + erase-mask set ----------------
__global__ void k_argmin(const float* __restrict__ wu) {
    int b = blockIdx.x, t = threadIdx.x;
    const float4* row = (const float4*)(wu + (size_t)b * N_);
    float mv = 3.4e38f; int mi = 0;
    for (int i = t; i < N_ / 4; i += 256) {
        float4 v = row[i];
        int base = i * 4;
        if (v.x < mv) { mv = v.x; mi = base; }
        if (v.y < mv) { mv = v.y; mi = base + 1; }
        if (v.z < mv) { mv = v.z; mi = base + 2; }
        if (v.w < mv) { mv = v.w; mi = base + 3; }
    }
    __shared__ float sv[256];
    __shared__ int   si[256];
    sv[t] = mv; si[t] = mi;
    __syncthreads();
    for (int s = 128; s > 0; s >>= 1) {
        if (t < s) {
            if (sv[t + s] < sv[t] || (sv[t + s] == sv[t] && si[t + s] < si[t])) {
                sv[t] = sv[t + s]; si[t] = si[t + s];
            }
        }
        __syncthreads();
    }
    if (t == 0) {
        g_least[b] = si[0];
        g_emask[si[0]] = 0.0f;
    }
}

// ---------------- K7: deterministic least-used scatter into g_dA ----------------
__global__ void k_scatter() {
    const int r = blockIdx.y;
    __shared__ int sL[B_];
    int t = threadIdx.x, b = blockIdx.x;
    sL[t] = g_least[t];
    __syncthreads();
    int my = sL[b];
    bool owner = true;
    for (int bb = 0; bb < b; bb++) if (sL[bb] == my) { owner = false; break; }
    if (!owner) return;
    if (t < M_) {
        float acc = 0.0f;
        for (int bb = b; bb < B_; bb++)
            if (sL[bb] == my)
                acc += (1.0f - g_alpha[bb * R_ + r]) * g_kt[((r << 8) + bb) * M_ + t];
        size_t o = (size_t)(r * M_ + t) * N_ + my;
        g_dA[o] = __float2half(__half2float(g_dA[o]) + acc);
    }
}

// ---------------- K8: chain: AnT = fp16(tanh^4 chain of A*e + deltas) ----------------
__global__ void k_chain(const float* __restrict__ A) {
    __shared__ float sT[64][65];
    __shared__ float se[64];
    int t = threadIdx.x, n0 = blockIdx.x * 64;
    for (int idx = t; idx < 4096; idx += 256) {
        int row = idx >> 6, c = idx & 63;
        sT[row][c] = A[(size_t)(n0 + row) * M_ + c];
    }
    if (t < 64) se[t] = g_emask[n0 + t];
    __syncthreads();
    for (int idx = t; idx < 4096; idx += 256) {
        int m = idx >> 6, n = idx & 63;
        float a = sT[n][m] * se[n];
        #pragma unroll
        for (int r = 0; r < 4; r++)
            a = ftanh(a + __half2float(g_dA[(size_t)(r * M_ + m) * N_ + n0 + n]));
        g_AnT[(size_t)m * N_ + n0 + n] = __float2half(a);
    }
}

// ---------------- K9: flash fused reads with cp.async double buffering ----------------
__global__ void __launch_bounds__(256, 2) k_read() {
    __shared__ __align__(16) __half sQ[128 * 72];
    __shared__ __align__(16) __half sK[2][128 * 72];
    __shared__ __align__(16) __half sV[2][64 * 136];
    const int t = threadIdx.x, w = t >> 5, l = t & 31;
    const int q0 = blockIdx.y * 128, n0 = blockIdx.x * 1024;
    uint32_t qb = smem_u32(sQ);

    for (int idx = t; idx < 1024; idx += 256) {
        int row = idx >> 3, c4 = idx & 7;
        cpa16(qb + (row * 72 + c4 * 8) * 2, g_ktsh + (size_t)(q0 + row) * M_ + c4 * 8);
    }
    {
        uint32_t kb = smem_u32(sK[0]), vb = smem_u32(sV[0]);
        for (int idx = t; idx < 1024; idx += 256) {
            int row = idx >> 3, c4 = idx & 7;
            cpa16(kb + (row * 72 + c4 * 8) * 2, g_Ash + (size_t)(n0 + row) * M_ + c4 * 8);
        }
        for (int idx = t; idx < 1024; idx += 256) {
            int row = idx >> 4, c4 = idx & 15;
            cpa16(vb + (row * 136 + c4 * 8) * 2, g_AnT + (size_t)row * N_ + n0 + c4 * 8);
        }
    }
    CP_COMMIT();

    uint32_t qa[4][4];
    float acc_o[8][4] = {};
    float den0 = 0.0f, den1 = 0.0f;
    for (int sub = 0; sub < 8; sub++) {
        if (sub + 1 < 8) {
            int kg = n0 + (sub + 1) * 128;
            uint32_t kb = smem_u32(sK[(sub + 1) & 1]), vb = smem_u32(sV[(sub + 1) & 1]);
            for (int idx = t; idx < 1024; idx += 256) {
                int row = idx >> 3, c4 = idx & 7;
                cpa16(kb + (row * 72 + c4 * 8) * 2, g_Ash + (size_t)(kg + row) * M_ + c4 * 8);
            }
            for (int idx = t; idx < 1024; idx += 256) {
                int row = idx >> 4, c4 = idx & 15;
                cpa16(vb + (row * 136 + c4 * 8) * 2, g_AnT + (size_t)row * N_ + kg + c4 * 8);
            }
        }
        CP_COMMIT();
        CP_WAIT(1);
        __syncthreads();
        if (sub == 0) {
            #pragma unroll
            for (int k16 = 0; k16 < 4; k16++)
                ldsm4(qa[k16], qb + ((w * 16 + (l & 15)) * 72 + (l >> 4) * 8 + k16 * 16) * 2);
        }
        uint32_t kb = smem_u32(sK[sub & 1]), vb = smem_u32(sV[sub & 1]);
        float s[16][4] = {};
        #pragma unroll
        for (int k16 = 0; k16 < 4; k16++) {
            #pragma unroll
            for (int j = 0; j < 8; j++) {
                uint32_t bbf[4];
                ldsm4(bbf, kb + ((j * 16 + (l & 15)) * 72 + (l >> 4) * 8 + k16 * 16) * 2);
                mma16816(s[2 * j],     qa[k16], bbf[0], bbf[2]);
                mma16816(s[2 * j + 1], qa[k16], bbf[1], bbf[3]);
            }
        }
        #pragma unroll
        for (int kk = 0; kk < 8; kk++) {
            float e00 = __expf(s[2 * kk][0]),     e01 = __expf(s[2 * kk][1]);
            float e02 = __expf(s[2 * kk][2]),     e03 = __expf(s[2 * kk][3]);
            float e10 = __expf(s[2 * kk + 1][0]), e11 = __expf(s[2 * kk + 1][1]);
            float e12 = __expf(s[2 * kk + 1][2]), e13 = __expf(s[2 * kk + 1][3]);
            den0 += e00 + e01 + e10 + e11;
            den1 += e02 + e03 + e12 + e13;
            uint32_t pa[4];
            pa[0] = packh2(e00, e01);
            pa[1] = packh2(e02, e03);
            pa[2] = packh2(e10, e11);
            pa[3] = packh2(e12, e13);
            #pragma unroll
            for (int j = 0; j < 4; j++) {
                uint32_t bbf[4];
                ldsm4(bbf, vb + ((j * 16 + (l & 15)) * 136 + (l >> 4) * 8 + kk * 16) * 2);
                mma16816(acc_o[2 * j],     pa, bbf[0], bbf[2]);
                mma16816(acc_o[2 * j + 1], pa, bbf[1], bbf[3]);
            }
        }
        __syncthreads();
    }
    den0 += __shfl_xor_sync(0xffffffffu, den0, 1);
    den0 += __shfl_xor_sync(0xffffffffu, den0, 2);
    den1 += __shfl_xor_sync(0xffffffffu, den1, 1);
    den1 += __shfl_xor_sync(0xffffffffu, den1, 2);
    int r0 = q0 + w * 16 + (l >> 2);
    if ((l & 3) == 0) {
        g_pden[r0 * NSPL + blockIdx.x]       = den0;
        g_pden[(r0 + 8) * NSPL + blockIdx.x] = den1;
    }
    float* p0 = g_pacc + ((size_t)r0 * NSPL + blockIdx.x) * M_;
    float* p1 = g_pacc + ((size_t)(r0 + 8) * NSPL + blockIdx.x) * M_;
    int cb = (l & 3) * 2;
    #pragma unroll
    for (int jj = 0; jj < 8; jj++) {
        *(float2*)(p0 + jj * 8 + cb) = make_float2(acc_o[jj][0], acc_o[jj][1]);
        *(float2*)(p1 + jj * 8 + cb) = make_float2(acc_o[jj][2], acc_o[jj][3]);
    }
}

// ---------------- K10: combine partials -> out[:, 256:512] ----------------
__global__ void k_combine(float* __restrict__ out) {
    int q = blockIdx.x;          // r*B + b
    int m = threadIdx.x;         // 64
    float acc = 0.0f, den = 0.0f;
    #pragma unroll
    for (int s = 0; s < NSPL; s++) {
        acc += g_pacc[((size_t)q * NSPL + s) * M_ + m];
        den += g_pden[q * NSPL + s];
    }
    int r = q >> 8, b = q & 255;
    out[b * 512 + 256 + r * M_ + m] = acc / den;
}

// ---------------- launch ----------------
extern "C" void kernel_launch(void* const* d_in, const int* in_sizes, int n_in,
                              void* d_out, int out_size) {
    const float* x    = (const float*)d_in[0];
    const float* A    = (const float*)d_in[1];
    const float* wrp  = (const float*)d_in[2];
    const float* wu   = (const float*)d_in[3];
    const float* rp   = (const float*)d_in[4];
    const float* h    = (const float*)d_in[5];
    const float* c    = (const float*)d_in[6];
    const float* W    = (const float*)d_in[7];
    const float* Uw   = (const float*)d_in[8];
    const float* bias = (const float*)d_in[9];
    const float* Wk   = (const float*)d_in[10];
    const float* bk   = (const float*)d_in[11];
    const float* Wa   = (const float*)d_in[12];
    const float* ba   = (const float*)d_in[13];
    float* out = (float*)d_out;

    k_gates  <<<dim3(16, 4), 256>>>(x, rp, h, W, Uw, bias);   // 0
    k_lstm   <<<B_, 256>>>(c, out, Wa, ba);                   // 1
    k_kt     <<<QT_, 64>>>(Wk, bk);                           // 2
    k_dA     <<<dim3(N_ / 128, R_), 256>>>(wrp);              // 3 <- profiled slot
    k_As     <<<N_ / 8, 256>>>(A);                            // 4
    k_argmin <<<B_, 256>>>(wu);                               // 5
    k_scatter<<<dim3(B_, R_), 256>>>();                       // 6
    k_chain  <<<N_ / 64, 256>>>(A);                           // 7
    k_read   <<<dim3(NSPL, 8), 256>>>();                      // 8
    k_combine<<<QT_, 64>>>(out);                              // 9
}

// round 9
// speedup vs baseline: 6.7728x; 1.0353x over previous
#include <cuda_runtime.h>
#include <cuda_fp16.h>
#include <math.h>
#include <stdint.h>

// Problem constants
#define B_   256
#define N_   32768
#define M_   64
#define R_   4
#define U_   256
#define DIN_ 512
#define G4_  1024
#define QT_  1024      // total queries = R*B
#define NSPL 32        // flash reads: split of N (1024 keys per chunk)

// ---------------- static scratch ----------------
__device__ float  g_gates[B_ * G4_];
__device__ float  g_kt   [QT_ * M_];          // raw tanh keys fp32 (scatter)
__device__ __half g_ktsh [QT_ * M_];          // normalized keys fp16 [q][m]
__device__ __half g_ktTh [R_ * M_ * B_];      // alpha-scaled keys fp16 [r][m][b]
__device__ float  g_alpha[B_ * R_];
__device__ int    g_least[B_];
__device__ __half g_Ash  [N_ * M_];           // A rows / ||A[n]|| fp16 [n][m]
__device__ __half g_dA   [R_ * M_ * N_];      // write deltas fp16 [r][m][n]
__device__ float  g_emask[N_];
__device__ __half g_AnT  [M_ * N_];           // new memory fp16 [m][n]
__device__ float  g_pden [QT_ * NSPL];
__device__ float  g_pacc [QT_ * NSPL * M_];

// fast transcendentals (bounded args on this workload; err ~1e-6 << fp16 noise)
__device__ __forceinline__ float fsigmoid(float x) {
    return __fdividef(1.0f, 1.0f + __expf(-x));
}
__device__ __forceinline__ float ftanh(float x) {
    float e = __expf(2.0f * x);
    return __fdividef(e - 1.0f, e + 1.0f);
}

__device__ __forceinline__ uint32_t smem_u32(const void* p) {
    uint32_t a;
    asm("{ .reg .u64 t; cvta.to.shared.u64 t, %1; cvt.u32.u64 %0, t; }" : "=r"(a) : "l"(p));
    return a;
}
__device__ __forceinline__ void ldsm4(uint32_t* r, uint32_t addr) {
    asm volatile("ldmatrix.sync.aligned.m8n8.x4.shared.b16 {%0,%1,%2,%3}, [%4];"
        : "=r"(r[0]), "=r"(r[1]), "=r"(r[2]), "=r"(r[3]) : "r"(addr));
}
__device__ __forceinline__ void ldsm4t(uint32_t* r, uint32_t addr) {
    asm volatile("ldmatrix.sync.aligned.m8n8.x4.trans.shared.b16 {%0,%1,%2,%3}, [%4];"
        : "=r"(r[0]), "=r"(r[1]), "=r"(r[2]), "=r"(r[3]) : "r"(addr));
}
__device__ __forceinline__ void mma16816(float* c, const uint32_t* a, uint32_t b0, uint32_t b1) {
    asm volatile("mma.sync.aligned.m16n8k16.row.col.f32.f16.f16.f32 "
        "{%0,%1,%2,%3}, {%4,%5,%6,%7}, {%8,%9}, {%0,%1,%2,%3};"
        : "+f"(c[0]), "+f"(c[1]), "+f"(c[2]), "+f"(c[3])
        : "r"(a[0]), "r"(a[1]), "r"(a[2]), "r"(a[3]), "r"(b0), "r"(b1));
}
__device__ __forceinline__ uint32_t packh2(float a, float b) {
    __half2 h = __floats2half2_rn(a, b);
    return *(uint32_t*)&h;
}
__device__ __forceinline__ void cpa16(uint32_t dst, const void* src) {
    asm volatile("cp.async.ca.shared.global [%0], [%1], 16;" :: "r"(dst), "l"(src));
}
#define CP_COMMIT() asm volatile("cp.async.commit_group;" ::: "memory")
#define CP_WAIT(n)  asm volatile("cp.async.wait_group %0;" :: "n"(n) : "memory")

// ---------------- K1: gates GEMM on tensor cores ----------------
// gates[256][1024] = [x|read_prev|h](fp16) @ [W;Uw](fp16) + b, fp32 accum.
// grid (8 col-blocks, 2 row-blocks), 256 threads. CTA tile: 128 b-rows x 128 cols, K=1024.
__global__ void __launch_bounds__(256) k_gates_mma(
        const float* __restrict__ x, const float* __restrict__ rp,
        const float* __restrict__ h, const float* __restrict__ W,
        const float* __restrict__ Uw, const float* __restrict__ bias) {
    __shared__ __align__(16) __half sIn[128 * 24];   // [row 128][k 16 +8]
    __shared__ __align__(16) __half sW [16 * 136];   // [k 16][col 128 +8]
    const int t = threadIdx.x, w = t >> 5, l = t & 31;
    const int j0 = blockIdx.x * 128, b0 = blockIdx.y * 128;
    uint32_t ib = smem_u32(sIn), wb = smem_u32(sW);

    const int irow = t >> 1,  icol = (t & 1) * 8;    // input: 128 rows x 16 (2 thr/row)
    const int wrow = t >> 4,  wcol = (t & 15) * 8;   // weights: 16 rows x 128 (16 thr/row)

    float4 iv0, iv1, wv0, wv1;
    auto ld_in = [&](int k0) {
        const float* s;
        if (k0 < DIN_)      s = x + (size_t)(b0 + irow) * DIN_ + k0 + icol;
        else if (k0 < 768) { int i0 = k0 - DIN_;
                            s = rp + ((size_t)(i0 >> 6) * B_ + b0 + irow) * M_ + (i0 & 63) + icol; }
        else                s = h + (size_t)(b0 + irow) * U_ + (k0 - 768) + icol;
        iv0 = *(const float4*)s; iv1 = *(const float4*)(s + 4);
    };
    auto ld_w = [&](int k0) {
        int kk = k0 + wrow;
        const float* s = (kk < 768) ? W + (size_t)kk * G4_ + j0 + wcol
                                    : Uw + (size_t)(kk - 768) * G4_ + j0 + wcol;
        wv0 = *(const float4*)s; wv1 = *(const float4*)(s + 4);
    };

    ld_in(0); ld_w(0);
    float acc[16][4] = {};
    for (int kt = 0; kt < 64; kt++) {
        __syncthreads();
        {
            uint4 o;
            o.x = packh2(iv0.x, iv0.y); o.y = packh2(iv0.z, iv0.w);
            o.z = packh2(iv1.x, iv1.y); o.w = packh2(iv1.z, iv1.w);
            *(uint4*)(sIn + irow * 24 + icol) = o;
            o.x = packh2(wv0.x, wv0.y); o.y = packh2(wv0.z, wv0.w);
            o.z = packh2(wv1.x, wv1.y); o.w = packh2(wv1.z, wv1.w);
            *(uint4*)(sW + wrow * 136 + wcol) = o;
        }
        __syncthreads();
        if (kt < 63) { ld_in((kt + 1) * 16); ld_w((kt + 1) * 16); }
        uint32_t a[4];
        ldsm4(a, ib + ((w * 16 + (l & 15)) * 24 + (l >> 4) * 8) * 2);
        #pragma unroll
        for (int j = 0; j < 8; j++) {
            uint32_t bb[4];
            int rowb = (l & 7) + ((l >> 3) & 1) * 8;
            int colb = j * 16 + ((l >> 4) & 1) * 8;
            ldsm4t(bb, wb + (rowb * 136 + colb) * 2);
            mma16816(acc[2 * j],     a, bb[0], bb[1]);
            mma16816(acc[2 * j + 1], a, bb[2], bb[3]);
        }
    }
    int mr = w * 16 + (l >> 2);
    int row0 = b0 + mr, row1 = row0 + 8;
    #pragma unroll
    for (int i = 0; i < 16; i++) {
        int col = j0 + i * 8 + (l & 3) * 2;
        float bz0 = bias[col], bz1 = bias[col + 1];
        *(float2*)(g_gates + (size_t)row0 * G4_ + col) = make_float2(acc[i][0] + bz0, acc[i][1] + bz1);
        *(float2*)(g_gates + (size_t)row1 * G4_ + col) = make_float2(acc[i][2] + bz0, acc[i][3] + bz1);
    }
}

// ---------------- K2: fused LSTM + alpha + keys (block = one batch row) ----------------
__global__ void __launch_bounds__(256) k_lstm_kt(
        const float* __restrict__ c, float* __restrict__ out,
        const float* __restrict__ Wa, const float* __restrict__ ba,
        const float* __restrict__ Wk, const float* __restrict__ bk) {
    __shared__ float hs[256];
    __shared__ float red[8][4];
    __shared__ float sal[4];
    __shared__ float sred[8];
    const int b = blockIdx.x, u = threadIdx.x;
    const int idx = b * 256 + u;
    const float* g = g_gates + b * G4_;
    float gi = g[u], gf = g[256 + u], gg = g[512 + u], go = g[768 + u];
    float cn = fsigmoid(gf) * c[idx] + fsigmoid(gi) * ftanh(gg);
    float hn = fsigmoid(go) * ftanh(cn);
    hs[u] = hn;
    out[b * 512 + u] = hn;
    // emask init: block b covers n = b*128 .. b*128+127
    if (u < 128) g_emask[b * 128 + u] = 1.0f;
    // alpha partials
    float4 w4 = *(const float4*)(Wa + u * 4);
    float p0 = hn * w4.x, p1 = hn * w4.y, p2 = hn * w4.z, p3 = hn * w4.w;
    #pragma unroll
    for (int o = 16; o > 0; o >>= 1) {
        p0 += __shfl_xor_sync(0xffffffffu, p0, o);
        p1 += __shfl_xor_sync(0xffffffffu, p1, o);
        p2 += __shfl_xor_sync(0xffffffffu, p2, o);
        p3 += __shfl_xor_sync(0xffffffffu, p3, o);
    }
    if ((u & 31) == 0) {
        red[u >> 5][0] = p0; red[u >> 5][1] = p1;
        red[u >> 5][2] = p2; red[u >> 5][3] = p3;
    }
    __syncthreads();
    if (u < 4) {
        float a = ba[u];
        #pragma unroll
        for (int i = 0; i < 8; i++) a += red[i][u];
        float al = fsigmoid(ftanh(a));
        sal[u] = al;
        g_alpha[b * 4 + u] = al;
    }
    __syncthreads();
    // keys: thread -> (r = u>>6, m = u&63)
    const int r = u >> 6, m = u & 63;
    float acc = bk[r * M_ + m];
    const float* wk = Wk + (size_t)r * U_ * M_ + m;
    #pragma unroll 8
    for (int uu = 0; uu < U_; uu++) acc += hs[uu] * wk[uu * M_];
    float kt = ftanh(acc);
    g_kt[(r * B_ + b) * M_ + m] = kt;
    g_ktTh[(r * M_ + m) * B_ + b] = __float2half(kt * sal[r]);
    float s = kt * kt;
    #pragma unroll
    for (int o = 16; o > 0; o >>= 1) s += __shfl_xor_sync(0xffffffffu, s, o);
    if ((u & 31) == 0) sred[u >> 5] = s;
    __syncthreads();
    float inv = rsqrtf(sred[2 * r] + sred[2 * r + 1]);
    g_ktsh[(r * B_ + b) * M_ + m] = __float2half(kt * inv);
}

// ---------------- K3: write deltas (tensor), software-pipelined (R6 config) ----------
// dA[r][m][n] = (alpha.*kt[r])^T @ wr_prev[r].  grid (N_/128, R_), 256 threads.
__global__ void __launch_bounds__(256) k_dA(const float* __restrict__ wrp) {
    __shared__ __align__(16) __half sP[64 * 136];   // [b-chunk 64][n 128 +8]
    __shared__ __align__(16) __half sA[64 * 72];    // [m 64][b-chunk 64 +8]
    const int t = threadIdx.x, w = t >> 5, l = t & 31;
    const int n0 = blockIdx.x * 128, r = blockIdx.y;
    const int mrow = (w & 3) * 16, nhalf = (w >> 2) * 64;
    const float* wr_base = wrp + (size_t)r * B_ * N_;
    float acc[8][4] = {};
    uint32_t pb = smem_u32(sP), ab = smem_u32(sA);

    const int prow = t >> 5, pc = t & 31;
    const int arow = t >> 3, ac4 = t & 7;
    float4 pv[8]; uint4 av[2];
    #pragma unroll
    for (int i = 0; i < 8; i++)
        pv[i] = *(const float4*)(wr_base + (size_t)(prow + i * 8) * N_ + n0 + pc * 4);
    #pragma unroll
    for (int i = 0; i < 2; i++)
        av[i] = *(const uint4*)(g_ktTh + (size_t)(r * M_ + arow + i * 32) * B_ + ac4 * 8);

    for (int kt = 0; kt < 4; kt++) {
        __syncthreads();
        #pragma unroll
        for (int i = 0; i < 8; i++) {
            int row = prow + i * 8;
            *(__half2*)(sP + row * 136 + pc * 4)     = __floats2half2_rn(pv[i].x, pv[i].y);
            *(__half2*)(sP + row * 136 + pc * 4 + 2) = __floats2half2_rn(pv[i].z, pv[i].w);
        }
        #pragma unroll
        for (int i = 0; i < 2; i++)
            *(uint4*)(sA + (arow + i * 32) * 72 + ac4 * 8) = av[i];
        __syncthreads();
        if (kt < 3) {
            int kb = (kt + 1) * 64;
            #pragma unroll
            for (int i = 0; i < 8; i++)
                pv[i] = *(const float4*)(wr_base + (size_t)(kb + prow + i * 8) * N_ + n0 + pc * 4);
            #pragma unroll
            for (int i = 0; i < 2; i++)
                av[i] = *(const uint4*)(g_ktTh + (size_t)(r * M_ + arow + i * 32) * B_ + kb + ac4 * 8);
        }
        #pragma unroll
        for (int k16 = 0; k16 < 4; k16++) {
            uint32_t a[4];
            ldsm4(a, ab + ((mrow + (l & 15)) * 72 + (l >> 4) * 8 + k16 * 16) * 2);
            #pragma unroll
            for (int j = 0; j < 4; j++) {
                uint32_t bb[4];
                int rowb = k16 * 16 + (l & 7) + ((l >> 3) & 1) * 8;
                int colb = nhalf + j * 16 + ((l >> 4) & 1) * 8;
                ldsm4t(bb, pb + (rowb * 136 + colb) * 2);
                mma16816(acc[2 * j],     a, bb[0], bb[1]);
                mma16816(acc[2 * j + 1], a, bb[2], bb[3]);
            }
        }
    }
    int m0 = mrow + (l >> 2), cb = n0 + nhalf + (l & 3) * 2;
    #pragma unroll
    for (int jj = 0; jj < 8; jj++) {
        *(__half2*)(g_dA + (size_t)(r * M_ + m0) * N_ + cb + jj * 8) =
            __floats2half2_rn(acc[jj][0], acc[jj][1]);
        *(__half2*)(g_dA + (size_t)(r * M_ + m0 + 8) * N_ + cb + jj * 8) =
            __floats2half2_rn(acc[jj][2], acc[jj][3]);
    }
}

// ---------------- K4: argmin + erase-mask set (emask pre-initialized in lstm_kt) -----
__global__ void k_argmin(const float* __restrict__ wu) {
    int b = blockIdx.x, t = threadIdx.x;
    const float4* row = (const float4*)(wu + (size_t)b * N_);
    float mv = 3.4e38f; int mi = 0;
    for (int i = t; i < N_ / 4; i += 256) {
        float4 v = row[i];
        int base = i * 4;
        if (v.x < mv) { mv = v.x; mi = base; }
        if (v.y < mv) { mv = v.y; mi = base + 1; }
        if (v.z < mv) { mv = v.z; mi = base + 2; }
        if (v.w < mv) { mv = v.w; mi = base + 3; }
    }
    __shared__ float sv[256];
    __shared__ int   si[256];
    sv[t] = mv; si[t] = mi;
    __syncthreads();
    for (int s = 128; s > 0; s >>= 1) {
        if (t < s) {
            if (sv[t + s] < sv[t] || (sv[t + s] == sv[t] && si[t + s] < si[t])) {
                sv[t] = sv[t + s]; si[t] = si[t + s];
            }
        }
        __syncthreads();
    }
    if (t == 0) {
        g_least[b] = si[0];
        g_emask[si[0]] = 0.0f;     // all duplicate writers store 0.0f: deterministic
    }
}

// ---------------- K5: Ash[n,:] = fp16( A[n,:] / ||A[n,:]|| ) ----------------
__global__ void k_As(const float* __restrict__ A) {
    int n = blockIdx.x * 8 + (threadIdx.x >> 5);
    int lane = threadIdx.x & 31;
    float a0 = A[n * M_ + lane], a1 = A[n * M_ + 32 + lane];
    float s = a0 * a0 + a1 * a1;
    #pragma unroll
    for (int o = 16; o > 0; o >>= 1) s += __shfl_xor_sync(0xffffffffu, s, o);
    float inv = rsqrtf(s);
    g_Ash[n * M_ + lane]      = __float2half(a0 * inv);
    g_Ash[n * M_ + 32 + lane] = __float2half(a1 * inv);
}

// ---------------- K6: deterministic least-used scatter into g_dA ----------------
__global__ void k_scatter() {
    const int r = blockIdx.y;
    __shared__ int sL[B_];
    int t = threadIdx.x, b = blockIdx.x;
    sL[t] = g_least[t];
    __syncthreads();
    int my = sL[b];
    bool owner = true;
    for (int bb = 0; bb < b; bb++) if (sL[bb] == my) { owner = false; break; }
    if (!owner) return;
    if (t < M_) {
        float acc = 0.0f;
        for (int bb = b; bb < B_; bb++)
            if (sL[bb] == my)
                acc += (1.0f - g_alpha[bb * R_ + r]) * g_kt[((r << 8) + bb) * M_ + t];
        size_t o = (size_t)(r * M_ + t) * N_ + my;
        g_dA[o] = __float2half(__half2float(g_dA[o]) + acc);
    }
}

// ---------------- K7: chain: AnT = fp16(tanh^4 chain of A*e + deltas) ----------------
__global__ void k_chain(const float* __restrict__ A) {
    __shared__ float sT[64][65];
    __shared__ float se[64];
    int t = threadIdx.x, n0 = blockIdx.x * 64;
    for (int idx = t; idx < 4096; idx += 256) {
        int row = idx >> 6, c = idx & 63;
        sT[row][c] = A[(size_t)(n0 + row) * M_ + c];
    }
    if (t < 64) se[t] = g_emask[n0 + t];
    __syncthreads();
    for (int idx = t; idx < 4096; idx += 256) {
        int m = idx >> 6, n = idx & 63;
        float a = sT[n][m] * se[n];
        #pragma unroll
        for (int r = 0; r < 4; r++)
            a = ftanh(a + __half2float(g_dA[(size_t)(r * M_ + m) * N_ + n0 + n]));
        g_AnT[(size_t)m * N_ + n0 + n] = __float2half(a);
    }
}

// ---------------- K8: flash fused reads with cp.async double buffering ----------------
__global__ void __launch_bounds__(256, 2) k_read() {
    __shared__ __align__(16) __half sQ[128 * 72];
    __shared__ __align__(16) __half sK[2][128 * 72];
    __shared__ __align__(16) __half sV[2][64 * 136];
    const int t = threadIdx.x, w = t >> 5, l = t & 31;
    const int q0 = blockIdx.y * 128, n0 = blockIdx.x * 1024;
    uint32_t qb = smem_u32(sQ);

    for (int idx = t; idx < 1024; idx += 256) {
        int row = idx >> 3, c4 = idx & 7;
        cpa16(qb + (row * 72 + c4 * 8) * 2, g_ktsh + (size_t)(q0 + row) * M_ + c4 * 8);
    }
    {
        uint32_t kb = smem_u32(sK[0]), vb = smem_u32(sV[0]);
        for (int idx = t; idx < 1024; idx += 256) {
            int row = idx >> 3, c4 = idx & 7;
            cpa16(kb + (row * 72 + c4 * 8) * 2, g_Ash + (size_t)(n0 + row) * M_ + c4 * 8);
        }
        for (int idx = t; idx < 1024; idx += 256) {
            int row = idx >> 4, c4 = idx & 15;
            cpa16(vb + (row * 136 + c4 * 8) * 2, g_AnT + (size_t)row * N_ + n0 + c4 * 8);
        }
    }
    CP_COMMIT();

    uint32_t qa[4][4];
    float acc_o[8][4] = {};
    float den0 = 0.0f, den1 = 0.0f;
    for (int sub = 0; sub < 8; sub++) {
        if (sub + 1 < 8) {
            int kg = n0 + (sub + 1) * 128;
            uint32_t kb = smem_u32(sK[(sub + 1) & 1]), vb = smem_u32(sV[(sub + 1) & 1]);
            for (int idx = t; idx < 1024; idx += 256) {
                int row = idx >> 3, c4 = idx & 7;
                cpa16(kb + (row * 72 + c4 * 8) * 2, g_Ash + (size_t)(kg + row) * M_ + c4 * 8);
            }
            for (int idx = t; idx < 1024; idx += 256) {
                int row = idx >> 4, c4 = idx & 15;
                cpa16(vb + (row * 136 + c4 * 8) * 2, g_AnT + (size_t)row * N_ + kg + c4 * 8);
            }
        }
        CP_COMMIT();
        CP_WAIT(1);
        __syncthreads();
        if (sub == 0) {
            #pragma unroll
            for (int k16 = 0; k16 < 4; k16++)
                ldsm4(qa[k16], qb + ((w * 16 + (l & 15)) * 72 + (l >> 4) * 8 + k16 * 16) * 2);
        }
        uint32_t kb = smem_u32(sK[sub & 1]), vb = smem_u32(sV[sub & 1]);
        float s[16][4] = {};
        #pragma unroll
        for (int k16 = 0; k16 < 4; k16++) {
            #pragma unroll
            for (int j = 0; j < 8; j++) {
                uint32_t bbf[4];
                ldsm4(bbf, kb + ((j * 16 + (l & 15)) * 72 + (l >> 4) * 8 + k16 * 16) * 2);
                mma16816(s[2 * j],     qa[k16], bbf[0], bbf[2]);
                mma16816(s[2 * j + 1], qa[k16], bbf[1], bbf[3]);
            }
        }
        #pragma unroll
        for (int kk = 0; kk < 8; kk++) {
            float e00 = __expf(s[2 * kk][0]),     e01 = __expf(s[2 * kk][1]);
            float e02 = __expf(s[2 * kk][2]),     e03 = __expf(s[2 * kk][3]);
            float e10 = __expf(s[2 * kk + 1][0]), e11 = __expf(s[2 * kk + 1][1]);
            float e12 = __expf(s[2 * kk + 1][2]), e13 = __expf(s[2 * kk + 1][3]);
            den0 += e00 + e01 + e10 + e11;
            den1 += e02 + e03 + e12 + e13;
            uint32_t pa[4];
            pa[0] = packh2(e00, e01);
            pa[1] = packh2(e02, e03);
            pa[2] = packh2(e10, e11);
            pa[3] = packh2(e12, e13);
            #pragma unroll
            for (int j = 0; j < 4; j++) {
                uint32_t bbf[4];
                ldsm4(bbf, vb + ((j * 16 + (l & 15)) * 136 + (l >> 4) * 8 + kk * 16) * 2);
                mma16816(acc_o[2 * j],     pa, bbf[0], bbf[2]);
                mma16816(acc_o[2 * j + 1], pa, bbf[1], bbf[3]);
            }
        }
        __syncthreads();
    }
    den0 += __shfl_xor_sync(0xffffffffu, den0, 1);
    den0 += __shfl_xor_sync(0xffffffffu, den0, 2);
    den1 += __shfl_xor_sync(0xffffffffu, den1, 1);
    den1 += __shfl_xor_sync(0xffffffffu, den1, 2);
    int r0 = q0 + w * 16 + (l >> 2);
    if ((l & 3) == 0) {
        g_pden[r0 * NSPL + blockIdx.x]       = den0;
        g_pden[(r0 + 8) * NSPL + blockIdx.x] = den1;
    }
    float* p0 = g_pacc + ((size_t)r0 * NSPL + blockIdx.x) * M_;
    float* p1 = g_pacc + ((size_t)(r0 + 8) * NSPL + blockIdx.x) * M_;
    int cb = (l & 3) * 2;
    #pragma unroll
    for (int jj = 0; jj < 8; jj++) {
        *(float2*)(p0 + jj * 8 + cb) = make_float2(acc_o[jj][0], acc_o[jj][1]);
        *(float2*)(p1 + jj * 8 + cb) = make_float2(acc_o[jj][2], acc_o[jj][3]);
    }
}

// ---------------- K9: combine partials -> out[:, 256:512] ----------------
__global__ void k_combine(float* __restrict__ out) {
    int q = blockIdx.x;          // r*B + b
    int m = threadIdx.x;         // 64
    float acc = 0.0f, den = 0.0f;
    #pragma unroll
    for (int s = 0; s < NSPL; s++) {
        acc += g_pacc[((size_t)q * NSPL + s) * M_ + m];
        den += g_pden[q * NSPL + s];
    }
    int r = q >> 8, b = q & 255;
    out[b * 512 + 256 + r * M_ + m] = acc / den;
}

// ---------------- launch ----------------
extern "C" void kernel_launch(void* const* d_in, const int* in_sizes, int n_in,
                              void* d_out, int out_size) {
    const float* x    = (const float*)d_in[0];
    const float* A    = (const float*)d_in[1];
    const float* wrp  = (const float*)d_in[2];
    const float* wu   = (const float*)d_in[3];
    const float* rp   = (const float*)d_in[4];
    const float* h    = (const float*)d_in[5];
    const float* c    = (const float*)d_in[6];
    const float* W    = (const float*)d_in[7];
    const float* Uw   = (const float*)d_in[8];
    const float* bias = (const float*)d_in[9];
    const float* Wk   = (const float*)d_in[10];
    const float* bk   = (const float*)d_in[11];
    const float* Wa   = (const float*)d_in[12];
    const float* ba   = (const float*)d_in[13];
    float* out = (float*)d_out;

    k_gates_mma<<<dim3(8, 2), 256>>>(x, rp, h, W, Uw, bias);  // 0
    k_lstm_kt  <<<B_, 256>>>(c, out, Wa, ba, Wk, bk);         // 1 (lstm+alpha+keys+emask)
    k_dA       <<<dim3(N_ / 128, R_), 256>>>(wrp);            // 2
    k_argmin   <<<B_, 256>>>(wu);                             // 3 <- profiled slot
    k_As       <<<N_ / 8, 256>>>(A);                          // 4
    k_scatter  <<<dim3(B_, R_), 256>>>();                     // 5
    k_chain    <<<N_ / 64, 256>>>(A);                         // 6
    k_read     <<<dim3(NSPL, 8), 256>>>();                    // 7
    k_combine  <<<QT_, 64>>>(out);                            // 8
}

// round 10
// speedup vs baseline: 8.8356x; 1.3046x over previous
#include <cuda_runtime.h>
#include <cuda_fp16.h>
#include <math.h>
#include <stdint.h>

// Problem constants
#define B_   256
#define N_   32768
#define M_   64
#define R_   4
#define U_   256
#define DIN_ 512
#define G4_  1024
#define QT_  1024      // total queries = R*B
#define NSPL 32        // flash reads: split of N (1024 keys per chunk)
#define KSPL 8         // gates GEMM split-K parts

// ---------------- static scratch ----------------
__device__ float  g_gpart[KSPL * B_ * G4_];   // gates split-K partials (8 MB)
__device__ float  g_kt   [QT_ * M_];          // raw tanh keys fp32 (scatter)
__device__ __half g_ktsh [QT_ * M_];          // normalized keys fp16 [q][m]
__device__ __half g_ktTh [R_ * M_ * B_];      // alpha-scaled keys fp16 [r][m][b]
__device__ float  g_alpha[B_ * R_];
__device__ int    g_least[B_];
__device__ __half g_Ash  [N_ * M_];           // A rows / ||A[n]|| fp16 [n][m]
__device__ __half g_dA   [R_ * M_ * N_];      // write deltas fp16 [r][m][n]
__device__ float  g_emask[N_];
__device__ __half g_AnT  [M_ * N_];           // new memory fp16 [m][n]
__device__ float  g_pden [QT_ * NSPL];
__device__ float  g_pacc [QT_ * NSPL * M_];

// fast transcendentals
__device__ __forceinline__ float fsigmoid(float x) {
    return __fdividef(1.0f, 1.0f + __expf(-x));
}
__device__ __forceinline__ float ftanh(float x) {
    float e = __expf(2.0f * x);
    return __fdividef(e - 1.0f, e + 1.0f);
}
__device__ __forceinline__ float htanh(float x) {     // MUFU.TANH, 1 op
    float y;
    asm("tanh.approx.f32 %0, %1;" : "=f"(y) : "f"(x));
    return y;
}

__device__ __forceinline__ uint32_t smem_u32(const void* p) {
    uint32_t a;
    asm("{ .reg .u64 t; cvta.to.shared.u64 t, %1; cvt.u32.u64 %0, t; }" : "=r"(a) : "l"(p));
    return a;
}
__device__ __forceinline__ void ldsm4(uint32_t* r, uint32_t addr) {
    asm volatile("ldmatrix.sync.aligned.m8n8.x4.shared.b16 {%0,%1,%2,%3}, [%4];"
        : "=r"(r[0]), "=r"(r[1]), "=r"(r[2]), "=r"(r[3]) : "r"(addr));
}
__device__ __forceinline__ void ldsm4t(uint32_t* r, uint32_t addr) {
    asm volatile("ldmatrix.sync.aligned.m8n8.x4.trans.shared.b16 {%0,%1,%2,%3}, [%4];"
        : "=r"(r[0]), "=r"(r[1]), "=r"(r[2]), "=r"(r[3]) : "r"(addr));
}
__device__ __forceinline__ void mma16816(float* c, const uint32_t* a, uint32_t b0, uint32_t b1) {
    asm volatile("mma.sync.aligned.m16n8k16.row.col.f32.f16.f16.f32 "
        "{%0,%1,%2,%3}, {%4,%5,%6,%7}, {%8,%9}, {%0,%1,%2,%3};"
        : "+f"(c[0]), "+f"(c[1]), "+f"(c[2]), "+f"(c[3])
        : "r"(a[0]), "r"(a[1]), "r"(a[2]), "r"(a[3]), "r"(b0), "r"(b1));
}
__device__ __forceinline__ uint32_t packh2(float a, float b) {
    __half2 h = __floats2half2_rn(a, b);
    return *(uint32_t*)&h;
}
__device__ __forceinline__ void cpa16(uint32_t dst, const void* src) {
    asm volatile("cp.async.ca.shared.global [%0], [%1], 16;" :: "r"(dst), "l"(src));
}
#define CP_COMMIT() asm volatile("cp.async.commit_group;" ::: "memory")
#define CP_WAIT(n)  asm volatile("cp.async.wait_group %0;" :: "n"(n) : "memory")

// ---------------- K1: gates GEMM on tensor cores, split-K ----------------
// partial[z] = [x|read_prev|h](fp16) @ [W;Uw](fp16) over K-chunk z, fp32 accum.
// grid (8 col-blocks, 2 row-blocks, KSPL), 256 threads. Tile: 128x128, K-chunk 128.
__global__ void __launch_bounds__(256) k_gates_mma(
        const float* __restrict__ x, const float* __restrict__ rp,
        const float* __restrict__ h, const float* __restrict__ W,
        const float* __restrict__ Uw) {
    __shared__ __align__(16) __half sIn[128 * 24];   // [row 128][k 16 +8]
    __shared__ __align__(16) __half sW [16 * 136];   // [k 16][col 128 +8]
    const int t = threadIdx.x, w = t >> 5, l = t & 31;
    const int j0 = blockIdx.x * 128, b0 = blockIdx.y * 128, z = blockIdx.z;
    uint32_t ib = smem_u32(sIn), wb = smem_u32(sW);

    const int irow = t >> 1,  icol = (t & 1) * 8;    // input: 128 rows x 16 (2 thr/row)
    const int wrow = t >> 4,  wcol = (t & 15) * 8;   // weights: 16 rows x 128 (16 thr/row)

    float4 iv0, iv1, wv0, wv1;
    auto ld_in = [&](int k0) {
        const float* s;
        if (k0 < DIN_)      s = x + (size_t)(b0 + irow) * DIN_ + k0 + icol;
        else if (k0 < 768) { int i0 = k0 - DIN_;
                            s = rp + ((size_t)(i0 >> 6) * B_ + b0 + irow) * M_ + (i0 & 63) + icol; }
        else                s = h + (size_t)(b0 + irow) * U_ + (k0 - 768) + icol;
        iv0 = *(const float4*)s; iv1 = *(const float4*)(s + 4);
    };
    auto ld_w = [&](int k0) {
        int kk = k0 + wrow;
        const float* s = (kk < 768) ? W + (size_t)kk * G4_ + j0 + wcol
                                    : Uw + (size_t)(kk - 768) * G4_ + j0 + wcol;
        wv0 = *(const float4*)s; wv1 = *(const float4*)(s + 4);
    };

    const int kt0 = z * (64 / KSPL);                 // 8 k16-steps per chunk
    ld_in(kt0 * 16); ld_w(kt0 * 16);
    float acc[16][4] = {};
    for (int kt = 0; kt < 64 / KSPL; kt++) {
        __syncthreads();
        {
            uint4 o;
            o.x = packh2(iv0.x, iv0.y); o.y = packh2(iv0.z, iv0.w);
            o.z = packh2(iv1.x, iv1.y); o.w = packh2(iv1.z, iv1.w);
            *(uint4*)(sIn + irow * 24 + icol) = o;
            o.x = packh2(wv0.x, wv0.y); o.y = packh2(wv0.z, wv0.w);
            o.z = packh2(wv1.x, wv1.y); o.w = packh2(wv1.z, wv1.w);
            *(uint4*)(sW + wrow * 136 + wcol) = o;
        }
        __syncthreads();
        if (kt < 64 / KSPL - 1) { ld_in((kt0 + kt + 1) * 16); ld_w((kt0 + kt + 1) * 16); }
        uint32_t a[4];
        ldsm4(a, ib + ((w * 16 + (l & 15)) * 24 + (l >> 4) * 8) * 2);
        #pragma unroll
        for (int j = 0; j < 8; j++) {
            uint32_t bb[4];
            int rowb = (l & 7) + ((l >> 3) & 1) * 8;
            int colb = j * 16 + ((l >> 4) & 1) * 8;
            ldsm4t(bb, wb + (rowb * 136 + colb) * 2);
            mma16816(acc[2 * j],     a, bb[0], bb[1]);
            mma16816(acc[2 * j + 1], a, bb[2], bb[3]);
        }
    }
    int mr = w * 16 + (l >> 2);
    float* gp = g_gpart + (size_t)z * B_ * G4_;
    int row0 = b0 + mr, row1 = row0 + 8;
    #pragma unroll
    for (int i = 0; i < 16; i++) {
        int col = j0 + i * 8 + (l & 3) * 2;
        *(float2*)(gp + (size_t)row0 * G4_ + col) = make_float2(acc[i][0], acc[i][1]);
        *(float2*)(gp + (size_t)row1 * G4_ + col) = make_float2(acc[i][2], acc[i][3]);
    }
}

// ---------------- K2: fused LSTM + alpha + keys (block = one batch row) ----------------
__global__ void __launch_bounds__(256) k_lstm_kt(
        const float* __restrict__ c, float* __restrict__ out,
        const float* __restrict__ Wa, const float* __restrict__ ba,
        const float* __restrict__ Wk, const float* __restrict__ bk,
        const float* __restrict__ bias) {
    __shared__ float hs[256];
    __shared__ float red[8][4];
    __shared__ float sal[4];
    __shared__ float sred[8];
    const int b = blockIdx.x, u = threadIdx.x;
    const int idx = b * 256 + u;
    float gi = bias[u], gf = bias[256 + u], gg = bias[512 + u], go = bias[768 + u];
    #pragma unroll
    for (int p = 0; p < KSPL; p++) {
        const float* gp = g_gpart + (size_t)p * B_ * G4_ + (size_t)b * G4_;
        gi += gp[u]; gf += gp[256 + u]; gg += gp[512 + u]; go += gp[768 + u];
    }
    float cn = fsigmoid(gf) * c[idx] + fsigmoid(gi) * ftanh(gg);
    float hn = fsigmoid(go) * ftanh(cn);
    hs[u] = hn;
    out[b * 512 + u] = hn;
    if (u < 128) g_emask[b * 128 + u] = 1.0f;    // B_ blocks x 128 = N_
    // alpha partials
    float4 w4 = *(const float4*)(Wa + u * 4);
    float p0 = hn * w4.x, p1 = hn * w4.y, p2 = hn * w4.z, p3 = hn * w4.w;
    #pragma unroll
    for (int o = 16; o > 0; o >>= 1) {
        p0 += __shfl_xor_sync(0xffffffffu, p0, o);
        p1 += __shfl_xor_sync(0xffffffffu, p1, o);
        p2 += __shfl_xor_sync(0xffffffffu, p2, o);
        p3 += __shfl_xor_sync(0xffffffffu, p3, o);
    }
    if ((u & 31) == 0) {
        red[u >> 5][0] = p0; red[u >> 5][1] = p1;
        red[u >> 5][2] = p2; red[u >> 5][3] = p3;
    }
    __syncthreads();
    if (u < 4) {
        float a = ba[u];
        #pragma unroll
        for (int i = 0; i < 8; i++) a += red[i][u];
        float al = fsigmoid(ftanh(a));
        sal[u] = al;
        g_alpha[b * 4 + u] = al;
    }
    __syncthreads();
    // keys: thread -> (r = u>>6, m = u&63)
    const int r = u >> 6, m = u & 63;
    float acc = bk[r * M_ + m];
    const float* wk = Wk + (size_t)r * U_ * M_ + m;
    #pragma unroll 8
    for (int uu = 0; uu < U_; uu++) acc += hs[uu] * wk[uu * M_];
    float kt = ftanh(acc);
    g_kt[(r * B_ + b) * M_ + m] = kt;
    g_ktTh[(r * M_ + m) * B_ + b] = __float2half(kt * sal[r]);
    float s = kt * kt;
    #pragma unroll
    for (int o = 16; o > 0; o >>= 1) s += __shfl_xor_sync(0xffffffffu, s, o);
    if ((u & 31) == 0) sred[u >> 5] = s;
    __syncthreads();
    float inv = rsqrtf(sred[2 * r] + sred[2 * r + 1]);
    g_ktsh[(r * B_ + b) * M_ + m] = __float2half(kt * inv);
}

// ---------------- K3: write deltas (tensor), software-pipelined (R6 config) ----------
__global__ void __launch_bounds__(256) k_dA(const float* __restrict__ wrp) {
    __shared__ __align__(16) __half sP[64 * 136];   // [b-chunk 64][n 128 +8]
    __shared__ __align__(16) __half sA[64 * 72];    // [m 64][b-chunk 64 +8]
    const int t = threadIdx.x, w = t >> 5, l = t & 31;
    const int n0 = blockIdx.x * 128, r = blockIdx.y;
    const int mrow = (w & 3) * 16, nhalf = (w >> 2) * 64;
    const float* wr_base = wrp + (size_t)r * B_ * N_;
    float acc[8][4] = {};
    uint32_t pb = smem_u32(sP), ab = smem_u32(sA);

    const int prow = t >> 5, pc = t & 31;
    const int arow = t >> 3, ac4 = t & 7;
    float4 pv[8]; uint4 av[2];
    #pragma unroll
    for (int i = 0; i < 8; i++)
        pv[i] = *(const float4*)(wr_base + (size_t)(prow + i * 8) * N_ + n0 + pc * 4);
    #pragma unroll
    for (int i = 0; i < 2; i++)
        av[i] = *(const uint4*)(g_ktTh + (size_t)(r * M_ + arow + i * 32) * B_ + ac4 * 8);

    for (int kt = 0; kt < 4; kt++) {
        __syncthreads();
        #pragma unroll
        for (int i = 0; i < 8; i++) {
            int row = prow + i * 8;
            *(__half2*)(sP + row * 136 + pc * 4)     = __floats2half2_rn(pv[i].x, pv[i].y);
            *(__half2*)(sP + row * 136 + pc * 4 + 2) = __floats2half2_rn(pv[i].z, pv[i].w);
        }
        #pragma unroll
        for (int i = 0; i < 2; i++)
            *(uint4*)(sA + (arow + i * 32) * 72 + ac4 * 8) = av[i];
        __syncthreads();
        if (kt < 3) {
            int kb = (kt + 1) * 64;
            #pragma unroll
            for (int i = 0; i < 8; i++)
                pv[i] = *(const float4*)(wr_base + (size_t)(kb + prow + i * 8) * N_ + n0 + pc * 4);
            #pragma unroll
            for (int i = 0; i < 2; i++)
                av[i] = *(const uint4*)(g_ktTh + (size_t)(r * M_ + arow + i * 32) * B_ + kb + ac4 * 8);
        }
        #pragma unroll
        for (int k16 = 0; k16 < 4; k16++) {
            uint32_t a[4];
            ldsm4(a, ab + ((mrow + (l & 15)) * 72 + (l >> 4) * 8 + k16 * 16) * 2);
            #pragma unroll
            for (int j = 0; j < 4; j++) {
                uint32_t bb[4];
                int rowb = k16 * 16 + (l & 7) + ((l >> 3) & 1) * 8;
                int colb = nhalf + j * 16 + ((l >> 4) & 1) * 8;
                ldsm4t(bb, pb + (rowb * 136 + colb) * 2);
                mma16816(acc[2 * j],     a, bb[0], bb[1]);
                mma16816(acc[2 * j + 1], a, bb[2], bb[3]);
            }
        }
    }
    int m0 = mrow + (l >> 2), cb = n0 + nhalf + (l & 3) * 2;
    #pragma unroll
    for (int jj = 0; jj < 8; jj++) {
        *(__half2*)(g_dA + (size_t)(r * M_ + m0) * N_ + cb + jj * 8) =
            __floats2half2_rn(acc[jj][0], acc[jj][1]);
        *(__half2*)(g_dA + (size_t)(r * M_ + m0 + 8) * N_ + cb + jj * 8) =
            __floats2half2_rn(acc[jj][2], acc[jj][3]);
    }
}

// ---------------- K4: argmin (MLP=4) + erase-mask set ----------------
__global__ void k_argmin(const float* __restrict__ wu) {
    int b = blockIdx.x, t = threadIdx.x;
    const float4* row = (const float4*)(wu + (size_t)b * N_);
    float mv = 3.4e38f; int mi = 0;
    for (int i = t; i < N_ / 4; i += 1024) {           // 8 outer iters, 4 loads each
        float4 v0 = row[i], v1 = row[i + 256], v2 = row[i + 512], v3 = row[i + 768];
        int b0 = i * 4, b1 = (i + 256) * 4, b2 = (i + 512) * 4, b3 = (i + 768) * 4;
        if (v0.x < mv) { mv = v0.x; mi = b0; }
        if (v0.y < mv) { mv = v0.y; mi = b0 + 1; }
        if (v0.z < mv) { mv = v0.z; mi = b0 + 2; }
        if (v0.w < mv) { mv = v0.w; mi = b0 + 3; }
        if (v1.x < mv) { mv = v1.x; mi = b1; }
        if (v1.y < mv) { mv = v1.y; mi = b1 + 1; }
        if (v1.z < mv) { mv = v1.z; mi = b1 + 2; }
        if (v1.w < mv) { mv = v1.w; mi = b1 + 3; }
        if (v2.x < mv) { mv = v2.x; mi = b2; }
        if (v2.y < mv) { mv = v2.y; mi = b2 + 1; }
        if (v2.z < mv) { mv = v2.z; mi = b2 + 2; }
        if (v2.w < mv) { mv = v2.w; mi = b2 + 3; }
        if (v3.x < mv) { mv = v3.x; mi = b3; }
        if (v3.y < mv) { mv = v3.y; mi = b3 + 1; }
        if (v3.z < mv) { mv = v3.z; mi = b3 + 2; }
        if (v3.w < mv) { mv = v3.w; mi = b3 + 3; }
    }
    __shared__ float sv[256];
    __shared__ int   si[256];
    sv[t] = mv; si[t] = mi;
    __syncthreads();
    for (int s = 128; s > 0; s >>= 1) {
        if (t < s) {
            if (sv[t + s] < sv[t] || (sv[t + s] == sv[t] && si[t + s] < si[t])) {
                sv[t] = sv[t + s]; si[t] = si[t + s];
            }
        }
        __syncthreads();
    }
    if (t == 0) {
        g_least[b] = si[0];
        g_emask[si[0]] = 0.0f;     // duplicate writers store same value: deterministic
    }
}

// ---------------- K5: deterministic least-used scatter into g_dA ----------------
__global__ void k_scatter() {
    const int r = blockIdx.y;
    __shared__ int sL[B_];
    int t = threadIdx.x, b = blockIdx.x;
    sL[t] = g_least[t];
    __syncthreads();
    int my = sL[b];
    bool owner = true;
    for (int bb = 0; bb < b; bb++) if (sL[bb] == my) { owner = false; break; }
    if (!owner) return;
    if (t < M_) {
        float acc = 0.0f;
        for (int bb = b; bb < B_; bb++)
            if (sL[bb] == my)
                acc += (1.0f - g_alpha[bb * R_ + r]) * g_kt[((r << 8) + bb) * M_ + t];
        size_t o = (size_t)(r * M_ + t) * N_ + my;
        g_dA[o] = __float2half(__half2float(g_dA[o]) + acc);
    }
}

// ---------------- K6: chain (+fused Ash): AnT = fp16(tanh^4 chain), Ash = A/||A|| -----
__global__ void k_chain(const float* __restrict__ A) {
    __shared__ float sT[64][65];
    __shared__ float se[64];
    int t = threadIdx.x, n0 = blockIdx.x * 64;
    int w = t >> 5, l = t & 31;
    for (int idx = t; idx < 4096; idx += 256) {
        int row = idx >> 6, c = idx & 63;
        sT[row][c] = A[(size_t)(n0 + row) * M_ + c];
    }
    if (t < 64) se[t] = g_emask[n0 + t];
    __syncthreads();
    // fused Ash: warp w handles rows w*8 .. w*8+7
    #pragma unroll
    for (int rr = 0; rr < 8; rr++) {
        int row = w * 8 + rr;
        float a0 = sT[row][l], a1 = sT[row][32 + l];
        float s = a0 * a0 + a1 * a1;
        #pragma unroll
        for (int o = 16; o > 0; o >>= 1) s += __shfl_xor_sync(0xffffffffu, s, o);
        float inv = rsqrtf(s);
        g_Ash[(size_t)(n0 + row) * M_ + l]      = __float2half(a0 * inv);
        g_Ash[(size_t)(n0 + row) * M_ + 32 + l] = __float2half(a1 * inv);
    }
    // tanh chain (MUFU.TANH)
    for (int idx = t; idx < 4096; idx += 256) {
        int m = idx >> 6, n = idx & 63;
        float a = sT[n][m] * se[n];
        #pragma unroll
        for (int r = 0; r < 4; r++)
            a = htanh(a + __half2float(g_dA[(size_t)(r * M_ + m) * N_ + n0 + n]));
        g_AnT[(size_t)m * N_ + n0 + n] = __float2half(a);
    }
}

// ---------------- K7: flash fused reads with cp.async double buffering ----------------
__global__ void __launch_bounds__(256, 2) k_read() {
    __shared__ __align__(16) __half sQ[128 * 72];
    __shared__ __align__(16) __half sK[2][128 * 72];
    __shared__ __align__(16) __half sV[2][64 * 136];
    const int t = threadIdx.x, w = t >> 5, l = t & 31;
    const int q0 = blockIdx.y * 128, n0 = blockIdx.x * 1024;
    uint32_t qb = smem_u32(sQ);

    for (int idx = t; idx < 1024; idx += 256) {
        int row = idx >> 3, c4 = idx & 7;
        cpa16(qb + (row * 72 + c4 * 8) * 2, g_ktsh + (size_t)(q0 + row) * M_ + c4 * 8);
    }
    {
        uint32_t kb = smem_u32(sK[0]), vb = smem_u32(sV[0]);
        for (int idx = t; idx < 1024; idx += 256) {
            int row = idx >> 3, c4 = idx & 7;
            cpa16(kb + (row * 72 + c4 * 8) * 2, g_Ash + (size_t)(n0 + row) * M_ + c4 * 8);
        }
        for (int idx = t; idx < 1024; idx += 256) {
            int row = idx >> 4, c4 = idx & 15;
            cpa16(vb + (row * 136 + c4 * 8) * 2, g_AnT + (size_t)row * N_ + n0 + c4 * 8);
        }
    }
    CP_COMMIT();

    uint32_t qa[4][4];
    float acc_o[8][4] = {};
    float den0 = 0.0f, den1 = 0.0f;
    for (int sub = 0; sub < 8; sub++) {
        if (sub + 1 < 8) {
            int kg = n0 + (sub + 1) * 128;
            uint32_t kb = smem_u32(sK[(sub + 1) & 1]), vb = smem_u32(sV[(sub + 1) & 1]);
            for (int idx = t; idx < 1024; idx += 256) {
                int row = idx >> 3, c4 = idx & 7;
                cpa16(kb + (row * 72 + c4 * 8) * 2, g_Ash + (size_t)(kg + row) * M_ + c4 * 8);
            }
            for (int idx = t; idx < 1024; idx += 256) {
                int row = idx >> 4, c4 = idx & 15;
                cpa16(vb + (row * 136 + c4 * 8) * 2, g_AnT + (size_t)row * N_ + kg + c4 * 8);
            }
        }
        CP_COMMIT();
        CP_WAIT(1);
        __syncthreads();
        if (sub == 0) {
            #pragma unroll
            for (int k16 = 0; k16 < 4; k16++)
                ldsm4(qa[k16], qb + ((w * 16 + (l & 15)) * 72 + (l >> 4) * 8 + k16 * 16) * 2);
        }
        uint32_t kb = smem_u32(sK[sub & 1]), vb = smem_u32(sV[sub & 1]);
        float s[16][4] = {};
        #pragma unroll
        for (int k16 = 0; k16 < 4; k16++) {
            #pragma unroll
            for (int j = 0; j < 8; j++) {
                uint32_t bbf[4];
                ldsm4(bbf, kb + ((j * 16 + (l & 15)) * 72 + (l >> 4) * 8 + k16 * 16) * 2);
                mma16816(s[2 * j],     qa[k16], bbf[0], bbf[2]);
                mma16816(s[2 * j + 1], qa[k16], bbf[1], bbf[3]);
            }
        }
        #pragma unroll
        for (int kk = 0; kk < 8; kk++) {
            float e00 = __expf(s[2 * kk][0]),     e01 = __expf(s[2 * kk][1]);
            float e02 = __expf(s[2 * kk][2]),     e03 = __expf(s[2 * kk][3]);
            float e10 = __expf(s[2 * kk + 1][0]), e11 = __expf(s[2 * kk + 1][1]);
            float e12 = __expf(s[2 * kk + 1][2]), e13 = __expf(s[2 * kk + 1][3]);
            den0 += e00 + e01 + e10 + e11;
            den1 += e02 + e03 + e12 + e13;
            uint32_t pa[4];
            pa[0] = packh2(e00, e01);
            pa[1] = packh2(e02, e03);
            pa[2] = packh2(e10, e11);
            pa[3] = packh2(e12, e13);
            #pragma unroll
            for (int j = 0; j < 4; j++) {
                uint32_t bbf[4];
                ldsm4(bbf, vb + ((j * 16 + (l & 15)) * 136 + (l >> 4) * 8 + kk * 16) * 2);
                mma16816(acc_o[2 * j],     pa, bbf[0], bbf[2]);
                mma16816(acc_o[2 * j + 1], pa, bbf[1], bbf[3]);
            }
        }
        __syncthreads();
    }
    den0 += __shfl_xor_sync(0xffffffffu, den0, 1);
    den0 += __shfl_xor_sync(0xffffffffu, den0, 2);
    den1 += __shfl_xor_sync(0xffffffffu, den1, 1);
    den1 += __shfl_xor_sync(0xffffffffu, den1, 2);
    int r0 = q0 + w * 16 + (l >> 2);
    if ((l & 3) == 0) {
        g_pden[r0 * NSPL + blockIdx.x]       = den0;
        g_pden[(r0 + 8) * NSPL + blockIdx.x] = den1;
    }
    float* p0 = g_pacc + ((size_t)r0 * NSPL + blockIdx.x) * M_;
    float* p1 = g_pacc + ((size_t)(r0 + 8) * NSPL + blockIdx.x) * M_;
    int cb = (l & 3) * 2;
    #pragma unroll
    for (int jj = 0; jj < 8; jj++) {
        *(float2*)(p0 + jj * 8 + cb) = make_float2(acc_o[jj][0], acc_o[jj][1]);
        *(float2*)(p1 + jj * 8 + cb) = make_float2(acc_o[jj][2], acc_o[jj][3]);
    }
}

// ---------------- K8: combine partials -> out[:, 256:512] ----------------
__global__ void k_combine(float* __restrict__ out) {
    int q = blockIdx.x;          // r*B + b
    int m = threadIdx.x;         // 64
    float acc = 0.0f, den = 0.0f;
    #pragma unroll
    for (int s = 0; s < NSPL; s++) {
        acc += g_pacc[((size_t)q * NSPL + s) * M_ + m];
        den += g_pden[q * NSPL + s];
    }
    int r = q >> 8, b = q & 255;
    out[b * 512 + 256 + r * M_ + m] = acc / den;
}

// ---------------- launch ----------------
extern "C" void kernel_launch(void* const* d_in, const int* in_sizes, int n_in,
                              void* d_out, int out_size) {
    const float* x    = (const float*)d_in[0];
    const float* A    = (const float*)d_in[1];
    const float* wrp  = (const float*)d_in[2];
    const float* wu   = (const float*)d_in[3];
    const float* rp   = (const float*)d_in[4];
    const float* h    = (const float*)d_in[5];
    const float* c    = (const float*)d_in[6];
    const float* W    = (const float*)d_in[7];
    const float* Uw   = (const float*)d_in[8];
    const float* bias = (const float*)d_in[9];
    const float* Wk   = (const float*)d_in[10];
    const float* bk   = (const float*)d_in[11];
    const float* Wa   = (const float*)d_in[12];
    const float* ba   = (const float*)d_in[13];
    float* out = (float*)d_out;

    k_gates_mma<<<dim3(8, 2, KSPL), 256>>>(x, rp, h, W, Uw);      // 0 (split-K)
    k_lstm_kt  <<<B_, 256>>>(c, out, Wa, ba, Wk, bk, bias);       // 1
    k_dA       <<<dim3(N_ / 128, R_), 256>>>(wrp);                // 2
    k_argmin   <<<B_, 256>>>(wu);                                 // 3 <- profiled slot
    k_scatter  <<<dim3(B_, R_), 256>>>();                         // 4
    k_chain    <<<N_ / 64, 256>>>(A);                             // 5 (+Ash fused)
    k_read     <<<dim3(NSPL, 8), 256>>>();                        // 6
    k_combine  <<<QT_, 64>>>(out);                                // 7
}